// round 9
// baseline (speedup 1.0000x reference)
#include <cuda_runtime.h>
#include <cuda_bf16.h>
#include <math.h>
#include <stdint.h>

#define Bn 4
#define Cc 256
#define C8 32
#define Hh 64
#define Ww 64
#define HW 4096

typedef unsigned long long u64;

__device__ __forceinline__ u64 ffma2(u64 a, u64 b, u64 c){
    u64 d; asm("fma.rn.f32x2 %0, %1, %2, %3;" : "=l"(d) : "l"(a), "l"(b), "l"(c)); return d;
}
__device__ __forceinline__ u64 pack2(float lo, float hi){
    u64 d; asm("mov.b64 %0, {%1, %2};" : "=l"(d) : "f"(lo), "f"(hi)); return d;
}
__device__ __forceinline__ float2 unpack2(u64 v){
    float lo, hi; asm("mov.b64 {%0, %1}, %2;" : "=f"(lo), "=f"(hi) : "l"(v));
    return make_float2(lo, hi);
}
__device__ __forceinline__ void mma_bf16(float4& d, const uint32_t a0, const uint32_t a1,
                                         const uint32_t a2, const uint32_t a3,
                                         const uint32_t b0, const uint32_t b1){
    asm volatile(
      "mma.sync.aligned.m16n8k16.row.col.f32.bf16.bf16.f32 "
      "{%0,%1,%2,%3}, {%4,%5,%6,%7}, {%8,%9}, {%0,%1,%2,%3};"
      : "+f"(d.x), "+f"(d.y), "+f"(d.z), "+f"(d.w)
      : "r"(a0), "r"(a1), "r"(a2), "r"(a3), "r"(b0), "r"(b1));
}
__device__ __forceinline__ uint32_t pkbf(__nv_bfloat16 a, __nv_bfloat16 b){
    __nv_bfloat162 t = __halves2bfloat162(a, b);
    return *reinterpret_cast<uint32_t*>(&t);
}

// ---------------- scratch ----------------
__device__ float g_x  [Bn*Cc*HW];
__device__ float g_sum[Bn*Cc*HW];
__device__ float g_t  [Bn*C8*HW];
__device__ float g_attn1[Bn*C8*C8];
__device__ float g_out3[Bn*C8*HW];
__device__ float g_q2n [Bn*HW*C8];
__device__ float g_norm[Bn*HW];
__device__ float g_pgram[Bn*32*C8*C8];
__device__ uint2 g_wb[9*128*Cc];   // [tap][ci2][co] -> (hi bf16-pair, lo bf16-pair)

// ================= weight prep =================
__global__ void __launch_bounds__(256) wprep_k(const float* __restrict__ w)
{
    int idx = blockIdx.x * 256 + threadIdx.x;   // 9*128*256 = 294912
    int co  = idx & 255;
    int ci2 = (idx >> 8) & 127;
    int tap = idx >> 15;
    float v0 = w[((size_t)co*Cc + 2*ci2    )*9 + tap];
    float v1 = w[((size_t)co*Cc + 2*ci2 + 1)*9 + tap];
    __nv_bfloat16 h0 = __float2bfloat16_rn(v0), h1 = __float2bfloat16_rn(v1);
    __nv_bfloat16 l0 = __float2bfloat16_rn(v0 - __bfloat162float(h0));
    __nv_bfloat16 l1 = __float2bfloat16_rn(v1 - __bfloat162float(h1));
    g_wb[idx] = make_uint2(pkbf(h0, h1), pkbf(l0, l1));
}

// ================= 3x3 conv via bf16 m16n8k16 MMA, interleaved hi/lo =================
// grid (32 pb, 2 cog, 4 b), block 256 (8 warps). CTA tile: 128 co x 128 px.
#define SXB2 276           // uint2 stride per ci2 for X strip (4 rows x 66, pad; ≡4 mod 16)
#define SWB2 132           // uint2 stride per ci2 for W tile (128 co, pad; ≡4 mod 16)
#define SWT2 (8*SWB2)      // per-tap W block (1056)
#define SX_ELEMS2 (8*SXB2) // 2208
#define SW_ALL2 (9*SWT2)   // 9504

__global__ void __launch_bounds__(256, 2) convmma_k(
    const float* __restrict__ x, const float* __restrict__ bias)
{
    extern __shared__ uint2 sm2[];
    uint2* sX = sm2;
    uint2* sW = sX + SX_ELEMS2;

    const int pb = blockIdx.x, cog = blockIdx.y, b = blockIdx.z;
    const int tid  = threadIdx.x;
    const int wid  = tid >> 5, lane = tid & 31;
    const int wm   = wid >> 1, wn = wid & 1;
    const int gid  = lane >> 2, tig = lane & 3;
    const int h0   = pb * 2;

    float4 acc[2][8];
#pragma unroll
    for (int mt = 0; mt < 2; mt++)
#pragma unroll
        for (int nt = 0; nt < 8; nt++) acc[mt][nt] = make_float4(0.f,0.f,0.f,0.f);

    for (int cib = 0; cib < Cc/16; cib++) {
        __syncthreads();
        // ---- stage X strip: 8 ci-pairs x 4 rows x 66 cols, interleaved (hi,lo)
        for (int e = tid; e < 8*264; e += 256) {
            int ci2 = e / 264;
            int rem = e - ci2*264;
            int r = rem / 66;
            int c = rem - r*66;
            int gh = h0 - 1 + r, gw = c - 1;
            float v0 = 0.f, v1 = 0.f;
            if (gh >= 0 && gh < Hh && gw >= 0 && gw < Ww) {
                const float* p = x + ((size_t)(b*Cc + cib*16 + 2*ci2))*HW + gh*Ww + gw;
                v0 = __ldg(p);
                v1 = __ldg(p + HW);
            }
            __nv_bfloat16 h0b = __float2bfloat16_rn(v0), h1b = __float2bfloat16_rn(v1);
            __nv_bfloat16 l0b = __float2bfloat16_rn(v0 - __bfloat162float(h0b));
            __nv_bfloat16 l1b = __float2bfloat16_rn(v1 - __bfloat162float(h1b));
            sX[ci2*SXB2 + rem] = make_uint2(pkbf(h0b, h1b), pkbf(l0b, l1b));
        }
        // ---- stage W: ALL 9 taps for this cib
        {
            const size_t base = (size_t)(cib*8)*256 + cog*128;
#pragma unroll 4
            for (int e = tid; e < 9*1024; e += 256) {
                int tap = e >> 10, rem = e & 1023;
                int ci2 = rem >> 7, col = rem & 127;
                sW[tap*SWT2 + ci2*SWB2 + col] =
                    __ldg(g_wb + (size_t)tap*32768 + base + (size_t)ci2*256 + col);
            }
        }
        __syncthreads();

#pragma unroll
        for (int tap = 0; tap < 9; tap++) {
            const int dh = tap/3 - 1, dw = tap%3 - 1;
            const uint2* wt = sW + tap*SWT2;

            uint2 a[2][4];
#pragma unroll
            for (int mt = 0; mt < 2; mt++) {
                int cb = wm*32 + mt*16 + gid;
                a[mt][0] = wt[tig*SWB2 + cb];
                a[mt][1] = wt[tig*SWB2 + cb + 8];
                a[mt][2] = wt[(tig+4)*SWB2 + cb];
                a[mt][3] = wt[(tig+4)*SWB2 + cb + 8];
            }
            const int boff = tig*SXB2 + (wn + 1 + dh)*66 + 1 + dw + gid;
#pragma unroll
            for (int nt = 0; nt < 8; nt++) {
                uint2 b0 = sX[boff + nt*8];
                uint2 b1 = sX[boff + nt*8 + 4*SXB2];
#pragma unroll
                for (int mt = 0; mt < 2; mt++) {
                    mma_bf16(acc[mt][nt], a[mt][0].x,a[mt][1].x,a[mt][2].x,a[mt][3].x, b0.x, b1.x);
                    mma_bf16(acc[mt][nt], a[mt][0].x,a[mt][1].x,a[mt][2].x,a[mt][3].x, b0.y, b1.y);
                    mma_bf16(acc[mt][nt], a[mt][0].y,a[mt][1].y,a[mt][2].y,a[mt][3].y, b0.x, b1.x);
                }
            }
        }
    }

#pragma unroll
    for (int mt = 0; mt < 2; mt++) {
        int co0 = cog*128 + wm*32 + mt*16 + gid;
        float b0 = __ldg(bias + co0);
        float b1 = __ldg(bias + co0 + 8);
#pragma unroll
        for (int nt = 0; nt < 8; nt++) {
            int px = pb*128 + wn*64 + nt*8 + 2*tig;
            float2* d0 = (float2*)(g_x + ((size_t)(b*Cc + co0))*HW + px);
            float2* d1 = (float2*)(g_x + ((size_t)(b*Cc + co0 + 8))*HW + px);
            float4 a4 = acc[mt][nt];
            *d0 = make_float2(a4.x + b0, a4.y + b0);
            *d1 = make_float2(a4.z + b1, a4.w + b1);
        }
    }
}

// ================= fused depthwise =================
template<int K>
__device__ __forceinline__ void dw_scale(
    const float* xs, float* hb, float out[16],
    const float* __restrict__ wh_c, const float* __restrict__ wv_c,
    float bh, float bv, int w, int h0)
{
    constexpr int P = K/2;
    float whr[K];
#pragma unroll
    for (int k = 0; k < K; k++) whr[k] = __ldg(wh_c + k);
#pragma unroll
    for (int i = 0; i < 16; i++) {
        int h = h0 + i; float s = bh;
#pragma unroll
        for (int k = 0; k < K; k++) {
            int ww = w + k - P;
            if (ww >= 0 && ww < Ww) s += whr[k] * xs[h*Ww + ww];
        }
        hb[h*Ww + w] = s;
    }
    __syncthreads();
    float wvr[K];
#pragma unroll
    for (int k = 0; k < K; k++) wvr[k] = __ldg(wv_c + k);
#pragma unroll
    for (int i = 0; i < 16; i++) {
        int h = h0 + i; float s = bv;
#pragma unroll
        for (int k = 0; k < K; k++) {
            int hh = h + k - P;
            if (hh >= 0 && hh < Hh) s += wvr[k] * hb[hh*Ww + w];
        }
        out[i] += s;
    }
    __syncthreads();
}

__global__ void __launch_bounds__(256) dwfused_k(
    const float* __restrict__ w01, const float* __restrict__ b01,
    const float* __restrict__ w02, const float* __restrict__ b02,
    const float* __restrict__ w11, const float* __restrict__ b11,
    const float* __restrict__ w12, const float* __restrict__ b12,
    const float* __restrict__ w21, const float* __restrict__ b21,
    const float* __restrict__ w22, const float* __restrict__ b22)
{
    __shared__ float xs[HW];
    __shared__ float hb[HW];
    const int plane = blockIdx.x;
    const int c = plane & (Cc-1);
    const int tid = threadIdx.x;
    const float* src = g_x + (size_t)plane*HW;

#pragma unroll
    for (int s = 0; s < 4; s++)
        ((float4*)xs)[tid + s*256] = ((const float4*)src)[tid + s*256];
    __syncthreads();

    const int w  = tid & 63;
    const int h0 = (tid >> 6) * 16;

    float out[16];
#pragma unroll
    for (int i = 0; i < 16; i++) out[i] = xs[(h0+i)*Ww + w];

    dw_scale<7> (xs, hb, out, w01 + c*7,  w02 + c*7,  __ldg(b01+c), __ldg(b02+c), w, h0);
    dw_scale<11>(xs, hb, out, w11 + c*11, w12 + c*11, __ldg(b11+c), __ldg(b12+c), w, h0);
    dw_scale<21>(xs, hb, out, w21 + c*21, w22 + c*21, __ldg(b21+c), __ldg(b22+c), w, h0);

    float* dst = g_sum + (size_t)plane*HW;
#pragma unroll
    for (int i = 0; i < 16; i++) dst[(h0+i)*Ww + w] = out[i];
}

// ================= fused 1x1 proj + transpose + l2norm =================
__global__ void __launch_bounds__(256, 2) projnorm_k(
    const float* __restrict__ w_proj, const float* __restrict__ b_proj)
{
    __shared__ float ws[Cc*C8];
    __shared__ float sred[4*64*33];
    __shared__ float st[64*33];

    const int tid = threadIdx.x;
    for (int idx = tid; idx < Cc*C8; idx += 256) {
        int o = idx >> 8, c = idx & 255;
        ws[c*C8 + o] = w_proj[o*Cc + c];
    }
    __syncthreads();

    const int px = tid & 63, slice = tid >> 6;
    const int g0 = blockIdx.x * 64;
    const int gp = g0 + px;
    const int b = gp >> 12, k = gp & (HW-1);

    u64 acc[16];
    const u64 zero = pack2(0.f, 0.f);
#pragma unroll
    for (int d = 0; d < 16; d++) acc[d] = zero;

    const float* src = g_sum + (size_t)b*Cc*HW + (size_t)slice*64*HW + k;
    const float* wsl = ws + slice*64*C8;
#pragma unroll 4
    for (int c = 0; c < 64; c++) {
        float v = __ldg(src + (size_t)c*HW);
        u64 vp = pack2(v, v);
        const u64* wrow = (const u64*)(wsl + c*C8);
#pragma unroll
        for (int d = 0; d < 16; d++) acc[d] = ffma2(vp, wrow[d], acc[d]);
    }
    float* srow = sred + (slice*64 + px)*33;
#pragma unroll
    for (int d = 0; d < 16; d++) {
        float2 v = unpack2(acc[d]);
        srow[2*d] = v.x; srow[2*d+1] = v.y;
    }
    __syncthreads();

    for (int e = tid; e < 64*C8; e += 256) {
        int p = e >> 5, o = e & 31;
        float v = __ldg(b_proj + o)
                + sred[(0*64+p)*33 + o] + sred[(1*64+p)*33 + o]
                + sred[(2*64+p)*33 + o] + sred[(3*64+p)*33 + o];
        st[p*33 + o] = v;
    }
    __syncthreads();

    if (tid < 64) {
        int p = tid;
        int gpp = g0 + p;
        int bb = gpp >> 12, kk = gpp & (HW-1);
        float v[C8]; float ss = 0.f;
#pragma unroll
        for (int c = 0; c < C8; c++) { v[c] = st[p*33 + c]; ss += v[c]*v[c]; }
        float n = sqrtf(ss);
        float inv = 1.f / fmaxf(n, 1e-12f);
        g_norm[gpp] = n;
        float4* qp = (float4*)(g_q2n + (size_t)gpp*C8);
#pragma unroll
        for (int d = 0; d < 8; d++)
            qp[d] = make_float4(v[d*4+0]*inv, v[d*4+1]*inv, v[d*4+2]*inv, v[d*4+3]*inv);
        float* tb = g_t + (size_t)bb*C8*HW + kk;
#pragma unroll
        for (int c = 0; c < C8; c++) tb[(size_t)c*HW] = v[c];
    }
}

// ================= gram partials =================
__global__ void __launch_bounds__(256) gram_k()
{
    __shared__ float st[32*129];
    const int slab = blockIdx.x, b = blockIdx.y;
    const int tid = threadIdx.x;
    const float* tb = g_t + (size_t)b*C8*HW + slab*128;
    for (int idx = tid; idx < 32*128; idx += 256) {
        int c = idx >> 7, x = idx & 127;
        st[c*129 + x] = tb[(size_t)c*HW + x];
    }
    __syncthreads();

    const int i  = tid >> 3;
    const int j0 = (tid & 7) * 4;
    const float* ri = st + i*129;
    const float* r0 = st + (j0+0)*129;
    const float* r1 = st + (j0+1)*129;
    const float* r2 = st + (j0+2)*129;
    const float* r3 = st + (j0+3)*129;
    float s0=0.f, s1=0.f, s2=0.f, s3=0.f;
#pragma unroll 8
    for (int x = 0; x < 128; x++) {
        float a = ri[x];
        s0 += a*r0[x]; s1 += a*r1[x]; s2 += a*r2[x]; s3 += a*r3[x];
    }
    float* dst = g_pgram + (((size_t)b*32 + slab) << 10) + i*32 + j0;
    dst[0]=s0; dst[1]=s1; dst[2]=s2; dst[3]=s3;
}

// ================= reduce gram + softmax =================
__global__ void __launch_bounds__(1024) chsoft_k()
{
    const int b = blockIdx.x;
    const int tid = threadIdx.x;
    __shared__ float G[1024];
    __shared__ float ninv[32];

    float g = 0.f;
#pragma unroll
    for (int s = 0; s < 32; s++)
        g += g_pgram[(((size_t)b*32 + s) << 10) + tid];
    G[tid] = g;
    if ((tid >> 5) == (tid & 31)) ninv[tid & 31] = 1.f / fmaxf(sqrtf(g), 1e-12f);
    __syncthreads();

    if (tid < 32) {
        int r = tid;
        float ir = ninv[r];
        float row[32]; float s = 0.f;
#pragma unroll
        for (int jj = 0; jj < 32; jj++) {
            float a = G[r*32 + jj] * ir * ninv[jj];
            float p = expf(a - 1.f);
            row[jj] = p; s += p;
        }
        float is = 1.f / s;
        float* dst = g_attn1 + b*C8*C8 + r*32;
#pragma unroll
        for (int jj = 0; jj < 32; jj++) dst[jj] = row[jj] * is;
    }
}

// ================= flash spatial attention, bf16 TC, interleaved hi/lo =================
// grid (32 q-tiles of 128, 4 b), block 256 (8 warps x 16 q-rows)
#define SPN2 20   // uint2 stride per key, [key][dimpair] -> (hi,lo)
#define SPD2 68   // uint2 stride per dim, [dim][keypair] -> (hi,lo)
#define SPP  68   // u32 stride per P row

__global__ void __launch_bounds__(256, 2) spflash_k()
{
    extern __shared__ uint32_t su[];
    uint2*    sKn = (uint2*)su;               // 128*20 uint2
    uint2*    sKd = sKn + 128*SPN2;           // 32*68 uint2
    uint32_t* sP  = (uint32_t*)(sKd + 32*SPD2); // 8*16*68 u32
    float*    sN  = (float*)(sP + 8*16*SPP);  // 128

    const int tid = threadIdx.x;
    const int w = tid >> 5, lane = tid & 31;
    const int gid = lane >> 2, tig = lane & 3;
    const int b = blockIdx.y;
    const int qb = blockIdx.x*128 + w*16;

    // Q A-fragments (bf16 hi/lo), 2 k-chunks of 16 dims
    uint32_t qh[2][4], ql[2][4];
    {
        const float* Q = g_q2n + ((size_t)b*HW + qb)*C8;
#pragma unroll
        for (int ks = 0; ks < 2; ks++)
#pragma unroll
        for (int i = 0; i < 4; i++) {
            int row = gid + (i & 1)*8;
            int dim = ks*16 + 2*tig + ((i & 2) ? 8 : 0);
            float f0 = Q[(size_t)row*32 + dim];
            float f1 = Q[(size_t)row*32 + dim + 1];
            __nv_bfloat16 h0 = __float2bfloat16_rn(f0), h1 = __float2bfloat16_rn(f1);
            __nv_bfloat16 l0 = __float2bfloat16_rn(f0 - __bfloat162float(h0));
            __nv_bfloat16 l1 = __float2bfloat16_rn(f1 - __bfloat162float(h1));
            qh[ks][i] = pkbf(h0, h1);
            ql[ks][i] = pkbf(l0, l1);
        }
    }

    float4 acc_o[4];
#pragma unroll
    for (int n = 0; n < 4; n++) acc_o[n] = make_float4(0.f,0.f,0.f,0.f);
    float l0 = 0.f, l1 = 0.f;
    uint32_t* sPw = sP + w*16*SPP;

    for (int kt = 0; kt < 32; kt++) {
        __syncthreads();
        // ---- stage K tile: interleaved (hi,lo) in [key][dimpair] and [dim][keypair]
        {
            int key = tid & 127, dh = tid >> 7;
            const float4* src = (const float4*)(g_q2n + ((size_t)b*HW + kt*128 + key)*C8 + dh*16);
            __nv_bfloat16* kdb = (__nv_bfloat16*)sKd;
            const int key2 = key >> 1, kp = key & 1;
#pragma unroll
            for (int q4 = 0; q4 < 4; q4++) {
                float4 v = src[q4];
                int dim = dh*16 + q4*4;
                float fs[4] = {v.x, v.y, v.z, v.w};
                __nv_bfloat16 h[4], l[4];
#pragma unroll
                for (int j = 0; j < 4; j++) {
                    h[j] = __float2bfloat16_rn(fs[j]);
                    l[j] = __float2bfloat16_rn(fs[j] - __bfloat162float(h[j]));
                }
                sKn[key*SPN2 + (dim>>1)    ] = make_uint2(pkbf(h[0],h[1]), pkbf(l[0],l[1]));
                sKn[key*SPN2 + (dim>>1) + 1] = make_uint2(pkbf(h[2],h[3]), pkbf(l[2],l[3]));
#pragma unroll
                for (int j = 0; j < 4; j++) {
                    int base = ((dim+j)*SPD2 + key2) * 4;
                    kdb[base + kp]     = h[j];
                    kdb[base + 2 + kp] = l[j];
                }
            }
            if (tid < 128) sN[tid] = g_norm[(size_t)b*HW + kt*128 + tid];
        }
        __syncthreads();

        // ---- S = Q @ K^T (bf16 2-way split), exp, fold norm, pack P (bf16)
#pragma unroll 4
        for (int nt = 0; nt < 16; nt++) {
            float4 s = make_float4(0.f,0.f,0.f,0.f);
            const int key = nt*8 + gid;
#pragma unroll
            for (int ks = 0; ks < 2; ks++) {
                uint2 B0 = sKn[key*SPN2 + ks*8 + tig];
                uint2 B1 = sKn[key*SPN2 + ks*8 + tig + 4];
                mma_bf16(s, qh[ks][0],qh[ks][1],qh[ks][2],qh[ks][3], B0.x, B1.x);
                mma_bf16(s, qh[ks][0],qh[ks][1],qh[ks][2],qh[ks][3], B0.y, B1.y);
                mma_bf16(s, ql[ks][0],ql[ks][1],ql[ks][2],ql[ks][3], B0.x, B1.x);
            }
            float n0 = sN[nt*8 + 2*tig], n1 = sN[nt*8 + 2*tig + 1];
            float e0 = __expf(s.x - 1.f), e1 = __expf(s.y - 1.f);
            float e2 = __expf(s.z - 1.f), e3 = __expf(s.w - 1.f);
            l0 += e0 + e1;
            l1 += e2 + e3;
            sPw[(size_t)gid*SPP     + nt*4 + tig] =
                pkbf(__float2bfloat16_rn(e0*n0), __float2bfloat16_rn(e1*n1));
            sPw[(size_t)(gid+8)*SPP + nt*4 + tig] =
                pkbf(__float2bfloat16_rn(e2*n0), __float2bfloat16_rn(e3*n1));
        }
        __syncwarp();

        // ---- O += P @ V  (V = diag(n)K folded into P; V hi+lo)
#pragma unroll
        for (int ks2 = 0; ks2 < 8; ks2++) {
            uint32_t a0 = sPw[(size_t)gid*SPP     + ks2*8 + tig];
            uint32_t a1 = sPw[(size_t)(gid+8)*SPP + ks2*8 + tig];
            uint32_t a2 = sPw[(size_t)gid*SPP     + ks2*8 + tig + 4];
            uint32_t a3 = sPw[(size_t)(gid+8)*SPP + ks2*8 + tig + 4];
#pragma unroll
            for (int nt2 = 0; nt2 < 4; nt2++) {
                int dimc = nt2*8 + gid;
                uint2 V0 = sKd[dimc*SPD2 + ks2*8 + tig];
                uint2 V1 = sKd[dimc*SPD2 + ks2*8 + tig + 4];
                mma_bf16(acc_o[nt2], a0,a1,a2,a3, V0.x, V1.x);
                mma_bf16(acc_o[nt2], a0,a1,a2,a3, V0.y, V1.y);
            }
        }
    }

    l0 += __shfl_xor_sync(0xffffffffu, l0, 1);
    l0 += __shfl_xor_sync(0xffffffffu, l0, 2);
    l1 += __shfl_xor_sync(0xffffffffu, l1, 1);
    l1 += __shfl_xor_sync(0xffffffffu, l1, 2);
    float i0 = 1.f / l0, i1 = 1.f / l1;

    int q0 = qb + gid, q1 = qb + gid + 8;
#pragma unroll
    for (int nt2 = 0; nt2 < 4; nt2++) {
        int d0 = nt2*8 + 2*tig, d1 = d0 + 1;
        g_out3[((size_t)b*C8 + d0)*HW + q0] = acc_o[nt2].x * i0;
        g_out3[((size_t)b*C8 + d1)*HW + q0] = acc_o[nt2].y * i0;
        g_out3[((size_t)b*C8 + d0)*HW + q1] = acc_o[nt2].z * i1;
        g_out3[((size_t)b*C8 + d1)*HW + q1] = acc_o[nt2].w * i1;
    }
}

// ================= final: fused chout + 1x1s =================
__global__ void __launch_bounds__(256, 2) final_k(
    const float* __restrict__ w3, const float* __restrict__ b3,
    const float* __restrict__ w4, const float* __restrict__ b4,
    float* __restrict__ out)
{
    __shared__ float sw3[64*32];
    __shared__ float sw4[Cc*C8];
    __shared__ float sb4[Cc];
    __shared__ float sA[C8*C8];
    __shared__ float so3[64*33];

    const int tid = threadIdx.x;
    const int px = tid & 63, coh = tid >> 6;
    const int g0 = blockIdx.x * 64;
    const int gp = g0 + px;
    const int b = gp >> 12, k = gp & (HW-1);

    for (int idx = tid; idx < 64*32; idx += 256) {
        int j = idx >> 5, o = idx & 31;
        sw3[j*32 + o] = w3[o*64 + j];
    }
    for (int idx = tid; idx < Cc*C8; idx += 256) sw4[idx] = w4[idx];
    if (tid < Cc) sb4[tid] = b4[tid];
    for (int idx = tid; idx < C8*C8; idx += 256) sA[idx] = g_attn1[b*C8*C8 + idx];

    if (coh == 0) {
        const float* o3 = g_out3 + (size_t)b*C8*HW + k;
#pragma unroll
        for (int c = 0; c < C8; c++) so3[px*33 + c] = __ldg(o3 + (size_t)c*HW);
    }
    __syncthreads();

    float tv[C8];
    {
        const float* tb = g_t + (size_t)b*C8*HW + k;
#pragma unroll
        for (int c = 0; c < C8; c++) tv[c] = tb[(size_t)c*HW];
    }
    u64 tvp[16];
#pragma unroll
    for (int d = 0; d < 16; d++) tvp[d] = pack2(tv[2*d], tv[2*d+1]);

    float out2[C8];
#pragma unroll
    for (int i = 0; i < C8; i++) {
        const u64* ar = (const u64*)(sA + i*32);
        u64 s2 = pack2(0.f, 0.f);
#pragma unroll
        for (int d = 0; d < 16; d++) s2 = ffma2(ar[d], tvp[d], s2);
        float2 f = unpack2(s2);
        out2[i] = f.x + f.y;
    }

    u64 o5[16];
#pragma unroll
    for (int d = 0; d < 16; d++)
        o5[d] = pack2(__ldg(b3 + 2*d) + tv[2*d], __ldg(b3 + 2*d+1) + tv[2*d+1]);

#pragma unroll 4
    for (int j = 0; j < 32; j++) {
        u64 vp = pack2(out2[j], out2[j]);
        const u64* wr = (const u64*)(sw3 + j*32);
#pragma unroll
        for (int d = 0; d < 16; d++) o5[d] = ffma2(vp, wr[d], o5[d]);
    }
#pragma unroll 4
    for (int j = 0; j < 32; j++) {
        float v = so3[px*33 + j];
        u64 vp = pack2(v, v);
        const u64* wr = (const u64*)(sw3 + (32+j)*32);
#pragma unroll
        for (int d = 0; d < 16; d++) o5[d] = ffma2(vp, wr[d], o5[d]);
    }

    const int co0 = coh * 64;
    float* dst = out + (size_t)b*Cc*HW + (size_t)co0*HW + k;
#pragma unroll 2
    for (int cc = 0; cc < 64; cc += 2) {
        const u64* w0 = (const u64*)(sw4 + (co0+cc)*C8);
        const u64* w1 = (const u64*)(sw4 + (co0+cc+1)*C8);
        u64 s0 = pack2(0.f, 0.f), s1 = pack2(0.f, 0.f);
#pragma unroll
        for (int d = 0; d < 16; d++) {
            s0 = ffma2(w0[d], o5[d], s0);
            s1 = ffma2(w1[d], o5[d], s1);
        }
        float2 f0 = unpack2(s0), f1 = unpack2(s1);
        dst[(size_t)cc*HW]     = f0.x + f0.y + sb4[co0+cc];
        dst[(size_t)(cc+1)*HW] = f1.x + f1.y + sb4[co0+cc+1];
    }
}

// ================= launch =================
extern "C" void kernel_launch(void* const* d_in, const int* in_sizes, int n_in,
                              void* d_out, int out_size)
{
    const float* x      = (const float*)d_in[0];
    const float* w_conv = (const float*)d_in[1];
    const float* b_conv = (const float*)d_in[2];
    const float* w01 = (const float*)d_in[3];
    const float* b01 = (const float*)d_in[4];
    const float* w02 = (const float*)d_in[5];
    const float* b02 = (const float*)d_in[6];
    const float* w11 = (const float*)d_in[7];
    const float* b11 = (const float*)d_in[8];
    const float* w12 = (const float*)d_in[9];
    const float* b12 = (const float*)d_in[10];
    const float* w21 = (const float*)d_in[11];
    const float* b21 = (const float*)d_in[12];
    const float* w22 = (const float*)d_in[13];
    const float* b22 = (const float*)d_in[14];
    const float* w_proj = (const float*)d_in[15];
    const float* b_proj = (const float*)d_in[16];
    const float* w3 = (const float*)d_in[17];
    const float* b3 = (const float*)d_in[18];
    const float* w4 = (const float*)d_in[19];
    const float* b4 = (const float*)d_in[20];
    float* out = (float*)d_out;

    const int convSmem = (SX_ELEMS2 + SW_ALL2) * (int)sizeof(uint2);
    const int spSmem   = (128*SPN2 + 32*SPD2) * (int)sizeof(uint2)
                       + 8*16*SPP * (int)sizeof(uint32_t)
                       + 128 * (int)sizeof(float);
    static bool attrSet = false;
    if (!attrSet) {
        cudaFuncSetAttribute(convmma_k, cudaFuncAttributeMaxDynamicSharedMemorySize, convSmem);
        cudaFuncSetAttribute(spflash_k, cudaFuncAttributeMaxDynamicSharedMemorySize, spSmem);
        attrSet = true;
    }

    wprep_k   <<<9*128*Cc/256, 256>>>(w_conv);
    convmma_k <<<dim3(32, 2, 4), 256, convSmem>>>(x, b_conv);
    dwfused_k <<<Bn*Cc, 256>>>(w01, b01, w02, b02, w11, b11, w12, b12, w21, b21, w22, b22);
    projnorm_k<<<256, 256>>>(w_proj, b_proj);
    gram_k    <<<dim3(32, 4), 256>>>();
    chsoft_k  <<<4, 1024>>>();
    spflash_k <<<dim3(32, 4), 256, spSmem>>>();
    final_k   <<<256, 256>>>(w3, b3, w4, b4, out);
}

// round 10
// speedup vs baseline: 1.0947x; 1.0947x over previous
#include <cuda_runtime.h>
#include <cuda_bf16.h>
#include <math.h>
#include <stdint.h>

#define Bn 4
#define Cc 256
#define C8 32
#define Hh 64
#define Ww 64
#define HW 4096

typedef unsigned long long u64;

__device__ __forceinline__ u64 ffma2(u64 a, u64 b, u64 c){
    u64 d; asm("fma.rn.f32x2 %0, %1, %2, %3;" : "=l"(d) : "l"(a), "l"(b), "l"(c)); return d;
}
__device__ __forceinline__ u64 pack2(float lo, float hi){
    u64 d; asm("mov.b64 %0, {%1, %2};" : "=l"(d) : "f"(lo), "f"(hi)); return d;
}
__device__ __forceinline__ float2 unpack2(u64 v){
    float lo, hi; asm("mov.b64 {%0, %1}, %2;" : "=f"(lo), "=f"(hi) : "l"(v));
    return make_float2(lo, hi);
}
__device__ __forceinline__ void mma_bf16(float4& d, const uint32_t a0, const uint32_t a1,
                                         const uint32_t a2, const uint32_t a3,
                                         const uint32_t b0, const uint32_t b1){
    asm volatile(
      "mma.sync.aligned.m16n8k16.row.col.f32.bf16.bf16.f32 "
      "{%0,%1,%2,%3}, {%4,%5,%6,%7}, {%8,%9}, {%0,%1,%2,%3};"
      : "+f"(d.x), "+f"(d.y), "+f"(d.z), "+f"(d.w)
      : "r"(a0), "r"(a1), "r"(a2), "r"(a3), "r"(b0), "r"(b1));
}
__device__ __forceinline__ uint32_t pkbf(__nv_bfloat16 a, __nv_bfloat16 b){
    __nv_bfloat162 t = __halves2bfloat162(a, b);
    return *reinterpret_cast<uint32_t*>(&t);
}

// ---------------- scratch ----------------
__device__ float g_x  [Bn*Cc*HW];
__device__ float g_sum[Bn*Cc*HW];
__device__ float g_t  [Bn*C8*HW];
__device__ float g_attn1[Bn*C8*C8];
__device__ float g_out3[Bn*C8*HW];
__device__ float g_q2n [Bn*HW*C8];
__device__ float g_norm[Bn*HW];
__device__ float g_pgram[Bn*32*C8*C8];
__device__ uint32_t g_wbh[9*128*Cc];   // [tap][ci2][co] bf16-pair hi
__device__ uint32_t g_wbl[9*128*Cc];   // bf16-pair lo

// ================= weight prep: bf16 hi/lo pairs, [tap][ci2][co] =================
__global__ void __launch_bounds__(256) wprep_k(const float* __restrict__ w)
{
    int idx = blockIdx.x * 256 + threadIdx.x;   // 9*128*256 = 294912
    int co  = idx & 255;
    int ci2 = (idx >> 8) & 127;
    int tap = idx >> 15;
    float v0 = w[((size_t)co*Cc + 2*ci2    )*9 + tap];
    float v1 = w[((size_t)co*Cc + 2*ci2 + 1)*9 + tap];
    __nv_bfloat16 h0 = __float2bfloat16_rn(v0), h1 = __float2bfloat16_rn(v1);
    __nv_bfloat16 l0 = __float2bfloat16_rn(v0 - __bfloat162float(h0));
    __nv_bfloat16 l1 = __float2bfloat16_rn(v1 - __bfloat162float(h1));
    g_wbh[idx] = pkbf(h0, h1);
    g_wbl[idx] = pkbf(l0, l1);
}

// ================= 3x3 conv via bf16 m16n8k16 MMA, all-taps W staging =================
// grid (32 pb, 2 cog, 4 b), block 256 (8 warps). CTA tile: 128 co x 128 px.
#define SXB 264            // u32 stride per ci2 for X strip (4 rows x 66)
#define SWB 136            // u32 stride per ci2 for W tile (128 co, padded)
#define SWT (8*SWB)        // per-tap W block (1088)
#define SXB_ELEMS (8*SXB)  // 2112
#define SW_ALL (9*SWT)     // 9792

__global__ void __launch_bounds__(256, 2) convmma_k(
    const float* __restrict__ x, const float* __restrict__ bias)
{
    extern __shared__ uint32_t smu[];
    uint32_t* sXh = smu;
    uint32_t* sXl = sXh + SXB_ELEMS;
    uint32_t* sWh = sXl + SXB_ELEMS;
    uint32_t* sWl = sWh + SW_ALL;

    const int pb = blockIdx.x, cog = blockIdx.y, b = blockIdx.z;
    const int tid  = threadIdx.x;
    const int wid  = tid >> 5, lane = tid & 31;
    const int wm   = wid >> 1, wn = wid & 1;
    const int gid  = lane >> 2, tig = lane & 3;
    const int h0   = pb * 2;

    float4 acc[2][8];
#pragma unroll
    for (int mt = 0; mt < 2; mt++)
#pragma unroll
        for (int nt = 0; nt < 8; nt++) acc[mt][nt] = make_float4(0.f,0.f,0.f,0.f);

    for (int cib = 0; cib < Cc/16; cib++) {
        __syncthreads();
        // ---- stage X strip: 8 ci-pairs x 4 rows x 66 cols, bf16 hi/lo pairs
        for (int e = tid; e < 8*264; e += 256) {
            int ci2 = e / 264;
            int rem = e - ci2*264;
            int r = rem / 66;
            int c = rem - r*66;
            int gh = h0 - 1 + r, gw = c - 1;
            float v0 = 0.f, v1 = 0.f;
            if (gh >= 0 && gh < Hh && gw >= 0 && gw < Ww) {
                const float* p = x + ((size_t)(b*Cc + cib*16 + 2*ci2))*HW + gh*Ww + gw;
                v0 = __ldg(p);
                v1 = __ldg(p + HW);
            }
            __nv_bfloat16 h0b = __float2bfloat16_rn(v0), h1b = __float2bfloat16_rn(v1);
            __nv_bfloat16 l0b = __float2bfloat16_rn(v0 - __bfloat162float(h0b));
            __nv_bfloat16 l1b = __float2bfloat16_rn(v1 - __bfloat162float(h1b));
            sXh[e] = pkbf(h0b, h1b);
            sXl[e] = pkbf(l0b, l1b);
        }
        // ---- stage W: ALL 9 taps for this cib
        {
            const size_t base = (size_t)(cib*8)*256 + cog*128;
#pragma unroll 4
            for (int e = tid; e < 9*1024; e += 256) {
                int tap = e >> 10, rem = e & 1023;
                int ci2 = rem >> 7, col = rem & 127;
                size_t src = (size_t)tap*32768 + base + (size_t)ci2*256 + col;
                int dst = tap*SWT + ci2*SWB + col;
                sWh[dst] = __ldg(g_wbh + src);
                sWl[dst] = __ldg(g_wbl + src);
            }
        }
        __syncthreads();

#pragma unroll
        for (int tap = 0; tap < 9; tap++) {
            const int dh = tap/3 - 1, dw = tap%3 - 1;
            const uint32_t* wh = sWh + tap*SWT;
            const uint32_t* wl = sWl + tap*SWT;

            uint32_t ah[2][4], al[2][4];
#pragma unroll
            for (int mt = 0; mt < 2; mt++) {
                int cb = wm*32 + mt*16 + gid;
                ah[mt][0] = wh[tig*SWB + cb];       ah[mt][1] = wh[tig*SWB + cb + 8];
                ah[mt][2] = wh[(tig+4)*SWB + cb];   ah[mt][3] = wh[(tig+4)*SWB + cb + 8];
                al[mt][0] = wl[tig*SWB + cb];       al[mt][1] = wl[tig*SWB + cb + 8];
                al[mt][2] = wl[(tig+4)*SWB + cb];   al[mt][3] = wl[(tig+4)*SWB + cb + 8];
            }
            const int boff = tig*SXB + (wn + 1 + dh)*66 + 1 + dw + gid;
#pragma unroll
            for (int nt = 0; nt < 8; nt++) {
                uint32_t b0h = sXh[boff + nt*8], b1h = sXh[boff + nt*8 + 4*SXB];
                uint32_t b0l = sXl[boff + nt*8], b1l = sXl[boff + nt*8 + 4*SXB];
#pragma unroll
                for (int mt = 0; mt < 2; mt++) {
                    mma_bf16(acc[mt][nt], ah[mt][0],ah[mt][1],ah[mt][2],ah[mt][3], b0h, b1h);
                    mma_bf16(acc[mt][nt], ah[mt][0],ah[mt][1],ah[mt][2],ah[mt][3], b0l, b1l);
                    mma_bf16(acc[mt][nt], al[mt][0],al[mt][1],al[mt][2],al[mt][3], b0h, b1h);
                }
            }
        }
    }

#pragma unroll
    for (int mt = 0; mt < 2; mt++) {
        int co0 = cog*128 + wm*32 + mt*16 + gid;
        float b0 = __ldg(bias + co0);
        float b1 = __ldg(bias + co0 + 8);
#pragma unroll
        for (int nt = 0; nt < 8; nt++) {
            int px = pb*128 + wn*64 + nt*8 + 2*tig;
            float2* d0 = (float2*)(g_x + ((size_t)(b*Cc + co0))*HW + px);
            float2* d1 = (float2*)(g_x + ((size_t)(b*Cc + co0 + 8))*HW + px);
            float4 a = acc[mt][nt];
            *d0 = make_float2(a.x + b0, a.y + b0);
            *d1 = make_float2(a.z + b1, a.w + b1);
        }
    }
}

// ================= fused depthwise =================
template<int K>
__device__ __forceinline__ void dw_scale(
    const float* xs, float* hb, float out[16],
    const float* __restrict__ wh_c, const float* __restrict__ wv_c,
    float bh, float bv, int w, int h0)
{
    constexpr int P = K/2;
    float whr[K];
#pragma unroll
    for (int k = 0; k < K; k++) whr[k] = __ldg(wh_c + k);
#pragma unroll
    for (int i = 0; i < 16; i++) {
        int h = h0 + i; float s = bh;
#pragma unroll
        for (int k = 0; k < K; k++) {
            int ww = w + k - P;
            if (ww >= 0 && ww < Ww) s += whr[k] * xs[h*Ww + ww];
        }
        hb[h*Ww + w] = s;
    }
    __syncthreads();
    float wvr[K];
#pragma unroll
    for (int k = 0; k < K; k++) wvr[k] = __ldg(wv_c + k);
#pragma unroll
    for (int i = 0; i < 16; i++) {
        int h = h0 + i; float s = bv;
#pragma unroll
        for (int k = 0; k < K; k++) {
            int hh = h + k - P;
            if (hh >= 0 && hh < Hh) s += wvr[k] * hb[hh*Ww + w];
        }
        out[i] += s;
    }
    __syncthreads();
}

__global__ void __launch_bounds__(256) dwfused_k(
    const float* __restrict__ w01, const float* __restrict__ b01,
    const float* __restrict__ w02, const float* __restrict__ b02,
    const float* __restrict__ w11, const float* __restrict__ b11,
    const float* __restrict__ w12, const float* __restrict__ b12,
    const float* __restrict__ w21, const float* __restrict__ b21,
    const float* __restrict__ w22, const float* __restrict__ b22)
{
    __shared__ float xs[HW];
    __shared__ float hb[HW];
    const int plane = blockIdx.x;
    const int c = plane & (Cc-1);
    const int tid = threadIdx.x;
    const float* src = g_x + (size_t)plane*HW;

#pragma unroll
    for (int s = 0; s < 4; s++)
        ((float4*)xs)[tid + s*256] = ((const float4*)src)[tid + s*256];
    __syncthreads();

    const int w  = tid & 63;
    const int h0 = (tid >> 6) * 16;

    float out[16];
#pragma unroll
    for (int i = 0; i < 16; i++) out[i] = xs[(h0+i)*Ww + w];

    dw_scale<7> (xs, hb, out, w01 + c*7,  w02 + c*7,  __ldg(b01+c), __ldg(b02+c), w, h0);
    dw_scale<11>(xs, hb, out, w11 + c*11, w12 + c*11, __ldg(b11+c), __ldg(b12+c), w, h0);
    dw_scale<21>(xs, hb, out, w21 + c*21, w22 + c*21, __ldg(b21+c), __ldg(b22+c), w, h0);

    float* dst = g_sum + (size_t)plane*HW;
#pragma unroll
    for (int i = 0; i < 16; i++) dst[(h0+i)*Ww + w] = out[i];
}

// ================= fused 1x1 proj + transpose + l2norm =================
__global__ void __launch_bounds__(256, 2) projnorm_k(
    const float* __restrict__ w_proj, const float* __restrict__ b_proj)
{
    __shared__ float ws[Cc*C8];
    __shared__ float sred[4*64*33];
    __shared__ float st[64*33];

    const int tid = threadIdx.x;
    for (int idx = tid; idx < Cc*C8; idx += 256) {
        int o = idx >> 8, c = idx & 255;
        ws[c*C8 + o] = w_proj[o*Cc + c];
    }
    __syncthreads();

    const int px = tid & 63, slice = tid >> 6;
    const int g0 = blockIdx.x * 64;
    const int gp = g0 + px;
    const int b = gp >> 12, k = gp & (HW-1);

    u64 acc[16];
    const u64 zero = pack2(0.f, 0.f);
#pragma unroll
    for (int d = 0; d < 16; d++) acc[d] = zero;

    const float* src = g_sum + (size_t)b*Cc*HW + (size_t)slice*64*HW + k;
    const float* wsl = ws + slice*64*C8;
#pragma unroll 4
    for (int c = 0; c < 64; c++) {
        float v = __ldg(src + (size_t)c*HW);
        u64 vp = pack2(v, v);
        const u64* wrow = (const u64*)(wsl + c*C8);
#pragma unroll
        for (int d = 0; d < 16; d++) acc[d] = ffma2(vp, wrow[d], acc[d]);
    }
    float* srow = sred + (slice*64 + px)*33;
#pragma unroll
    for (int d = 0; d < 16; d++) {
        float2 v = unpack2(acc[d]);
        srow[2*d] = v.x; srow[2*d+1] = v.y;
    }
    __syncthreads();

    for (int e = tid; e < 64*C8; e += 256) {
        int p = e >> 5, o = e & 31;
        float v = __ldg(b_proj + o)
                + sred[(0*64+p)*33 + o] + sred[(1*64+p)*33 + o]
                + sred[(2*64+p)*33 + o] + sred[(3*64+p)*33 + o];
        st[p*33 + o] = v;
    }
    __syncthreads();

    if (tid < 64) {
        int p = tid;
        int gpp = g0 + p;
        int bb = gpp >> 12, kk = gpp & (HW-1);
        float v[C8]; float ss = 0.f;
#pragma unroll
        for (int c = 0; c < C8; c++) { v[c] = st[p*33 + c]; ss += v[c]*v[c]; }
        float n = sqrtf(ss);
        float inv = 1.f / fmaxf(n, 1e-12f);
        g_norm[gpp] = n;
        float4* qp = (float4*)(g_q2n + (size_t)gpp*C8);
#pragma unroll
        for (int d = 0; d < 8; d++)
            qp[d] = make_float4(v[d*4+0]*inv, v[d*4+1]*inv, v[d*4+2]*inv, v[d*4+3]*inv);
        float* tb = g_t + (size_t)bb*C8*HW + kk;
#pragma unroll
        for (int c = 0; c < C8; c++) tb[(size_t)c*HW] = v[c];
    }
}

// ================= gram partials =================
__global__ void __launch_bounds__(256) gram_k()
{
    __shared__ float st[32*129];
    const int slab = blockIdx.x, b = blockIdx.y;
    const int tid = threadIdx.x;
    const float* tb = g_t + (size_t)b*C8*HW + slab*128;
    for (int idx = tid; idx < 32*128; idx += 256) {
        int c = idx >> 7, x = idx & 127;
        st[c*129 + x] = tb[(size_t)c*HW + x];
    }
    __syncthreads();

    const int i  = tid >> 3;
    const int j0 = (tid & 7) * 4;
    const float* ri = st + i*129;
    const float* r0 = st + (j0+0)*129;
    const float* r1 = st + (j0+1)*129;
    const float* r2 = st + (j0+2)*129;
    const float* r3 = st + (j0+3)*129;
    float s0=0.f, s1=0.f, s2=0.f, s3=0.f;
#pragma unroll 8
    for (int x = 0; x < 128; x++) {
        float a = ri[x];
        s0 += a*r0[x]; s1 += a*r1[x]; s2 += a*r2[x]; s3 += a*r3[x];
    }
    float* dst = g_pgram + (((size_t)b*32 + slab) << 10) + i*32 + j0;
    dst[0]=s0; dst[1]=s1; dst[2]=s2; dst[3]=s3;
}

// ================= reduce gram + softmax =================
__global__ void __launch_bounds__(1024) chsoft_k()
{
    const int b = blockIdx.x;
    const int tid = threadIdx.x;
    __shared__ float G[1024];
    __shared__ float ninv[32];

    float g = 0.f;
#pragma unroll
    for (int s = 0; s < 32; s++)
        g += g_pgram[(((size_t)b*32 + s) << 10) + tid];
    G[tid] = g;
    if ((tid >> 5) == (tid & 31)) ninv[tid & 31] = 1.f / fmaxf(sqrtf(g), 1e-12f);
    __syncthreads();

    if (tid < 32) {
        int r = tid;
        float ir = ninv[r];
        float row[32]; float s = 0.f;
#pragma unroll
        for (int jj = 0; jj < 32; jj++) {
            float a = G[r*32 + jj] * ir * ninv[jj];
            float p = expf(a - 1.f);
            row[jj] = p; s += p;
        }
        float is = 1.f / s;
        float* dst = g_attn1 + b*C8*C8 + r*32;
#pragma unroll
        for (int jj = 0; jj < 32; jj++) dst[jj] = row[jj] * is;
    }
}

// ================= flash spatial attention, bf16 tensor cores =================
// grid (32 q-tiles of 128, 4 b), block 256 (8 warps x 16 q-rows)
#define SPN 20    // u32 stride per key, [key][dimpair]
#define SPD 68    // u32 stride per dim, [dim][keypair]
#define SPP 68    // u32 stride per P row

__global__ void __launch_bounds__(256, 2) spflash_k()
{
    extern __shared__ uint32_t su[];
    uint32_t* sKnh = su;                     // 128*20
    uint32_t* sKnl = sKnh + 128*SPN;
    uint32_t* sKdh = sKnl + 128*SPN;         // 32*68
    uint32_t* sKdl = sKdh + 32*SPD;
    uint32_t* sP   = sKdl + 32*SPD;          // 8*16*68
    float*    sN   = (float*)(sP + 8*16*SPP);// 128

    const int tid = threadIdx.x;
    const int w = tid >> 5, lane = tid & 31;
    const int gid = lane >> 2, tig = lane & 3;
    const int b = blockIdx.y;
    const int qb = blockIdx.x*128 + w*16;

    // Q A-fragments (bf16 hi/lo), 2 k-chunks of 16 dims
    uint32_t qh[2][4], ql[2][4];
    {
        const float* Q = g_q2n + ((size_t)b*HW + qb)*C8;
#pragma unroll
        for (int ks = 0; ks < 2; ks++)
#pragma unroll
        for (int i = 0; i < 4; i++) {
            int row = gid + (i & 1)*8;
            int dim = ks*16 + 2*tig + ((i & 2) ? 8 : 0);
            float f0 = Q[(size_t)row*32 + dim];
            float f1 = Q[(size_t)row*32 + dim + 1];
            __nv_bfloat16 h0 = __float2bfloat16_rn(f0), h1 = __float2bfloat16_rn(f1);
            __nv_bfloat16 l0 = __float2bfloat16_rn(f0 - __bfloat162float(h0));
            __nv_bfloat16 l1 = __float2bfloat16_rn(f1 - __bfloat162float(h1));
            qh[ks][i] = pkbf(h0, h1);
            ql[ks][i] = pkbf(l0, l1);
        }
    }

    float4 acc_o[4];
#pragma unroll
    for (int n = 0; n < 4; n++) acc_o[n] = make_float4(0.f,0.f,0.f,0.f);
    float l0 = 0.f, l1 = 0.f;
    uint32_t* sPw = sP + w*16*SPP;

    for (int kt = 0; kt < 32; kt++) {
        __syncthreads();
        // ---- stage K tile: bf16 hi/lo in [key][dimpair] and [dim][keypair]
        {
            int key = tid & 127, dh = tid >> 7;
            const float4* src = (const float4*)(g_q2n + ((size_t)b*HW + kt*128 + key)*C8 + dh*16);
            __nv_bfloat16* knh = (__nv_bfloat16*)sKnh;
            __nv_bfloat16* knl = (__nv_bfloat16*)sKnl;
            __nv_bfloat16* kdh = (__nv_bfloat16*)sKdh;
            __nv_bfloat16* kdl = (__nv_bfloat16*)sKdl;
#pragma unroll
            for (int q4 = 0; q4 < 4; q4++) {
                float4 v = src[q4];
                int dim = dh*16 + q4*4;
                float fs[4] = {v.x, v.y, v.z, v.w};
#pragma unroll
                for (int j = 0; j < 4; j++) {
                    __nv_bfloat16 h = __float2bfloat16_rn(fs[j]);
                    __nv_bfloat16 l = __float2bfloat16_rn(fs[j] - __bfloat162float(h));
                    knh[key*(2*SPN) + dim + j] = h;
                    knl[key*(2*SPN) + dim + j] = l;
                    kdh[(dim+j)*(2*SPD) + key] = h;
                    kdl[(dim+j)*(2*SPD) + key] = l;
                }
            }
            if (tid < 128) sN[tid] = g_norm[(size_t)b*HW + kt*128 + tid];
        }
        __syncthreads();

        // ---- S = Q @ K^T (bf16 2-way split), exp, fold norm, pack P (bf16)
#pragma unroll 4
        for (int nt = 0; nt < 16; nt++) {
            float4 s = make_float4(0.f,0.f,0.f,0.f);
            const int key = nt*8 + gid;
#pragma unroll
            for (int ks = 0; ks < 2; ks++) {
                uint32_t bh0 = sKnh[key*SPN + ks*8 + tig];
                uint32_t bh1 = sKnh[key*SPN + ks*8 + tig + 4];
                uint32_t bl0 = sKnl[key*SPN + ks*8 + tig];
                uint32_t bl1 = sKnl[key*SPN + ks*8 + tig + 4];
                mma_bf16(s, qh[ks][0],qh[ks][1],qh[ks][2],qh[ks][3], bh0, bh1);
                mma_bf16(s, qh[ks][0],qh[ks][1],qh[ks][2],qh[ks][3], bl0, bl1);
                mma_bf16(s, ql[ks][0],ql[ks][1],ql[ks][2],ql[ks][3], bh0, bh1);
            }
            float n0 = sN[nt*8 + 2*tig], n1 = sN[nt*8 + 2*tig + 1];
            float e0 = __expf(s.x - 1.f), e1 = __expf(s.y - 1.f);
            float e2 = __expf(s.z - 1.f), e3 = __expf(s.w - 1.f);
            l0 += e0 + e1;
            l1 += e2 + e3;
            sPw[(size_t)gid*SPP     + nt*4 + tig] =
                pkbf(__float2bfloat16_rn(e0*n0), __float2bfloat16_rn(e1*n1));
            sPw[(size_t)(gid+8)*SPP + nt*4 + tig] =
                pkbf(__float2bfloat16_rn(e2*n0), __float2bfloat16_rn(e3*n1));
        }
        __syncwarp();

        // ---- O += P @ V  (V = diag(n)K folded into P; V hi+lo)
#pragma unroll
        for (int ks2 = 0; ks2 < 8; ks2++) {
            uint32_t a0 = sPw[(size_t)gid*SPP     + ks2*8 + tig];
            uint32_t a1 = sPw[(size_t)(gid+8)*SPP + ks2*8 + tig];
            uint32_t a2 = sPw[(size_t)gid*SPP     + ks2*8 + tig + 4];
            uint32_t a3 = sPw[(size_t)(gid+8)*SPP + ks2*8 + tig + 4];
#pragma unroll
            for (int nt2 = 0; nt2 < 4; nt2++) {
                int dimc = nt2*8 + gid;
                uint32_t vh0 = sKdh[dimc*SPD + ks2*8 + tig];
                uint32_t vh1 = sKdh[dimc*SPD + ks2*8 + tig + 4];
                uint32_t vl0 = sKdl[dimc*SPD + ks2*8 + tig];
                uint32_t vl1 = sKdl[dimc*SPD + ks2*8 + tig + 4];
                mma_bf16(acc_o[nt2], a0,a1,a2,a3, vh0, vh1);
                mma_bf16(acc_o[nt2], a0,a1,a2,a3, vl0, vl1);
            }
        }
    }

    l0 += __shfl_xor_sync(0xffffffffu, l0, 1);
    l0 += __shfl_xor_sync(0xffffffffu, l0, 2);
    l1 += __shfl_xor_sync(0xffffffffu, l1, 1);
    l1 += __shfl_xor_sync(0xffffffffu, l1, 2);
    float i0 = 1.f / l0, i1 = 1.f / l1;

    int q0 = qb + gid, q1 = qb + gid + 8;
#pragma unroll
    for (int nt2 = 0; nt2 < 4; nt2++) {
        int d0 = nt2*8 + 2*tig, d1 = d0 + 1;
        g_out3[((size_t)b*C8 + d0)*HW + q0] = acc_o[nt2].x * i0;
        g_out3[((size_t)b*C8 + d1)*HW + q0] = acc_o[nt2].y * i0;
        g_out3[((size_t)b*C8 + d0)*HW + q1] = acc_o[nt2].z * i1;
        g_out3[((size_t)b*C8 + d1)*HW + q1] = acc_o[nt2].w * i1;
    }
}

// ================= final: fused chout + 1x1s =================
__global__ void __launch_bounds__(256, 2) final_k(
    const float* __restrict__ w3, const float* __restrict__ b3,
    const float* __restrict__ w4, const float* __restrict__ b4,
    float* __restrict__ out)
{
    __shared__ float sw3[64*32];
    __shared__ float sw4[Cc*C8];
    __shared__ float sb4[Cc];
    __shared__ float sA[C8*C8];
    __shared__ float so3[64*33];

    const int tid = threadIdx.x;
    const int px = tid & 63, coh = tid >> 6;
    const int g0 = blockIdx.x * 64;
    const int gp = g0 + px;
    const int b = gp >> 12, k = gp & (HW-1);

    for (int idx = tid; idx < 64*32; idx += 256) {
        int j = idx >> 5, o = idx & 31;
        sw3[j*32 + o] = w3[o*64 + j];
    }
    for (int idx = tid; idx < Cc*C8; idx += 256) sw4[idx] = w4[idx];
    if (tid < Cc) sb4[tid] = b4[tid];
    for (int idx = tid; idx < C8*C8; idx += 256) sA[idx] = g_attn1[b*C8*C8 + idx];

    if (coh == 0) {
        const float* o3 = g_out3 + (size_t)b*C8*HW + k;
#pragma unroll
        for (int c = 0; c < C8; c++) so3[px*33 + c] = __ldg(o3 + (size_t)c*HW);
    }
    __syncthreads();

    float tv[C8];
    {
        const float* tb = g_t + (size_t)b*C8*HW + k;
#pragma unroll
        for (int c = 0; c < C8; c++) tv[c] = tb[(size_t)c*HW];
    }
    u64 tvp[16];
#pragma unroll
    for (int d = 0; d < 16; d++) tvp[d] = pack2(tv[2*d], tv[2*d+1]);

    float out2[C8];
#pragma unroll
    for (int i = 0; i < C8; i++) {
        const u64* ar = (const u64*)(sA + i*32);
        u64 s2 = pack2(0.f, 0.f);
#pragma unroll
        for (int d = 0; d < 16; d++) s2 = ffma2(ar[d], tvp[d], s2);
        float2 f = unpack2(s2);
        out2[i] = f.x + f.y;
    }

    u64 o5[16];
#pragma unroll
    for (int d = 0; d < 16; d++)
        o5[d] = pack2(__ldg(b3 + 2*d) + tv[2*d], __ldg(b3 + 2*d+1) + tv[2*d+1]);

#pragma unroll 4
    for (int j = 0; j < 32; j++) {
        u64 vp = pack2(out2[j], out2[j]);
        const u64* wr = (const u64*)(sw3 + j*32);
#pragma unroll
        for (int d = 0; d < 16; d++) o5[d] = ffma2(vp, wr[d], o5[d]);
    }
#pragma unroll 4
    for (int j = 0; j < 32; j++) {
        float v = so3[px*33 + j];
        u64 vp = pack2(v, v);
        const u64* wr = (const u64*)(sw3 + (32+j)*32);
#pragma unroll
        for (int d = 0; d < 16; d++) o5[d] = ffma2(vp, wr[d], o5[d]);
    }

    const int co0 = coh * 64;
    float* dst = out + (size_t)b*Cc*HW + (size_t)co0*HW + k;
#pragma unroll 2
    for (int cc = 0; cc < 64; cc += 2) {
        const u64* w0 = (const u64*)(sw4 + (co0+cc)*C8);
        const u64* w1 = (const u64*)(sw4 + (co0+cc+1)*C8);
        u64 s0 = pack2(0.f, 0.f), s1 = pack2(0.f, 0.f);
#pragma unroll
        for (int d = 0; d < 16; d++) {
            s0 = ffma2(w0[d], o5[d], s0);
            s1 = ffma2(w1[d], o5[d], s1);
        }
        float2 f0 = unpack2(s0), f1 = unpack2(s1);
        dst[(size_t)cc*HW]     = f0.x + f0.y + sb4[co0+cc];
        dst[(size_t)(cc+1)*HW] = f1.x + f1.y + sb4[co0+cc+1];
    }
}

// ================= launch =================
extern "C" void kernel_launch(void* const* d_in, const int* in_sizes, int n_in,
                              void* d_out, int out_size)
{
    const float* x      = (const float*)d_in[0];
    const float* w_conv = (const float*)d_in[1];
    const float* b_conv = (const float*)d_in[2];
    const float* w01 = (const float*)d_in[3];
    const float* b01 = (const float*)d_in[4];
    const float* w02 = (const float*)d_in[5];
    const float* b02 = (const float*)d_in[6];
    const float* w11 = (const float*)d_in[7];
    const float* b11 = (const float*)d_in[8];
    const float* w12 = (const float*)d_in[9];
    const float* b12 = (const float*)d_in[10];
    const float* w21 = (const float*)d_in[11];
    const float* b21 = (const float*)d_in[12];
    const float* w22 = (const float*)d_in[13];
    const float* b22 = (const float*)d_in[14];
    const float* w_proj = (const float*)d_in[15];
    const float* b_proj = (const float*)d_in[16];
    const float* w3 = (const float*)d_in[17];
    const float* b3 = (const float*)d_in[18];
    const float* w4 = (const float*)d_in[19];
    const float* b4 = (const float*)d_in[20];
    float* out = (float*)d_out;

    const int convSmem = (2*SXB_ELEMS + 2*SW_ALL) * (int)sizeof(uint32_t);
    const int spSmem   = (2*128*SPN + 2*32*SPD + 8*16*SPP) * (int)sizeof(uint32_t)
                       + 128 * (int)sizeof(float);
    static bool attrSet = false;
    if (!attrSet) {
        cudaFuncSetAttribute(convmma_k, cudaFuncAttributeMaxDynamicSharedMemorySize, convSmem);
        cudaFuncSetAttribute(spflash_k, cudaFuncAttributeMaxDynamicSharedMemorySize, spSmem);
        attrSet = true;
    }

    wprep_k   <<<9*128*Cc/256, 256>>>(w_conv);
    convmma_k <<<dim3(32, 2, 4), 256, convSmem>>>(x, b_conv);
    dwfused_k <<<Bn*Cc, 256>>>(w01, b01, w02, b02, w11, b11, w12, b12, w21, b21, w22, b22);
    projnorm_k<<<256, 256>>>(w_proj, b_proj);
    gram_k    <<<dim3(32, 4), 256>>>();
    chsoft_k  <<<4, 1024>>>();
    spflash_k <<<dim3(32, 4), 256, spSmem>>>();
    final_k   <<<256, 256>>>(w3, b3, w4, b4, out);
}

// round 11
// speedup vs baseline: 1.6265x; 1.4858x over previous
#include <cuda_runtime.h>
#include <cuda_fp16.h>
#include <math.h>
#include <stdint.h>

#define Bn 4
#define Cc 256
#define C8 32
#define Hh 64
#define Ww 64
#define HW 4096

typedef unsigned long long u64;

__device__ __forceinline__ u64 ffma2(u64 a, u64 b, u64 c){
    u64 d; asm("fma.rn.f32x2 %0, %1, %2, %3;" : "=l"(d) : "l"(a), "l"(b), "l"(c)); return d;
}
__device__ __forceinline__ u64 pack2(float lo, float hi){
    u64 d; asm("mov.b64 %0, {%1, %2};" : "=l"(d) : "f"(lo), "f"(hi)); return d;
}
__device__ __forceinline__ float2 unpack2(u64 v){
    float lo, hi; asm("mov.b64 {%0, %1}, %2;" : "=f"(lo), "=f"(hi) : "l"(v));
    return make_float2(lo, hi);
}
__device__ __forceinline__ void mma_f16(float4& d, const uint32_t a0, const uint32_t a1,
                                        const uint32_t a2, const uint32_t a3,
                                        const uint32_t b0, const uint32_t b1){
    asm volatile(
      "mma.sync.aligned.m16n8k16.row.col.f32.f16.f16.f32 "
      "{%0,%1,%2,%3}, {%4,%5,%6,%7}, {%8,%9}, {%0,%1,%2,%3};"
      : "+f"(d.x), "+f"(d.y), "+f"(d.z), "+f"(d.w)
      : "r"(a0), "r"(a1), "r"(a2), "r"(a3), "r"(b0), "r"(b1));
}
__device__ __forceinline__ uint32_t pkhf(float a, float b){
    __half2 t = __floats2half2_rn(a, b);
    return *reinterpret_cast<uint32_t*>(&t);
}

// ---------------- scratch ----------------
__device__ float g_x  [Bn*Cc*HW];
__device__ float g_sum[Bn*Cc*HW];
__device__ float g_t  [Bn*C8*HW];
__device__ float g_attn1[Bn*C8*C8];
__device__ float g_out3[Bn*C8*HW];
__device__ float g_q2n [Bn*HW*C8];
__device__ float g_norm[Bn*HW];
__device__ float g_pgram[Bn*32*C8*C8];
__device__ uint32_t g_wf[9*128*Cc];   // [tap][ci2][co] fp16 pairs

// ================= weight prep: fp16 pairs, [tap][ci2][co] =================
__global__ void __launch_bounds__(256) wprep_k(const float* __restrict__ w)
{
    int idx = blockIdx.x * 256 + threadIdx.x;   // 9*128*256 = 294912
    int co  = idx & 255;
    int ci2 = (idx >> 8) & 127;
    int tap = idx >> 15;
    float v0 = w[((size_t)co*Cc + 2*ci2    )*9 + tap];
    float v1 = w[((size_t)co*Cc + 2*ci2 + 1)*9 + tap];
    g_wf[idx] = pkhf(v0, v1);
}

// ================= 3x3 conv via fp16 m16n8k16 MMA, all-taps W staging =================
// grid (32 pb, 2 cog, 4 b), block 256 (8 warps). CTA tile: 128 co x 128 px.
#define SXB 264            // u32 stride per ci2 for X strip (4 rows x 66)
#define SWB 136            // u32 stride per ci2 for W tile (128 co, padded)
#define SWT (8*SWB)        // per-tap W block (1088)
#define SXB_ELEMS (8*SXB)  // 2112
#define SW_ALL (9*SWT)     // 9792

__global__ void __launch_bounds__(256, 2) convmma_k(
    const float* __restrict__ x, const float* __restrict__ bias)
{
    extern __shared__ uint32_t smu[];
    uint32_t* sX = smu;
    uint32_t* sW = sX + SXB_ELEMS;

    const int pb = blockIdx.x, cog = blockIdx.y, b = blockIdx.z;
    const int tid  = threadIdx.x;
    const int wid  = tid >> 5, lane = tid & 31;
    const int wm   = wid >> 1, wn = wid & 1;
    const int gid  = lane >> 2, tig = lane & 3;
    const int h0   = pb * 2;

    float4 acc[2][8];
#pragma unroll
    for (int mt = 0; mt < 2; mt++)
#pragma unroll
        for (int nt = 0; nt < 8; nt++) acc[mt][nt] = make_float4(0.f,0.f,0.f,0.f);

    for (int cib = 0; cib < Cc/16; cib++) {
        __syncthreads();
        // ---- stage X strip: 8 ci-pairs x 4 rows x 66 cols, fp16 pairs
        for (int e = tid; e < 8*264; e += 256) {
            int ci2 = e / 264;
            int rem = e - ci2*264;
            int r = rem / 66;
            int c = rem - r*66;
            int gh = h0 - 1 + r, gw = c - 1;
            float v0 = 0.f, v1 = 0.f;
            if (gh >= 0 && gh < Hh && gw >= 0 && gw < Ww) {
                const float* p = x + ((size_t)(b*Cc + cib*16 + 2*ci2))*HW + gh*Ww + gw;
                v0 = __ldg(p);
                v1 = __ldg(p + HW);
            }
            sX[ci2*SXB + rem] = pkhf(v0, v1);
        }
        // ---- stage W: ALL 9 taps for this cib
        {
            const size_t base = (size_t)(cib*8)*256 + cog*128;
#pragma unroll 4
            for (int e = tid; e < 9*1024; e += 256) {
                int tap = e >> 10, rem = e & 1023;
                int ci2 = rem >> 7, col = rem & 127;
                sW[tap*SWT + ci2*SWB + col] =
                    __ldg(g_wf + (size_t)tap*32768 + base + (size_t)ci2*256 + col);
            }
        }
        __syncthreads();

#pragma unroll
        for (int tap = 0; tap < 9; tap++) {
            const int dh = tap/3 - 1, dw = tap%3 - 1;
            const uint32_t* wt = sW + tap*SWT;

            uint32_t a[2][4];
#pragma unroll
            for (int mt = 0; mt < 2; mt++) {
                int cb = wm*32 + mt*16 + gid;
                a[mt][0] = wt[tig*SWB + cb];       a[mt][1] = wt[tig*SWB + cb + 8];
                a[mt][2] = wt[(tig+4)*SWB + cb];   a[mt][3] = wt[(tig+4)*SWB + cb + 8];
            }
            const int boff = tig*SXB + (wn + 1 + dh)*66 + 1 + dw + gid;
#pragma unroll
            for (int nt = 0; nt < 8; nt++) {
                uint32_t b0 = sX[boff + nt*8];
                uint32_t b1 = sX[boff + nt*8 + 4*SXB];
#pragma unroll
                for (int mt = 0; mt < 2; mt++)
                    mma_f16(acc[mt][nt], a[mt][0],a[mt][1],a[mt][2],a[mt][3], b0, b1);
            }
        }
    }

#pragma unroll
    for (int mt = 0; mt < 2; mt++) {
        int co0 = cog*128 + wm*32 + mt*16 + gid;
        float b0 = __ldg(bias + co0);
        float b1 = __ldg(bias + co0 + 8);
#pragma unroll
        for (int nt = 0; nt < 8; nt++) {
            int px = pb*128 + wn*64 + nt*8 + 2*tig;
            float2* d0 = (float2*)(g_x + ((size_t)(b*Cc + co0))*HW + px);
            float2* d1 = (float2*)(g_x + ((size_t)(b*Cc + co0 + 8))*HW + px);
            float4 a4 = acc[mt][nt];
            *d0 = make_float2(a4.x + b0, a4.y + b0);
            *d1 = make_float2(a4.z + b1, a4.w + b1);
        }
    }
}

// ================= fused depthwise =================
template<int K>
__device__ __forceinline__ void dw_scale(
    const float* xs, float* hb, float out[16],
    const float* __restrict__ wh_c, const float* __restrict__ wv_c,
    float bh, float bv, int w, int h0)
{
    constexpr int P = K/2;
    float whr[K];
#pragma unroll
    for (int k = 0; k < K; k++) whr[k] = __ldg(wh_c + k);
#pragma unroll
    for (int i = 0; i < 16; i++) {
        int h = h0 + i; float s = bh;
#pragma unroll
        for (int k = 0; k < K; k++) {
            int ww = w + k - P;
            if (ww >= 0 && ww < Ww) s += whr[k] * xs[h*Ww + ww];
        }
        hb[h*Ww + w] = s;
    }
    __syncthreads();
    float wvr[K];
#pragma unroll
    for (int k = 0; k < K; k++) wvr[k] = __ldg(wv_c + k);
#pragma unroll
    for (int i = 0; i < 16; i++) {
        int h = h0 + i; float s = bv;
#pragma unroll
        for (int k = 0; k < K; k++) {
            int hh = h + k - P;
            if (hh >= 0 && hh < Hh) s += wvr[k] * hb[hh*Ww + w];
        }
        out[i] += s;
    }
    __syncthreads();
}

__global__ void __launch_bounds__(256) dwfused_k(
    const float* __restrict__ w01, const float* __restrict__ b01,
    const float* __restrict__ w02, const float* __restrict__ b02,
    const float* __restrict__ w11, const float* __restrict__ b11,
    const float* __restrict__ w12, const float* __restrict__ b12,
    const float* __restrict__ w21, const float* __restrict__ b21,
    const float* __restrict__ w22, const float* __restrict__ b22)
{
    __shared__ float xs[HW];
    __shared__ float hb[HW];
    const int plane = blockIdx.x;
    const int c = plane & (Cc-1);
    const int tid = threadIdx.x;
    const float* src = g_x + (size_t)plane*HW;

#pragma unroll
    for (int s = 0; s < 4; s++)
        ((float4*)xs)[tid + s*256] = ((const float4*)src)[tid + s*256];
    __syncthreads();

    const int w  = tid & 63;
    const int h0 = (tid >> 6) * 16;

    float out[16];
#pragma unroll
    for (int i = 0; i < 16; i++) out[i] = xs[(h0+i)*Ww + w];

    dw_scale<7> (xs, hb, out, w01 + c*7,  w02 + c*7,  __ldg(b01+c), __ldg(b02+c), w, h0);
    dw_scale<11>(xs, hb, out, w11 + c*11, w12 + c*11, __ldg(b11+c), __ldg(b12+c), w, h0);
    dw_scale<21>(xs, hb, out, w21 + c*21, w22 + c*21, __ldg(b21+c), __ldg(b22+c), w, h0);

    float* dst = g_sum + (size_t)plane*HW;
#pragma unroll
    for (int i = 0; i < 16; i++) dst[(h0+i)*Ww + w] = out[i];
}

// ================= fused 1x1 proj + transpose + l2norm =================
__global__ void __launch_bounds__(256, 2) projnorm_k(
    const float* __restrict__ w_proj, const float* __restrict__ b_proj)
{
    __shared__ float ws[Cc*C8];
    __shared__ float sred[4*64*33];
    __shared__ float st[64*33];

    const int tid = threadIdx.x;
    for (int idx = tid; idx < Cc*C8; idx += 256) {
        int o = idx >> 8, c = idx & 255;
        ws[c*C8 + o] = w_proj[o*Cc + c];
    }
    __syncthreads();

    const int px = tid & 63, slice = tid >> 6;
    const int g0 = blockIdx.x * 64;
    const int gp = g0 + px;
    const int b = gp >> 12, k = gp & (HW-1);

    u64 acc[16];
    const u64 zero = pack2(0.f, 0.f);
#pragma unroll
    for (int d = 0; d < 16; d++) acc[d] = zero;

    const float* src = g_sum + (size_t)b*Cc*HW + (size_t)slice*64*HW + k;
    const float* wsl = ws + slice*64*C8;
#pragma unroll 4
    for (int c = 0; c < 64; c++) {
        float v = __ldg(src + (size_t)c*HW);
        u64 vp = pack2(v, v);
        const u64* wrow = (const u64*)(wsl + c*C8);
#pragma unroll
        for (int d = 0; d < 16; d++) acc[d] = ffma2(vp, wrow[d], acc[d]);
    }
    float* srow = sred + (slice*64 + px)*33;
#pragma unroll
    for (int d = 0; d < 16; d++) {
        float2 v = unpack2(acc[d]);
        srow[2*d] = v.x; srow[2*d+1] = v.y;
    }
    __syncthreads();

    for (int e = tid; e < 64*C8; e += 256) {
        int p = e >> 5, o = e & 31;
        float v = __ldg(b_proj + o)
                + sred[(0*64+p)*33 + o] + sred[(1*64+p)*33 + o]
                + sred[(2*64+p)*33 + o] + sred[(3*64+p)*33 + o];
        st[p*33 + o] = v;
    }
    __syncthreads();

    if (tid < 64) {
        int p = tid;
        int gpp = g0 + p;
        int bb = gpp >> 12, kk = gpp & (HW-1);
        float v[C8]; float ss = 0.f;
#pragma unroll
        for (int c = 0; c < C8; c++) { v[c] = st[p*33 + c]; ss += v[c]*v[c]; }
        float n = sqrtf(ss);
        float inv = 1.f / fmaxf(n, 1e-12f);
        g_norm[gpp] = n;
        float4* qp = (float4*)(g_q2n + (size_t)gpp*C8);
#pragma unroll
        for (int d = 0; d < 8; d++)
            qp[d] = make_float4(v[d*4+0]*inv, v[d*4+1]*inv, v[d*4+2]*inv, v[d*4+3]*inv);
        float* tb = g_t + (size_t)bb*C8*HW + kk;
#pragma unroll
        for (int c = 0; c < C8; c++) tb[(size_t)c*HW] = v[c];
    }
}

// ================= gram partials =================
__global__ void __launch_bounds__(256) gram_k()
{
    __shared__ float st[32*129];
    const int slab = blockIdx.x, b = blockIdx.y;
    const int tid = threadIdx.x;
    const float* tb = g_t + (size_t)b*C8*HW + slab*128;
    for (int idx = tid; idx < 32*128; idx += 256) {
        int c = idx >> 7, x = idx & 127;
        st[c*129 + x] = tb[(size_t)c*HW + x];
    }
    __syncthreads();

    const int i  = tid >> 3;
    const int j0 = (tid & 7) * 4;
    const float* ri = st + i*129;
    const float* r0 = st + (j0+0)*129;
    const float* r1 = st + (j0+1)*129;
    const float* r2 = st + (j0+2)*129;
    const float* r3 = st + (j0+3)*129;
    float s0=0.f, s1=0.f, s2=0.f, s3=0.f;
#pragma unroll 8
    for (int x = 0; x < 128; x++) {
        float a = ri[x];
        s0 += a*r0[x]; s1 += a*r1[x]; s2 += a*r2[x]; s3 += a*r3[x];
    }
    float* dst = g_pgram + (((size_t)b*32 + slab) << 10) + i*32 + j0;
    dst[0]=s0; dst[1]=s1; dst[2]=s2; dst[3]=s3;
}

// ================= reduce gram + softmax =================
__global__ void __launch_bounds__(1024) chsoft_k()
{
    const int b = blockIdx.x;
    const int tid = threadIdx.x;
    __shared__ float G[1024];
    __shared__ float ninv[32];

    float g = 0.f;
#pragma unroll
    for (int s = 0; s < 32; s++)
        g += g_pgram[(((size_t)b*32 + s) << 10) + tid];
    G[tid] = g;
    if ((tid >> 5) == (tid & 31)) ninv[tid & 31] = 1.f / fmaxf(sqrtf(g), 1e-12f);
    __syncthreads();

    if (tid < 32) {
        int r = tid;
        float ir = ninv[r];
        float row[32]; float s = 0.f;
#pragma unroll
        for (int jj = 0; jj < 32; jj++) {
            float a = G[r*32 + jj] * ir * ninv[jj];
            float p = expf(a - 1.f);
            row[jj] = p; s += p;
        }
        float is = 1.f / s;
        float* dst = g_attn1 + b*C8*C8 + r*32;
#pragma unroll
        for (int jj = 0; jj < 32; jj++) dst[jj] = row[jj] * is;
    }
}

// ================= flash spatial attention, fp16 tensor cores =================
// grid (32 q-tiles of 128, 4 b), block 256 (8 warps x 16 q-rows)
#define SPN 20    // u32 stride per key, [key][dimpair]
#define SPD 68    // u32 stride per dim, [dim][keypair]
#define SPP 68    // u32 stride per P row

__global__ void __launch_bounds__(256, 2) spflash_k()
{
    extern __shared__ uint32_t su[];
    uint32_t* sKn = su;                      // 128*20
    uint32_t* sKd = sKn + 128*SPN;           // 32*68
    uint32_t* sP  = sKd + 32*SPD;            // 8*16*68
    float*    sN  = (float*)(sP + 8*16*SPP); // 128

    const int tid = threadIdx.x;
    const int w = tid >> 5, lane = tid & 31;
    const int gid = lane >> 2, tig = lane & 3;
    const int b = blockIdx.y;
    const int qb = blockIdx.x*128 + w*16;

    // Q A-fragments (fp16), 2 k-chunks of 16 dims
    uint32_t qf[2][4];
    {
        const float* Q = g_q2n + ((size_t)b*HW + qb)*C8;
#pragma unroll
        for (int ks = 0; ks < 2; ks++)
#pragma unroll
        for (int i = 0; i < 4; i++) {
            int row = gid + (i & 1)*8;
            int dim = ks*16 + 2*tig + ((i & 2) ? 8 : 0);
            float f0 = Q[(size_t)row*32 + dim];
            float f1 = Q[(size_t)row*32 + dim + 1];
            qf[ks][i] = pkhf(f0, f1);
        }
    }

    float4 acc_o[4];
#pragma unroll
    for (int n = 0; n < 4; n++) acc_o[n] = make_float4(0.f,0.f,0.f,0.f);
    float l0 = 0.f, l1 = 0.f;
    uint32_t* sPw = sP + w*16*SPP;

    for (int kt = 0; kt < 32; kt++) {
        __syncthreads();
        // ---- stage K tile: fp16 in [key][dimpair] and [dim][keypair]
        {
            int key = tid & 127, dh = tid >> 7;
            const float4* src = (const float4*)(g_q2n + ((size_t)b*HW + kt*128 + key)*C8 + dh*16);
            __half* kd = (__half*)sKd;
#pragma unroll
            for (int q4 = 0; q4 < 4; q4++) {
                float4 v = src[q4];
                int dim = dh*16 + q4*4;
                sKn[key*SPN + (dim>>1)    ] = pkhf(v.x, v.y);
                sKn[key*SPN + (dim>>1) + 1] = pkhf(v.z, v.w);
                kd[(dim+0)*(2*SPD) + key] = __float2half_rn(v.x);
                kd[(dim+1)*(2*SPD) + key] = __float2half_rn(v.y);
                kd[(dim+2)*(2*SPD) + key] = __float2half_rn(v.z);
                kd[(dim+3)*(2*SPD) + key] = __float2half_rn(v.w);
            }
            if (tid < 128) sN[tid] = g_norm[(size_t)b*HW + kt*128 + tid];
        }
        __syncthreads();

        // ---- S = Q @ K^T (fp16), exp, fold norm, pack P (fp16)
#pragma unroll 4
        for (int nt = 0; nt < 16; nt++) {
            float4 s = make_float4(0.f,0.f,0.f,0.f);
            const int key = nt*8 + gid;
#pragma unroll
            for (int ks = 0; ks < 2; ks++) {
                uint32_t b0 = sKn[key*SPN + ks*8 + tig];
                uint32_t b1 = sKn[key*SPN + ks*8 + tig + 4];
                mma_f16(s, qf[ks][0],qf[ks][1],qf[ks][2],qf[ks][3], b0, b1);
            }
            float n0 = sN[nt*8 + 2*tig], n1 = sN[nt*8 + 2*tig + 1];
            float e0 = __expf(s.x - 1.f), e1 = __expf(s.y - 1.f);
            float e2 = __expf(s.z - 1.f), e3 = __expf(s.w - 1.f);
            l0 += e0 + e1;
            l1 += e2 + e3;
            sPw[(size_t)gid*SPP     + nt*4 + tig] = pkhf(e0*n0, e1*n1);
            sPw[(size_t)(gid+8)*SPP + nt*4 + tig] = pkhf(e2*n0, e3*n1);
        }
        __syncwarp();

        // ---- O += P @ V  (V = diag(n)K folded into P)
#pragma unroll
        for (int ks2 = 0; ks2 < 8; ks2++) {
            uint32_t a0 = sPw[(size_t)gid*SPP     + ks2*8 + tig];
            uint32_t a1 = sPw[(size_t)(gid+8)*SPP + ks2*8 + tig];
            uint32_t a2 = sPw[(size_t)gid*SPP     + ks2*8 + tig + 4];
            uint32_t a3 = sPw[(size_t)(gid+8)*SPP + ks2*8 + tig + 4];
#pragma unroll
            for (int nt2 = 0; nt2 < 4; nt2++) {
                int dimc = nt2*8 + gid;
                uint32_t v0 = sKd[dimc*SPD + ks2*8 + tig];
                uint32_t v1 = sKd[dimc*SPD + ks2*8 + tig + 4];
                mma_f16(acc_o[nt2], a0,a1,a2,a3, v0, v1);
            }
        }
    }

    l0 += __shfl_xor_sync(0xffffffffu, l0, 1);
    l0 += __shfl_xor_sync(0xffffffffu, l0, 2);
    l1 += __shfl_xor_sync(0xffffffffu, l1, 1);
    l1 += __shfl_xor_sync(0xffffffffu, l1, 2);
    float i0 = 1.f / l0, i1 = 1.f / l1;

    int q0 = qb + gid, q1 = qb + gid + 8;
#pragma unroll
    for (int nt2 = 0; nt2 < 4; nt2++) {
        int d0 = nt2*8 + 2*tig, d1 = d0 + 1;
        g_out3[((size_t)b*C8 + d0)*HW + q0] = acc_o[nt2].x * i0;
        g_out3[((size_t)b*C8 + d1)*HW + q0] = acc_o[nt2].y * i0;
        g_out3[((size_t)b*C8 + d0)*HW + q1] = acc_o[nt2].z * i1;
        g_out3[((size_t)b*C8 + d1)*HW + q1] = acc_o[nt2].w * i1;
    }
}

// ================= final: fused chout + 1x1s =================
__global__ void __launch_bounds__(256, 2) final_k(
    const float* __restrict__ w3, const float* __restrict__ b3,
    const float* __restrict__ w4, const float* __restrict__ b4,
    float* __restrict__ out)
{
    __shared__ float sw3[64*32];
    __shared__ float sw4[Cc*C8];
    __shared__ float sb4[Cc];
    __shared__ float sA[C8*C8];
    __shared__ float so3[64*33];

    const int tid = threadIdx.x;
    const int px = tid & 63, coh = tid >> 6;
    const int g0 = blockIdx.x * 64;
    const int gp = g0 + px;
    const int b = gp >> 12, k = gp & (HW-1);

    for (int idx = tid; idx < 64*32; idx += 256) {
        int j = idx >> 5, o = idx & 31;
        sw3[j*32 + o] = w3[o*64 + j];
    }
    for (int idx = tid; idx < Cc*C8; idx += 256) sw4[idx] = w4[idx];
    if (tid < Cc) sb4[tid] = b4[tid];
    for (int idx = tid; idx < C8*C8; idx += 256) sA[idx] = g_attn1[b*C8*C8 + idx];

    if (coh == 0) {
        const float* o3 = g_out3 + (size_t)b*C8*HW + k;
#pragma unroll
        for (int c = 0; c < C8; c++) so3[px*33 + c] = __ldg(o3 + (size_t)c*HW);
    }
    __syncthreads();

    float tv[C8];
    {
        const float* tb = g_t + (size_t)b*C8*HW + k;
#pragma unroll
        for (int c = 0; c < C8; c++) tv[c] = tb[(size_t)c*HW];
    }
    u64 tvp[16];
#pragma unroll
    for (int d = 0; d < 16; d++) tvp[d] = pack2(tv[2*d], tv[2*d+1]);

    float out2[C8];
#pragma unroll
    for (int i = 0; i < C8; i++) {
        const u64* ar = (const u64*)(sA + i*32);
        u64 s2 = pack2(0.f, 0.f);
#pragma unroll
        for (int d = 0; d < 16; d++) s2 = ffma2(ar[d], tvp[d], s2);
        float2 f = unpack2(s2);
        out2[i] = f.x + f.y;
    }

    u64 o5[16];
#pragma unroll
    for (int d = 0; d < 16; d++)
        o5[d] = pack2(__ldg(b3 + 2*d) + tv[2*d], __ldg(b3 + 2*d+1) + tv[2*d+1]);

#pragma unroll 4
    for (int j = 0; j < 32; j++) {
        u64 vp = pack2(out2[j], out2[j]);
        const u64* wr = (const u64*)(sw3 + j*32);
#pragma unroll
        for (int d = 0; d < 16; d++) o5[d] = ffma2(vp, wr[d], o5[d]);
    }
#pragma unroll 4
    for (int j = 0; j < 32; j++) {
        float v = so3[px*33 + j];
        u64 vp = pack2(v, v);
        const u64* wr = (const u64*)(sw3 + (32+j)*32);
#pragma unroll
        for (int d = 0; d < 16; d++) o5[d] = ffma2(vp, wr[d], o5[d]);
    }

    const int co0 = coh * 64;
    float* dst = out + (size_t)b*Cc*HW + (size_t)co0*HW + k;
#pragma unroll 2
    for (int cc = 0; cc < 64; cc += 2) {
        const u64* w0 = (const u64*)(sw4 + (co0+cc)*C8);
        const u64* w1 = (const u64*)(sw4 + (co0+cc+1)*C8);
        u64 s0 = pack2(0.f, 0.f), s1 = pack2(0.f, 0.f);
#pragma unroll
        for (int d = 0; d < 16; d++) {
            s0 = ffma2(w0[d], o5[d], s0);
            s1 = ffma2(w1[d], o5[d], s1);
        }
        float2 f0 = unpack2(s0), f1 = unpack2(s1);
        dst[(size_t)cc*HW]     = f0.x + f0.y + sb4[co0+cc];
        dst[(size_t)(cc+1)*HW] = f1.x + f1.y + sb4[co0+cc+1];
    }
}

// ================= launch =================
extern "C" void kernel_launch(void* const* d_in, const int* in_sizes, int n_in,
                              void* d_out, int out_size)
{
    const float* x      = (const float*)d_in[0];
    const float* w_conv = (const float*)d_in[1];
    const float* b_conv = (const float*)d_in[2];
    const float* w01 = (const float*)d_in[3];
    const float* b01 = (const float*)d_in[4];
    const float* w02 = (const float*)d_in[5];
    const float* b02 = (const float*)d_in[6];
    const float* w11 = (const float*)d_in[7];
    const float* b11 = (const float*)d_in[8];
    const float* w12 = (const float*)d_in[9];
    const float* b12 = (const float*)d_in[10];
    const float* w21 = (const float*)d_in[11];
    const float* b21 = (const float*)d_in[12];
    const float* w22 = (const float*)d_in[13];
    const float* b22 = (const float*)d_in[14];
    const float* w_proj = (const float*)d_in[15];
    const float* b_proj = (const float*)d_in[16];
    const float* w3 = (const float*)d_in[17];
    const float* b3 = (const float*)d_in[18];
    const float* w4 = (const float*)d_in[19];
    const float* b4 = (const float*)d_in[20];
    float* out = (float*)d_out;

    const int convSmem = (SXB_ELEMS + SW_ALL) * (int)sizeof(uint32_t);
    const int spSmem   = (128*SPN + 32*SPD + 8*16*SPP) * (int)sizeof(uint32_t)
                       + 128 * (int)sizeof(float);
    static bool attrSet = false;
    if (!attrSet) {
        cudaFuncSetAttribute(convmma_k, cudaFuncAttributeMaxDynamicSharedMemorySize, convSmem);
        cudaFuncSetAttribute(spflash_k, cudaFuncAttributeMaxDynamicSharedMemorySize, spSmem);
        attrSet = true;
    }

    wprep_k   <<<9*128*Cc/256, 256>>>(w_conv);
    convmma_k <<<dim3(32, 2, 4), 256, convSmem>>>(x, b_conv);
    dwfused_k <<<Bn*Cc, 256>>>(w01, b01, w02, b02, w11, b11, w12, b12, w21, b21, w22, b22);
    projnorm_k<<<256, 256>>>(w_proj, b_proj);
    gram_k    <<<dim3(32, 4), 256>>>();
    chsoft_k  <<<4, 1024>>>();
    spflash_k <<<dim3(32, 4), 256, spSmem>>>();
    final_k   <<<256, 256>>>(w3, b3, w4, b4, out);
}

// round 12
// speedup vs baseline: 1.8579x; 1.1422x over previous
#include <cuda_runtime.h>
#include <cuda_fp16.h>
#include <math.h>
#include <stdint.h>

#define Bn 4
#define Cc 256
#define C8 32
#define Hh 64
#define Ww 64
#define HW 4096

typedef unsigned long long u64;

__device__ __forceinline__ u64 ffma2(u64 a, u64 b, u64 c){
    u64 d; asm("fma.rn.f32x2 %0, %1, %2, %3;" : "=l"(d) : "l"(a), "l"(b), "l"(c)); return d;
}
__device__ __forceinline__ u64 pack2(float lo, float hi){
    u64 d; asm("mov.b64 %0, {%1, %2};" : "=l"(d) : "f"(lo), "f"(hi)); return d;
}
__device__ __forceinline__ float2 unpack2(u64 v){
    float lo, hi; asm("mov.b64 {%0, %1}, %2;" : "=f"(lo), "=f"(hi) : "l"(v));
    return make_float2(lo, hi);
}
__device__ __forceinline__ void mma_f16(float4& d, const uint32_t a0, const uint32_t a1,
                                        const uint32_t a2, const uint32_t a3,
                                        const uint32_t b0, const uint32_t b1){
    asm volatile(
      "mma.sync.aligned.m16n8k16.row.col.f32.f16.f16.f32 "
      "{%0,%1,%2,%3}, {%4,%5,%6,%7}, {%8,%9}, {%0,%1,%2,%3};"
      : "+f"(d.x), "+f"(d.y), "+f"(d.z), "+f"(d.w)
      : "r"(a0), "r"(a1), "r"(a2), "r"(a3), "r"(b0), "r"(b1));
}
__device__ __forceinline__ uint32_t pkhf(float a, float b){
    __half2 t = __floats2half2_rn(a, b);
    return *reinterpret_cast<uint32_t*>(&t);
}

// ---------------- scratch ----------------
__device__ float g_x  [Bn*Cc*HW];
__device__ float g_sum[Bn*Cc*HW];
__device__ float g_t  [Bn*C8*HW];
__device__ float g_attn1[Bn*C8*C8];
__device__ float g_out3[Bn*C8*HW];
__device__ uint32_t g_qh[Bn*HW*16];   // l2-normalized rows, fp16 pairs [b][hw][16]
__device__ float g_norm[Bn*HW];
__device__ float g_pgram[Bn*64*C8*C8];
__device__ uint32_t g_wf[9*128*Cc];   // [tap][ci2][co] fp16 pairs

// ================= weight prep: fp16 pairs, [tap][ci2][co] =================
__global__ void __launch_bounds__(256) wprep_k(const float* __restrict__ w)
{
    int idx = blockIdx.x * 256 + threadIdx.x;   // 294912
    int co  = idx & 255;
    int ci2 = (idx >> 8) & 127;
    int tap = idx >> 15;
    float v0 = w[((size_t)co*Cc + 2*ci2    )*9 + tap];
    float v1 = w[((size_t)co*Cc + 2*ci2 + 1)*9 + tap];
    g_wf[idx] = pkhf(v0, v1);
}

// ================= 3x3 conv via fp16 m16n8k16 MMA =================
#define SXB 264
#define SWB 136
#define SWT (8*SWB)
#define SXB_ELEMS (8*SXB)
#define SW_ALL (9*SWT)

__global__ void __launch_bounds__(256, 2) convmma_k(
    const float* __restrict__ x, const float* __restrict__ bias)
{
    extern __shared__ uint32_t smu[];
    uint32_t* sX = smu;
    uint32_t* sW = sX + SXB_ELEMS;

    const int pb = blockIdx.x, cog = blockIdx.y, b = blockIdx.z;
    const int tid  = threadIdx.x;
    const int wid  = tid >> 5, lane = tid & 31;
    const int wm   = wid >> 1, wn = wid & 1;
    const int gid  = lane >> 2, tig = lane & 3;
    const int h0   = pb * 2;

    float4 acc[2][8];
#pragma unroll
    for (int mt = 0; mt < 2; mt++)
#pragma unroll
        for (int nt = 0; nt < 8; nt++) acc[mt][nt] = make_float4(0.f,0.f,0.f,0.f);

    for (int cib = 0; cib < Cc/16; cib++) {
        __syncthreads();
        // ---- stage X strip: fp16 pairs
        for (int e = tid; e < 8*264; e += 256) {
            int ci2 = e / 264;
            int rem = e - ci2*264;
            int r = rem / 66;
            int c = rem - r*66;
            int gh = h0 - 1 + r, gw = c - 1;
            float v0 = 0.f, v1 = 0.f;
            if (gh >= 0 && gh < Hh && gw >= 0 && gw < Ww) {
                const float* p = x + ((size_t)(b*Cc + cib*16 + 2*ci2))*HW + gh*Ww + gw;
                v0 = __ldg(p);
                v1 = __ldg(p + HW);
            }
            sX[ci2*SXB + rem] = pkhf(v0, v1);
        }
        // ---- stage W (all 9 taps) via uint4: 9 iterations of LDG.128+STS.128
        {
            const size_t base = (size_t)(cib*8)*256 + cog*128;
#pragma unroll
            for (int i = 0; i < 9; i++) {
                int e = tid + i*256;          // 0..2303
                int tap = e >> 8;
                int rem = e & 255;
                int ci2 = rem >> 5, c4 = rem & 31;
                uint4 v = __ldg((const uint4*)(g_wf + (size_t)tap*32768 + base + (size_t)ci2*256) + c4);
                *(uint4*)(sW + tap*SWT + ci2*SWB + c4*4) = v;
            }
        }
        __syncthreads();

#pragma unroll
        for (int tap = 0; tap < 9; tap++) {
            const int dh = tap/3 - 1, dw = tap%3 - 1;
            const uint32_t* wt = sW + tap*SWT;

            uint32_t a[2][4];
#pragma unroll
            for (int mt = 0; mt < 2; mt++) {
                int cb = wm*32 + mt*16 + gid;
                a[mt][0] = wt[tig*SWB + cb];       a[mt][1] = wt[tig*SWB + cb + 8];
                a[mt][2] = wt[(tig+4)*SWB + cb];   a[mt][3] = wt[(tig+4)*SWB + cb + 8];
            }
            const int boff = tig*SXB + (wn + 1 + dh)*66 + 1 + dw + gid;
#pragma unroll
            for (int nt = 0; nt < 8; nt++) {
                uint32_t b0 = sX[boff + nt*8];
                uint32_t b1 = sX[boff + nt*8 + 4*SXB];
#pragma unroll
                for (int mt = 0; mt < 2; mt++)
                    mma_f16(acc[mt][nt], a[mt][0],a[mt][1],a[mt][2],a[mt][3], b0, b1);
            }
        }
    }

#pragma unroll
    for (int mt = 0; mt < 2; mt++) {
        int co0 = cog*128 + wm*32 + mt*16 + gid;
        float b0 = __ldg(bias + co0);
        float b1 = __ldg(bias + co0 + 8);
#pragma unroll
        for (int nt = 0; nt < 8; nt++) {
            int px = pb*128 + wn*64 + nt*8 + 2*tig;
            float2* d0 = (float2*)(g_x + ((size_t)(b*Cc + co0))*HW + px);
            float2* d1 = (float2*)(g_x + ((size_t)(b*Cc + co0 + 8))*HW + px);
            float4 a4 = acc[mt][nt];
            *d0 = make_float2(a4.x + b0, a4.y + b0);
            *d1 = make_float2(a4.z + b1, a4.w + b1);
        }
    }
}

// ================= fused depthwise, zero-padded halos (no bounds checks) =================
#define XSP 88   // xs row stride: 12 + 64 + 12
template<int K>
__device__ __forceinline__ void dw_scale(
    const float* xs, float* hb, float out[16],
    const float* __restrict__ wh_c, const float* __restrict__ wv_c,
    float bh, float bv, int w, int h0)
{
    constexpr int P = K/2;
    float whr[K];
#pragma unroll
    for (int k = 0; k < K; k++) whr[k] = __ldg(wh_c + k);
#pragma unroll
    for (int i = 0; i < 16; i++) {
        int h = h0 + i; float s = bh;
        const float* row = xs + h*XSP + 12 + w - P;
#pragma unroll
        for (int k = 0; k < K; k++) s += whr[k] * row[k];
        hb[(12 + h)*64 + w] = s;
    }
    __syncthreads();
    float wvr[K];
#pragma unroll
    for (int k = 0; k < K; k++) wvr[k] = __ldg(wv_c + k);
#pragma unroll
    for (int i = 0; i < 16; i++) {
        int h = h0 + i; float s = bv;
        const float* col = hb + (12 + h - P)*64 + w;
#pragma unroll
        for (int k = 0; k < K; k++) s += wvr[k] * col[k*64];
        out[i] += s;
    }
    __syncthreads();
}

__global__ void __launch_bounds__(256) dwfused_k(
    const float* __restrict__ w01, const float* __restrict__ b01,
    const float* __restrict__ w02, const float* __restrict__ b02,
    const float* __restrict__ w11, const float* __restrict__ b11,
    const float* __restrict__ w12, const float* __restrict__ b12,
    const float* __restrict__ w21, const float* __restrict__ b21,
    const float* __restrict__ w22, const float* __restrict__ b22)
{
    __shared__ float sbuf[64*XSP + XSP*64];   // xs [64][88] + hb [88][64]
    float* xs = sbuf;
    float* hb = sbuf + 64*XSP;

    const int plane = blockIdx.x;
    const int c = plane & (Cc-1);
    const int tid = threadIdx.x;
    const float* src = g_x + (size_t)plane*HW;

    // zero everything (halo stays zero thereafter)
#pragma unroll
    for (int s = 0; s < 11; s++)
        ((float4*)sbuf)[tid + s*256] = make_float4(0.f,0.f,0.f,0.f);
    __syncthreads();

    // stage interior
#pragma unroll
    for (int s = 0; s < 4; s++) {
        int idx = tid + s*256;                // float4 index over 4096 floats
        float4 v = ((const float4*)src)[idx];
        int h = idx >> 4, w4 = idx & 15;
        *(float4*)(xs + h*XSP + 12 + w4*4) = v;
    }
    __syncthreads();

    const int w  = tid & 63;
    const int h0 = (tid >> 6) * 16;

    float out[16];
#pragma unroll
    for (int i = 0; i < 16; i++) out[i] = xs[(h0+i)*XSP + 12 + w];

    dw_scale<7> (xs, hb, out, w01 + c*7,  w02 + c*7,  __ldg(b01+c), __ldg(b02+c), w, h0);
    dw_scale<11>(xs, hb, out, w11 + c*11, w12 + c*11, __ldg(b11+c), __ldg(b12+c), w, h0);
    dw_scale<21>(xs, hb, out, w21 + c*21, w22 + c*21, __ldg(b21+c), __ldg(b22+c), w, h0);

    float* dst = g_sum + (size_t)plane*HW;
#pragma unroll
    for (int i = 0; i < 16; i++) dst[(h0+i)*Ww + w] = out[i];
}

// ================= fused 1x1 proj + l2norm + gram partials =================
// grid 256, block 256 = 64 px x 4 channel-slices of 64
__global__ void __launch_bounds__(256, 2) projnorm_k(
    const float* __restrict__ w_proj, const float* __restrict__ b_proj)
{
    __shared__ float ws[Cc*C8];
    __shared__ float sred[4*64*33];
    __shared__ float st[64*33];

    const int tid = threadIdx.x;
    for (int idx = tid; idx < Cc*C8; idx += 256) {
        int o = idx >> 8, c = idx & 255;
        ws[c*C8 + o] = w_proj[o*Cc + c];
    }
    __syncthreads();

    const int px = tid & 63, slice = tid >> 6;
    const int g0 = blockIdx.x * 64;
    const int gp = g0 + px;
    const int b = gp >> 12, k = gp & (HW-1);

    u64 acc[16];
    const u64 zero = pack2(0.f, 0.f);
#pragma unroll
    for (int d = 0; d < 16; d++) acc[d] = zero;

    const float* src = g_sum + (size_t)b*Cc*HW + (size_t)slice*64*HW + k;
    const float* wsl = ws + slice*64*C8;
#pragma unroll 4
    for (int c = 0; c < 64; c++) {
        float v = __ldg(src + (size_t)c*HW);
        u64 vp = pack2(v, v);
        const u64* wrow = (const u64*)(wsl + c*C8);
#pragma unroll
        for (int d = 0; d < 16; d++) acc[d] = ffma2(vp, wrow[d], acc[d]);
    }
    float* srow = sred + (slice*64 + px)*33;
#pragma unroll
    for (int d = 0; d < 16; d++) {
        float2 v = unpack2(acc[d]);
        srow[2*d] = v.x; srow[2*d+1] = v.y;
    }
    __syncthreads();

    for (int e = tid; e < 64*C8; e += 256) {
        int p = e >> 5, o = e & 31;
        float v = __ldg(b_proj + o)
                + sred[(0*64+p)*33 + o] + sred[(1*64+p)*33 + o]
                + sred[(2*64+p)*33 + o] + sred[(3*64+p)*33 + o];
        st[p*33 + o] = v;
    }
    __syncthreads();

    // t, norms, fp16 q2n
    if (tid < 64) {
        int p = tid;
        int gpp = g0 + p;
        int bb = gpp >> 12, kk = gpp & (HW-1);
        float v[C8]; float ss = 0.f;
#pragma unroll
        for (int c = 0; c < C8; c++) { v[c] = st[p*33 + c]; ss += v[c]*v[c]; }
        float n = sqrtf(ss);
        float inv = 1.f / fmaxf(n, 1e-12f);
        g_norm[gpp] = n;
        uint32_t* qh = g_qh + (size_t)gpp*16;
#pragma unroll
        for (int d = 0; d < 8; d++) {
            qh[2*d]   = pkhf(v[4*d+0]*inv, v[4*d+1]*inv);
            qh[2*d+1] = pkhf(v[4*d+2]*inv, v[4*d+3]*inv);
        }
        float* tb = g_t + (size_t)bb*C8*HW + kk;
#pragma unroll
        for (int c = 0; c < C8; c++) tb[(size_t)c*HW] = v[c];
    }

    // gram partial over this block's 64 pixels
    {
        const int i  = tid >> 3;
        const int j0 = (tid & 7) * 4;
        float s0=0.f, s1=0.f, s2=0.f, s3=0.f;
#pragma unroll 8
        for (int xx = 0; xx < 64; xx++) {
            const float* r = st + xx*33;
            float a = r[i];
            s0 += a*r[j0]; s1 += a*r[j0+1]; s2 += a*r[j0+2]; s3 += a*r[j0+3];
        }
        float* dst = g_pgram + ((size_t)blockIdx.x << 10) + i*32 + j0;
        dst[0]=s0; dst[1]=s1; dst[2]=s2; dst[3]=s3;
    }
}

// ================= reduce gram (64 slabs) + softmax =================
__global__ void __launch_bounds__(1024) chsoft_k(float* __restrict__ dummy)
{
    const int b = blockIdx.x;
    const int tid = threadIdx.x;
    __shared__ float G[1024];
    __shared__ float ninv[32];

    float g = 0.f;
#pragma unroll 8
    for (int s = 0; s < 64; s++)
        g += g_pgram[(((size_t)b*64 + s) << 10) + tid];
    G[tid] = g;
    if ((tid >> 5) == (tid & 31)) ninv[tid & 31] = 1.f / fmaxf(sqrtf(g), 1e-12f);
    __syncthreads();

    if (tid < 32) {
        int r = tid;
        float ir = ninv[r];
        float row[32]; float s = 0.f;
#pragma unroll
        for (int jj = 0; jj < 32; jj++) {
            float a = G[r*32 + jj] * ir * ninv[jj];
            float p = expf(a - 1.f);
            row[jj] = p; s += p;
        }
        float is = 1.f / s;
        float* dst = g_attn1 + b*C8*C8 + r*32;
#pragma unroll
        for (int jj = 0; jj < 32; jj++) dst[jj] = row[jj] * is;
    }
}

// ================= flash spatial attention, fp16 tensor cores =================
#define SPN 20    // u32 stride per key, [key][dimpair]
#define SPD 68    // u32 stride per dim, [dim][keypair]
#define SPP 68    // u32 stride per P row

__global__ void __launch_bounds__(256, 2) spflash_k()
{
    extern __shared__ uint32_t su[];
    uint32_t* sKn = su;                      // 128*20
    uint32_t* sKd = sKn + 128*SPN;           // 32*68
    uint32_t* sP  = sKd + 32*SPD;            // 8*16*68
    float*    sN  = (float*)(sP + 8*16*SPP); // 128

    const int tid = threadIdx.x;
    const int w = tid >> 5, lane = tid & 31;
    const int gid = lane >> 2, tig = lane & 3;
    const int b = blockIdx.y;
    const int qb = blockIdx.x*128 + w*16;

    // Q A-fragments: direct u32 loads from g_qh
    uint32_t qf[2][4];
    {
        const uint32_t* Q = g_qh + ((size_t)b*HW + qb)*16;
#pragma unroll
        for (int ks = 0; ks < 2; ks++)
#pragma unroll
        for (int i = 0; i < 4; i++) {
            int row = gid + (i & 1)*8;
            int du = ks*8 + tig + ((i & 2) ? 4 : 0);
            qf[ks][i] = __ldg(Q + row*16 + du);
        }
    }

    float4 acc_o[4];
#pragma unroll
    for (int n = 0; n < 4; n++) acc_o[n] = make_float4(0.f,0.f,0.f,0.f);
    float l0 = 0.f, l1 = 0.f;
    uint32_t* sPw = sP + w*16*SPP;

    for (int kt = 0; kt < 32; kt++) {
        __syncthreads();
        // ---- stage K tile from g_qh: kn = pure copy; kd = byte_perm transpose
        {
            const uint4* src = (const uint4*)(g_qh + ((size_t)b*HW + kt*128)*16);
            // kn: [key][16 u32], 2 threads per key
            int key = tid & 127, hf = tid >> 7;
            uint4 v0 = __ldg(src + key*4 + hf*2);
            uint4 v1 = __ldg(src + key*4 + hf*2 + 1);
            *(uint4*)(sKn + key*SPN + hf*8)     = v0;
            *(uint4*)(sKn + key*SPN + hf*8 + 4) = v1;
            // kd: [dim][key-pair], thread = (k2, dim-group)
            int k2 = tid & 63, dg = tid >> 6;
            uint4 ua = __ldg(src + (2*k2)*4 + dg);
            uint4 ub = __ldg(src + (2*k2+1)*4 + dg);
            uint32_t uaa[4] = {ua.x, ua.y, ua.z, ua.w};
            uint32_t ubb[4] = {ub.x, ub.y, ub.z, ub.w};
#pragma unroll
            for (int j = 0; j < 4; j++) {
                sKd[(dg*8 + 2*j  )*SPD + k2] = __byte_perm(uaa[j], ubb[j], 0x5410);
                sKd[(dg*8 + 2*j+1)*SPD + k2] = __byte_perm(uaa[j], ubb[j], 0x7632);
            }
            if (tid < 128) sN[tid] = g_norm[(size_t)b*HW + kt*128 + tid];
        }
        __syncthreads();

        // ---- S = Q @ K^T (fp16), exp, fold norm, pack P (fp16)
#pragma unroll 4
        for (int nt = 0; nt < 16; nt++) {
            float4 s = make_float4(0.f,0.f,0.f,0.f);
            const int key = nt*8 + gid;
#pragma unroll
            for (int ks = 0; ks < 2; ks++) {
                uint32_t b0 = sKn[key*SPN + ks*8 + tig];
                uint32_t b1 = sKn[key*SPN + ks*8 + tig + 4];
                mma_f16(s, qf[ks][0],qf[ks][1],qf[ks][2],qf[ks][3], b0, b1);
            }
            float n0 = sN[nt*8 + 2*tig], n1 = sN[nt*8 + 2*tig + 1];
            float e0 = __expf(s.x - 1.f), e1 = __expf(s.y - 1.f);
            float e2 = __expf(s.z - 1.f), e3 = __expf(s.w - 1.f);
            l0 += e0 + e1;
            l1 += e2 + e3;
            sPw[(size_t)gid*SPP     + nt*4 + tig] = pkhf(e0*n0, e1*n1);
            sPw[(size_t)(gid+8)*SPP + nt*4 + tig] = pkhf(e2*n0, e3*n1);
        }
        __syncwarp();

        // ---- O += P @ V  (V = diag(n)K folded into P)
#pragma unroll
        for (int ks2 = 0; ks2 < 8; ks2++) {
            uint32_t a0 = sPw[(size_t)gid*SPP     + ks2*8 + tig];
            uint32_t a1 = sPw[(size_t)(gid+8)*SPP + ks2*8 + tig];
            uint32_t a2 = sPw[(size_t)gid*SPP     + ks2*8 + tig + 4];
            uint32_t a3 = sPw[(size_t)(gid+8)*SPP + ks2*8 + tig + 4];
#pragma unroll
            for (int nt2 = 0; nt2 < 4; nt2++) {
                int dimc = nt2*8 + gid;
                uint32_t v0 = sKd[dimc*SPD + ks2*8 + tig];
                uint32_t v1 = sKd[dimc*SPD + ks2*8 + tig + 4];
                mma_f16(acc_o[nt2], a0,a1,a2,a3, v0, v1);
            }
        }
    }

    l0 += __shfl_xor_sync(0xffffffffu, l0, 1);
    l0 += __shfl_xor_sync(0xffffffffu, l0, 2);
    l1 += __shfl_xor_sync(0xffffffffu, l1, 1);
    l1 += __shfl_xor_sync(0xffffffffu, l1, 2);
    float i0 = 1.f / l0, i1 = 1.f / l1;

    int q0 = qb + gid, q1 = qb + gid + 8;
#pragma unroll
    for (int nt2 = 0; nt2 < 4; nt2++) {
        int d0 = nt2*8 + 2*tig, d1 = d0 + 1;
        g_out3[((size_t)b*C8 + d0)*HW + q0] = acc_o[nt2].x * i0;
        g_out3[((size_t)b*C8 + d1)*HW + q0] = acc_o[nt2].y * i0;
        g_out3[((size_t)b*C8 + d0)*HW + q1] = acc_o[nt2].z * i1;
        g_out3[((size_t)b*C8 + d1)*HW + q1] = acc_o[nt2].w * i1;
    }
}

// ================= final: fused chout + 1x1s =================
__global__ void __launch_bounds__(256, 2) final_k(
    const float* __restrict__ w3, const float* __restrict__ b3,
    const float* __restrict__ w4, const float* __restrict__ b4,
    float* __restrict__ out)
{
    __shared__ float sw3[64*32];
    __shared__ float sw4[Cc*C8];
    __shared__ float sb4[Cc];
    __shared__ float sA[C8*C8];
    __shared__ float so3[64*33];

    const int tid = threadIdx.x;
    const int px = tid & 63, coh = tid >> 6;
    const int g0 = blockIdx.x * 64;
    const int gp = g0 + px;
    const int b = gp >> 12, k = gp & (HW-1);

    for (int idx = tid; idx < 64*32; idx += 256) {
        int j = idx >> 5, o = idx & 31;
        sw3[j*32 + o] = w3[o*64 + j];
    }
    for (int idx = tid; idx < Cc*C8; idx += 256) sw4[idx] = w4[idx];
    if (tid < Cc) sb4[tid] = b4[tid];
    for (int idx = tid; idx < C8*C8; idx += 256) sA[idx] = g_attn1[b*C8*C8 + idx];

    if (coh == 0) {
        const float* o3 = g_out3 + (size_t)b*C8*HW + k;
#pragma unroll
        for (int c = 0; c < C8; c++) so3[px*33 + c] = __ldg(o3 + (size_t)c*HW);
    }
    __syncthreads();

    float tv[C8];
    {
        const float* tb = g_t + (size_t)b*C8*HW + k;
#pragma unroll
        for (int c = 0; c < C8; c++) tv[c] = tb[(size_t)c*HW];
    }
    u64 tvp[16];
#pragma unroll
    for (int d = 0; d < 16; d++) tvp[d] = pack2(tv[2*d], tv[2*d+1]);

    float out2[C8];
#pragma unroll
    for (int i = 0; i < C8; i++) {
        const u64* ar = (const u64*)(sA + i*32);
        u64 s2 = pack2(0.f, 0.f);
#pragma unroll
        for (int d = 0; d < 16; d++) s2 = ffma2(ar[d], tvp[d], s2);
        float2 f = unpack2(s2);
        out2[i] = f.x + f.y;
    }

    u64 o5[16];
#pragma unroll
    for (int d = 0; d < 16; d++)
        o5[d] = pack2(__ldg(b3 + 2*d) + tv[2*d], __ldg(b3 + 2*d+1) + tv[2*d+1]);

#pragma unroll 4
    for (int j = 0; j < 32; j++) {
        u64 vp = pack2(out2[j], out2[j]);
        const u64* wr = (const u64*)(sw3 + j*32);
#pragma unroll
        for (int d = 0; d < 16; d++) o5[d] = ffma2(vp, wr[d], o5[d]);
    }
#pragma unroll 4
    for (int j = 0; j < 32; j++) {
        float v = so3[px*33 + j];
        u64 vp = pack2(v, v);
        const u64* wr = (const u64*)(sw3 + (32+j)*32);
#pragma unroll
        for (int d = 0; d < 16; d++) o5[d] = ffma2(vp, wr[d], o5[d]);
    }

    const int co0 = coh * 64;
    float* dst = out + (size_t)b*Cc*HW + (size_t)co0*HW + k;
#pragma unroll 2
    for (int cc = 0; cc < 64; cc += 2) {
        const u64* w0 = (const u64*)(sw4 + (co0+cc)*C8);
        const u64* w1 = (const u64*)(sw4 + (co0+cc+1)*C8);
        u64 s0 = pack2(0.f, 0.f), s1 = pack2(0.f, 0.f);
#pragma unroll
        for (int d = 0; d < 16; d++) {
            s0 = ffma2(w0[d], o5[d], s0);
            s1 = ffma2(w1[d], o5[d], s1);
        }
        float2 f0 = unpack2(s0), f1 = unpack2(s1);
        dst[(size_t)cc*HW]     = f0.x + f0.y + sb4[co0+cc];
        dst[(size_t)(cc+1)*HW] = f1.x + f1.y + sb4[co0+cc+1];
    }
}

// ================= launch =================
extern "C" void kernel_launch(void* const* d_in, const int* in_sizes, int n_in,
                              void* d_out, int out_size)
{
    const float* x      = (const float*)d_in[0];
    const float* w_conv = (const float*)d_in[1];
    const float* b_conv = (const float*)d_in[2];
    const float* w01 = (const float*)d_in[3];
    const float* b01 = (const float*)d_in[4];
    const float* w02 = (const float*)d_in[5];
    const float* b02 = (const float*)d_in[6];
    const float* w11 = (const float*)d_in[7];
    const float* b11 = (const float*)d_in[8];
    const float* w12 = (const float*)d_in[9];
    const float* b12 = (const float*)d_in[10];
    const float* w21 = (const float*)d_in[11];
    const float* b21 = (const float*)d_in[12];
    const float* w22 = (const float*)d_in[13];
    const float* b22 = (const float*)d_in[14];
    const float* w_proj = (const float*)d_in[15];
    const float* b_proj = (const float*)d_in[16];
    const float* w3 = (const float*)d_in[17];
    const float* b3 = (const float*)d_in[18];
    const float* w4 = (const float*)d_in[19];
    const float* b4 = (const float*)d_in[20];
    float* out = (float*)d_out;

    const int convSmem = (SXB_ELEMS + SW_ALL) * (int)sizeof(uint32_t);
    const int spSmem   = (128*SPN + 32*SPD + 8*16*SPP) * (int)sizeof(uint32_t)
                       + 128 * (int)sizeof(float);
    static bool attrSet = false;
    if (!attrSet) {
        cudaFuncSetAttribute(convmma_k, cudaFuncAttributeMaxDynamicSharedMemorySize, convSmem);
        cudaFuncSetAttribute(spflash_k, cudaFuncAttributeMaxDynamicSharedMemorySize, spSmem);
        attrSet = true;
    }

    wprep_k   <<<9*128*Cc/256, 256>>>(w_conv);
    convmma_k <<<dim3(32, 2, 4), 256, convSmem>>>(x, b_conv);
    dwfused_k <<<Bn*Cc, 256>>>(w01, b01, w02, b02, w11, b11, w12, b12, w21, b21, w22, b22);
    projnorm_k<<<256, 256>>>(w_proj, b_proj);
    chsoft_k  <<<4, 1024>>>(nullptr);
    spflash_k <<<dim3(32, 4), 256, spSmem>>>();
    final_k   <<<256, 256>>>(w3, b3, w4, b4, out);
}

// round 13
// speedup vs baseline: 1.9572x; 1.0535x over previous
#include <cuda_runtime.h>
#include <cuda_fp16.h>
#include <math.h>
#include <stdint.h>

#define Bn 4
#define Cc 256
#define C8 32
#define Hh 64
#define Ww 64
#define HW 4096

typedef unsigned long long u64;

__device__ __forceinline__ u64 ffma2(u64 a, u64 b, u64 c){
    u64 d; asm("fma.rn.f32x2 %0, %1, %2, %3;" : "=l"(d) : "l"(a), "l"(b), "l"(c)); return d;
}
__device__ __forceinline__ u64 pack2(float lo, float hi){
    u64 d; asm("mov.b64 %0, {%1, %2};" : "=l"(d) : "f"(lo), "f"(hi)); return d;
}
__device__ __forceinline__ float2 unpack2(u64 v){
    float lo, hi; asm("mov.b64 {%0, %1}, %2;" : "=f"(lo), "=f"(hi) : "l"(v));
    return make_float2(lo, hi);
}
__device__ __forceinline__ void mma_f16(float4& d, const uint32_t a0, const uint32_t a1,
                                        const uint32_t a2, const uint32_t a3,
                                        const uint32_t b0, const uint32_t b1){
    asm volatile(
      "mma.sync.aligned.m16n8k16.row.col.f32.f16.f16.f32 "
      "{%0,%1,%2,%3}, {%4,%5,%6,%7}, {%8,%9}, {%0,%1,%2,%3};"
      : "+f"(d.x), "+f"(d.y), "+f"(d.z), "+f"(d.w)
      : "r"(a0), "r"(a1), "r"(a2), "r"(a3), "r"(b0), "r"(b1));
}
__device__ __forceinline__ uint32_t pkhf(float a, float b){
    __half2 t = __floats2half2_rn(a, b);
    return *reinterpret_cast<uint32_t*>(&t);
}

// ---------------- scratch ----------------
__device__ float g_x  [Bn*Cc*HW];
__device__ float g_sum[Bn*Cc*HW];
__device__ float g_t  [Bn*C8*HW];
__device__ float g_attn1[Bn*C8*C8];
__device__ float g_p3 [Bn*2*HW*C8];   // split-K partial acc (norm folded)
__device__ float g_pl [Bn*2*HW];      // split-K partial l
__device__ uint32_t g_qh[Bn*HW*16];   // l2-normalized rows, fp16 pairs
__device__ float g_norm[Bn*HW];
__device__ float g_pgram[Bn*128*C8*C8];
__device__ uint32_t g_wf[9*128*Cc];

// ================= weight prep =================
__global__ void __launch_bounds__(256) wprep_k(const float* __restrict__ w)
{
    int idx = blockIdx.x * 256 + threadIdx.x;
    int co  = idx & 255;
    int ci2 = (idx >> 8) & 127;
    int tap = idx >> 15;
    float v0 = w[((size_t)co*Cc + 2*ci2    )*9 + tap];
    float v1 = w[((size_t)co*Cc + 2*ci2 + 1)*9 + tap];
    g_wf[idx] = pkhf(v0, v1);
}

// ================= 3x3 conv via fp16 m16n8k16 MMA =================
#define SXB 264
#define SWB 136
#define SWT (8*SWB)
#define SXB_ELEMS (8*SXB)
#define SW_ALL (9*SWT)

__global__ void __launch_bounds__(256, 2) convmma_k(
    const float* __restrict__ x, const float* __restrict__ bias)
{
    extern __shared__ uint32_t smu[];
    uint32_t* sX = smu;
    uint32_t* sW = sX + SXB_ELEMS;

    const int pb = blockIdx.x, cog = blockIdx.y, b = blockIdx.z;
    const int tid  = threadIdx.x;
    const int wid  = tid >> 5, lane = tid & 31;
    const int wm   = wid >> 1, wn = wid & 1;
    const int gid  = lane >> 2, tig = lane & 3;
    const int h0   = pb * 2;

    float4 acc[2][8];
#pragma unroll
    for (int mt = 0; mt < 2; mt++)
#pragma unroll
        for (int nt = 0; nt < 8; nt++) acc[mt][nt] = make_float4(0.f,0.f,0.f,0.f);

    for (int cib = 0; cib < Cc/16; cib++) {
        __syncthreads();
        for (int e = tid; e < 8*264; e += 256) {
            int ci2 = e / 264;
            int rem = e - ci2*264;
            int r = rem / 66;
            int c = rem - r*66;
            int gh = h0 - 1 + r, gw = c - 1;
            float v0 = 0.f, v1 = 0.f;
            if (gh >= 0 && gh < Hh && gw >= 0 && gw < Ww) {
                const float* p = x + ((size_t)(b*Cc + cib*16 + 2*ci2))*HW + gh*Ww + gw;
                v0 = __ldg(p);
                v1 = __ldg(p + HW);
            }
            sX[ci2*SXB + rem] = pkhf(v0, v1);
        }
        {
            const size_t base = (size_t)(cib*8)*256 + cog*128;
#pragma unroll
            for (int i = 0; i < 9; i++) {
                int e = tid + i*256;
                int tap = e >> 8;
                int rem = e & 255;
                int ci2 = rem >> 5, c4 = rem & 31;
                uint4 v = __ldg((const uint4*)(g_wf + (size_t)tap*32768 + base + (size_t)ci2*256) + c4);
                *(uint4*)(sW + tap*SWT + ci2*SWB + c4*4) = v;
            }
        }
        __syncthreads();

#pragma unroll
        for (int tap = 0; tap < 9; tap++) {
            const int dh = tap/3 - 1, dw = tap%3 - 1;
            const uint32_t* wt = sW + tap*SWT;

            uint32_t a[2][4];
#pragma unroll
            for (int mt = 0; mt < 2; mt++) {
                int cb = wm*32 + mt*16 + gid;
                a[mt][0] = wt[tig*SWB + cb];       a[mt][1] = wt[tig*SWB + cb + 8];
                a[mt][2] = wt[(tig+4)*SWB + cb];   a[mt][3] = wt[(tig+4)*SWB + cb + 8];
            }
            const int boff = tig*SXB + (wn + 1 + dh)*66 + 1 + dw + gid;
#pragma unroll
            for (int nt = 0; nt < 8; nt++) {
                uint32_t b0 = sX[boff + nt*8];
                uint32_t b1 = sX[boff + nt*8 + 4*SXB];
#pragma unroll
                for (int mt = 0; mt < 2; mt++)
                    mma_f16(acc[mt][nt], a[mt][0],a[mt][1],a[mt][2],a[mt][3], b0, b1);
            }
        }
    }

#pragma unroll
    for (int mt = 0; mt < 2; mt++) {
        int co0 = cog*128 + wm*32 + mt*16 + gid;
        float b0 = __ldg(bias + co0);
        float b1 = __ldg(bias + co0 + 8);
#pragma unroll
        for (int nt = 0; nt < 8; nt++) {
            int px = pb*128 + wn*64 + nt*8 + 2*tig;
            float2* d0 = (float2*)(g_x + ((size_t)(b*Cc + co0))*HW + px);
            float2* d1 = (float2*)(g_x + ((size_t)(b*Cc + co0 + 8))*HW + px);
            float4 a4 = acc[mt][nt];
            *d0 = make_float2(a4.x + b0, a4.y + b0);
            *d1 = make_float2(a4.z + b1, a4.w + b1);
        }
    }
}

// ================= fused depthwise, zero-padded halos =================
#define XSP 88
template<int K>
__device__ __forceinline__ void dw_scale(
    const float* xs, float* hb, float out[16],
    const float* __restrict__ wh_c, const float* __restrict__ wv_c,
    float bh, float bv, int w, int h0)
{
    constexpr int P = K/2;
    float whr[K];
#pragma unroll
    for (int k = 0; k < K; k++) whr[k] = __ldg(wh_c + k);
#pragma unroll
    for (int i = 0; i < 16; i++) {
        int h = h0 + i; float s = bh;
        const float* row = xs + h*XSP + 12 + w - P;
#pragma unroll
        for (int k = 0; k < K; k++) s += whr[k] * row[k];
        hb[(12 + h)*64 + w] = s;
    }
    __syncthreads();
    float wvr[K];
#pragma unroll
    for (int k = 0; k < K; k++) wvr[k] = __ldg(wv_c + k);
#pragma unroll
    for (int i = 0; i < 16; i++) {
        int h = h0 + i; float s = bv;
        const float* col = hb + (12 + h - P)*64 + w;
#pragma unroll
        for (int k = 0; k < K; k++) s += wvr[k] * col[k*64];
        out[i] += s;
    }
    __syncthreads();
}

__global__ void __launch_bounds__(256) dwfused_k(
    const float* __restrict__ w01, const float* __restrict__ b01,
    const float* __restrict__ w02, const float* __restrict__ b02,
    const float* __restrict__ w11, const float* __restrict__ b11,
    const float* __restrict__ w12, const float* __restrict__ b12,
    const float* __restrict__ w21, const float* __restrict__ b21,
    const float* __restrict__ w22, const float* __restrict__ b22)
{
    __shared__ float sbuf[64*XSP + XSP*64];
    float* xs = sbuf;
    float* hb = sbuf + 64*XSP;

    const int plane = blockIdx.x;
    const int c = plane & (Cc-1);
    const int tid = threadIdx.x;
    const float* src = g_x + (size_t)plane*HW;

#pragma unroll
    for (int s = 0; s < 11; s++)
        ((float4*)sbuf)[tid + s*256] = make_float4(0.f,0.f,0.f,0.f);
    __syncthreads();

#pragma unroll
    for (int s = 0; s < 4; s++) {
        int idx = tid + s*256;
        float4 v = ((const float4*)src)[idx];
        int h = idx >> 4, w4 = idx & 15;
        *(float4*)(xs + h*XSP + 12 + w4*4) = v;
    }
    __syncthreads();

    const int w  = tid & 63;
    const int h0 = (tid >> 6) * 16;

    float out[16];
#pragma unroll
    for (int i = 0; i < 16; i++) out[i] = xs[(h0+i)*XSP + 12 + w];

    dw_scale<7> (xs, hb, out, w01 + c*7,  w02 + c*7,  __ldg(b01+c), __ldg(b02+c), w, h0);
    dw_scale<11>(xs, hb, out, w11 + c*11, w12 + c*11, __ldg(b11+c), __ldg(b12+c), w, h0);
    dw_scale<21>(xs, hb, out, w21 + c*21, w22 + c*21, __ldg(b21+c), __ldg(b22+c), w, h0);

    float* dst = g_sum + (size_t)plane*HW;
#pragma unroll
    for (int i = 0; i < 16; i++) dst[(h0+i)*Ww + w] = out[i];
}

// ================= fused 1x1 proj + l2norm + gram partials =================
// grid 512, block 256 = 32 px x 8 channel-slices of 32
__global__ void __launch_bounds__(256, 2) projnorm_k(
    const float* __restrict__ w_proj, const float* __restrict__ b_proj)
{
    __shared__ float ws[Cc*C8];
    __shared__ float sred[8*32*33];
    __shared__ float st[32*33];

    const int tid = threadIdx.x;
    for (int idx = tid; idx < Cc*C8; idx += 256) {
        int o = idx >> 8, c = idx & 255;
        ws[c*C8 + o] = w_proj[o*Cc + c];
    }
    __syncthreads();

    const int px = tid & 31, slice = tid >> 5;
    const int g0 = blockIdx.x * 32;
    const int gp = g0 + px;
    const int b = gp >> 12, k = gp & (HW-1);

    u64 acc[16];
    const u64 zero = pack2(0.f, 0.f);
#pragma unroll
    for (int d = 0; d < 16; d++) acc[d] = zero;

    const float* src = g_sum + (size_t)b*Cc*HW + (size_t)slice*32*HW + k;
    const float* wsl = ws + slice*32*C8;
#pragma unroll 8
    for (int c = 0; c < 32; c++) {
        float v = __ldg(src + (size_t)c*HW);
        u64 vp = pack2(v, v);
        const u64* wrow = (const u64*)(wsl + c*C8);
#pragma unroll
        for (int d = 0; d < 16; d++) acc[d] = ffma2(vp, wrow[d], acc[d]);
    }
    float* srow = sred + (slice*32 + px)*33;
#pragma unroll
    for (int d = 0; d < 16; d++) {
        float2 v = unpack2(acc[d]);
        srow[2*d] = v.x; srow[2*d+1] = v.y;
    }
    __syncthreads();

    // reduce 8 slices + bias -> st [32 px][32 o]
    for (int e = tid; e < 32*C8; e += 256) {
        int p = e >> 5, o = e & 31;
        float v = __ldg(b_proj + o);
#pragma unroll
        for (int s = 0; s < 8; s++) v += sred[(s*32 + p)*33 + o];
        st[p*33 + o] = v;
    }
    __syncthreads();

    // t, norms, fp16 q2n (32 threads, one per px)
    if (tid < 32) {
        int p = tid;
        int gpp = g0 + p;
        int bb = gpp >> 12, kk = gpp & (HW-1);
        float v[C8]; float ss = 0.f;
#pragma unroll
        for (int c = 0; c < C8; c++) { v[c] = st[p*33 + c]; ss += v[c]*v[c]; }
        float n = sqrtf(ss);
        float inv = 1.f / fmaxf(n, 1e-12f);
        g_norm[gpp] = n;
        uint32_t* qh = g_qh + (size_t)gpp*16;
#pragma unroll
        for (int d = 0; d < 8; d++) {
            qh[2*d]   = pkhf(v[4*d+0]*inv, v[4*d+1]*inv);
            qh[2*d+1] = pkhf(v[4*d+2]*inv, v[4*d+3]*inv);
        }
        float* tb = g_t + (size_t)bb*C8*HW + kk;
#pragma unroll
        for (int c = 0; c < C8; c++) tb[(size_t)c*HW] = v[c];
    }

    // gram partial over this block's 32 pixels
    {
        const int i  = tid >> 3;
        const int j0 = (tid & 7) * 4;
        float s0=0.f, s1=0.f, s2=0.f, s3=0.f;
#pragma unroll 8
        for (int xx = 0; xx < 32; xx++) {
            const float* r = st + xx*33;
            float a = r[i];
            s0 += a*r[j0]; s1 += a*r[j0+1]; s2 += a*r[j0+2]; s3 += a*r[j0+3];
        }
        float* dst = g_pgram + ((size_t)blockIdx.x << 10) + i*32 + j0;
        dst[0]=s0; dst[1]=s1; dst[2]=s2; dst[3]=s3;
    }
}

// ================= reduce gram (128 slabs) + softmax =================
__global__ void __launch_bounds__(1024) chsoft_k()
{
    const int b = blockIdx.x;
    const int tid = threadIdx.x;
    __shared__ float G[1024];
    __shared__ float ninv[32];

    float g = 0.f;
#pragma unroll 8
    for (int s = 0; s < 128; s++)
        g += g_pgram[(((size_t)b*128 + s) << 10) + tid];
    G[tid] = g;
    if ((tid >> 5) == (tid & 31)) ninv[tid & 31] = 1.f / fmaxf(sqrtf(g), 1e-12f);
    __syncthreads();

    if (tid < 32) {
        int r = tid;
        float ir = ninv[r];
        float row[32]; float s = 0.f;
#pragma unroll
        for (int jj = 0; jj < 32; jj++) {
            float a = G[r*32 + jj] * ir * ninv[jj];
            float p = expf(a - 1.f);
            row[jj] = p; s += p;
        }
        float is = 1.f / s;
        float* dst = g_attn1 + b*C8*C8 + r*32;
#pragma unroll
        for (int jj = 0; jj < 32; jj++) dst[jj] = row[jj] * is;
    }
}

// ================= flash spatial attention, fp16 TC, split-K x2 =================
// grid (32 q-tiles, 2 k-splits, 4 b), block 256 (8 warps x 16 q-rows)
#define SPN 20
#define SPD 68
#define SPP 68

__global__ void __launch_bounds__(256, 2) spflash_k()
{
    extern __shared__ uint32_t su[];
    uint32_t* sKn = su;
    uint32_t* sKd = sKn + 128*SPN;
    uint32_t* sP  = sKd + 32*SPD;
    float*    sN  = (float*)(sP + 8*16*SPP);

    const int tid = threadIdx.x;
    const int w = tid >> 5, lane = tid & 31;
    const int gid = lane >> 2, tig = lane & 3;
    const int ks = blockIdx.y, b = blockIdx.z;
    const int qb = blockIdx.x*128 + w*16;

    uint32_t qf[2][4];
    {
        const uint32_t* Q = g_qh + ((size_t)b*HW + qb)*16;
#pragma unroll
        for (int kc = 0; kc < 2; kc++)
#pragma unroll
        for (int i = 0; i < 4; i++) {
            int row = gid + (i & 1)*8;
            int du = kc*8 + tig + ((i & 2) ? 4 : 0);
            qf[kc][i] = __ldg(Q + row*16 + du);
        }
    }

    float4 acc_o[4];
#pragma unroll
    for (int n = 0; n < 4; n++) acc_o[n] = make_float4(0.f,0.f,0.f,0.f);
    float l0 = 0.f, l1 = 0.f;
    uint32_t* sPw = sP + w*16*SPP;

    for (int kt = ks*16; kt < ks*16 + 16; kt++) {
        __syncthreads();
        {
            const uint4* src = (const uint4*)(g_qh + ((size_t)b*HW + kt*128)*16);
            int key = tid & 127, hf = tid >> 7;
            uint4 v0 = __ldg(src + key*4 + hf*2);
            uint4 v1 = __ldg(src + key*4 + hf*2 + 1);
            *(uint4*)(sKn + key*SPN + hf*8)     = v0;
            *(uint4*)(sKn + key*SPN + hf*8 + 4) = v1;
            int k2 = tid & 63, dg = tid >> 6;
            uint4 ua = __ldg(src + (2*k2)*4 + dg);
            uint4 ub = __ldg(src + (2*k2+1)*4 + dg);
            uint32_t uaa[4] = {ua.x, ua.y, ua.z, ua.w};
            uint32_t ubb[4] = {ub.x, ub.y, ub.z, ub.w};
#pragma unroll
            for (int j = 0; j < 4; j++) {
                sKd[(dg*8 + 2*j  )*SPD + k2] = __byte_perm(uaa[j], ubb[j], 0x5410);
                sKd[(dg*8 + 2*j+1)*SPD + k2] = __byte_perm(uaa[j], ubb[j], 0x7632);
            }
            if (tid < 128) sN[tid] = g_norm[(size_t)b*HW + kt*128 + tid];
        }
        __syncthreads();

#pragma unroll 4
        for (int nt = 0; nt < 16; nt++) {
            float4 s = make_float4(0.f,0.f,0.f,0.f);
            const int key = nt*8 + gid;
#pragma unroll
            for (int kc = 0; kc < 2; kc++) {
                uint32_t b0 = sKn[key*SPN + kc*8 + tig];
                uint32_t b1 = sKn[key*SPN + kc*8 + tig + 4];
                mma_f16(s, qf[kc][0],qf[kc][1],qf[kc][2],qf[kc][3], b0, b1);
            }
            float n0 = sN[nt*8 + 2*tig], n1 = sN[nt*8 + 2*tig + 1];
            float e0 = __expf(s.x - 1.f), e1 = __expf(s.y - 1.f);
            float e2 = __expf(s.z - 1.f), e3 = __expf(s.w - 1.f);
            l0 += e0 + e1;
            l1 += e2 + e3;
            sPw[(size_t)gid*SPP     + nt*4 + tig] = pkhf(e0*n0, e1*n1);
            sPw[(size_t)(gid+8)*SPP + nt*4 + tig] = pkhf(e2*n0, e3*n1);
        }
        __syncwarp();

#pragma unroll
        for (int ks2 = 0; ks2 < 8; ks2++) {
            uint32_t a0 = sPw[(size_t)gid*SPP     + ks2*8 + tig];
            uint32_t a1 = sPw[(size_t)(gid+8)*SPP + ks2*8 + tig];
            uint32_t a2 = sPw[(size_t)gid*SPP     + ks2*8 + tig + 4];
            uint32_t a3 = sPw[(size_t)(gid+8)*SPP + ks2*8 + tig + 4];
#pragma unroll
            for (int nt2 = 0; nt2 < 4; nt2++) {
                int dimc = nt2*8 + gid;
                uint32_t v0 = sKd[dimc*SPD + ks2*8 + tig];
                uint32_t v1 = sKd[dimc*SPD + ks2*8 + tig + 4];
                mma_f16(acc_o[nt2], a0,a1,a2,a3, v0, v1);
            }
        }
    }

    l0 += __shfl_xor_sync(0xffffffffu, l0, 1);
    l0 += __shfl_xor_sync(0xffffffffu, l0, 2);
    l1 += __shfl_xor_sync(0xffffffffu, l1, 1);
    l1 += __shfl_xor_sync(0xffffffffu, l1, 2);

    int q0 = qb + gid, q1 = qb + gid + 8;
    float* p0 = g_p3 + ((size_t)(b*2 + ks)*HW + q0)*C8;
    float* p1 = g_p3 + ((size_t)(b*2 + ks)*HW + q1)*C8;
#pragma unroll
    for (int nt2 = 0; nt2 < 4; nt2++) {
        int d0 = nt2*8 + 2*tig, d1 = d0 + 1;
        p0[d0] = acc_o[nt2].x;  p0[d1] = acc_o[nt2].y;
        p1[d0] = acc_o[nt2].z;  p1[d1] = acc_o[nt2].w;
    }
    if (tig == 0) {
        g_pl[(size_t)(b*2 + ks)*HW + q0] = l0;
        g_pl[(size_t)(b*2 + ks)*HW + q1] = l1;
    }
}

// ================= final: combine split-K + chout + 1x1s =================
__global__ void __launch_bounds__(256, 2) final_k(
    const float* __restrict__ w3, const float* __restrict__ b3,
    const float* __restrict__ w4, const float* __restrict__ b4,
    float* __restrict__ out)
{
    __shared__ float sw3[64*32];
    __shared__ float sw4[Cc*C8];
    __shared__ float sb4[Cc];
    __shared__ float sA[C8*C8];
    __shared__ float so3[64*33];

    const int tid = threadIdx.x;
    const int px = tid & 63, coh = tid >> 6;
    const int g0 = blockIdx.x * 64;
    const int gp = g0 + px;
    const int b = gp >> 12, k = gp & (HW-1);

    for (int idx = tid; idx < 64*32; idx += 256) {
        int j = idx >> 5, o = idx & 31;
        sw3[j*32 + o] = w3[o*64 + j];
    }
    for (int idx = tid; idx < Cc*C8; idx += 256) sw4[idx] = w4[idx];
    if (tid < Cc) sb4[tid] = b4[tid];
    for (int idx = tid; idx < C8*C8; idx += 256) sA[idx] = g_attn1[b*C8*C8 + idx];

    // combine split-K partials -> so3
    if (coh == 0) {
        float l = g_pl[(size_t)(b*2)*HW + k] + g_pl[(size_t)(b*2+1)*HW + k];
        float inv = 1.f / l;
        const float4* pa = (const float4*)(g_p3 + ((size_t)(b*2)*HW + k)*C8);
        const float4* pb = (const float4*)(g_p3 + ((size_t)(b*2+1)*HW + k)*C8);
#pragma unroll
        for (int d = 0; d < 8; d++) {
            float4 va = pa[d], vb = pb[d];
            so3[px*33 + 4*d+0] = (va.x + vb.x) * inv;
            so3[px*33 + 4*d+1] = (va.y + vb.y) * inv;
            so3[px*33 + 4*d+2] = (va.z + vb.z) * inv;
            so3[px*33 + 4*d+3] = (va.w + vb.w) * inv;
        }
    }
    __syncthreads();

    float tv[C8];
    {
        const float* tb = g_t + (size_t)b*C8*HW + k;
#pragma unroll
        for (int c = 0; c < C8; c++) tv[c] = tb[(size_t)c*HW];
    }
    u64 tvp[16];
#pragma unroll
    for (int d = 0; d < 16; d++) tvp[d] = pack2(tv[2*d], tv[2*d+1]);

    float out2[C8];
#pragma unroll
    for (int i = 0; i < C8; i++) {
        const u64* ar = (const u64*)(sA + i*32);
        u64 s2 = pack2(0.f, 0.f);
#pragma unroll
        for (int d = 0; d < 16; d++) s2 = ffma2(ar[d], tvp[d], s2);
        float2 f = unpack2(s2);
        out2[i] = f.x + f.y;
    }

    u64 o5[16];
#pragma unroll
    for (int d = 0; d < 16; d++)
        o5[d] = pack2(__ldg(b3 + 2*d) + tv[2*d], __ldg(b3 + 2*d+1) + tv[2*d+1]);

#pragma unroll 4
    for (int j = 0; j < 32; j++) {
        u64 vp = pack2(out2[j], out2[j]);
        const u64* wr = (const u64*)(sw3 + j*32);
#pragma unroll
        for (int d = 0; d < 16; d++) o5[d] = ffma2(vp, wr[d], o5[d]);
    }
#pragma unroll 4
    for (int j = 0; j < 32; j++) {
        float v = so3[px*33 + j];
        u64 vp = pack2(v, v);
        const u64* wr = (const u64*)(sw3 + (32+j)*32);
#pragma unroll
        for (int d = 0; d < 16; d++) o5[d] = ffma2(vp, wr[d], o5[d]);
    }

    const int co0 = coh * 64;
    float* dst = out + (size_t)b*Cc*HW + (size_t)co0*HW + k;
#pragma unroll 2
    for (int cc = 0; cc < 64; cc += 2) {
        const u64* w0 = (const u64*)(sw4 + (co0+cc)*C8);
        const u64* w1 = (const u64*)(sw4 + (co0+cc+1)*C8);
        u64 s0 = pack2(0.f, 0.f), s1 = pack2(0.f, 0.f);
#pragma unroll
        for (int d = 0; d < 16; d++) {
            s0 = ffma2(w0[d], o5[d], s0);
            s1 = ffma2(w1[d], o5[d], s1);
        }
        float2 f0 = unpack2(s0), f1 = unpack2(s1);
        dst[(size_t)cc*HW]     = f0.x + f0.y + sb4[co0+cc];
        dst[(size_t)(cc+1)*HW] = f1.x + f1.y + sb4[co0+cc+1];
    }
}

// ================= launch =================
extern "C" void kernel_launch(void* const* d_in, const int* in_sizes, int n_in,
                              void* d_out, int out_size)
{
    const float* x      = (const float*)d_in[0];
    const float* w_conv = (const float*)d_in[1];
    const float* b_conv = (const float*)d_in[2];
    const float* w01 = (const float*)d_in[3];
    const float* b01 = (const float*)d_in[4];
    const float* w02 = (const float*)d_in[5];
    const float* b02 = (const float*)d_in[6];
    const float* w11 = (const float*)d_in[7];
    const float* b11 = (const float*)d_in[8];
    const float* w12 = (const float*)d_in[9];
    const float* b12 = (const float*)d_in[10];
    const float* w21 = (const float*)d_in[11];
    const float* b21 = (const float*)d_in[12];
    const float* w22 = (const float*)d_in[13];
    const float* b22 = (const float*)d_in[14];
    const float* w_proj = (const float*)d_in[15];
    const float* b_proj = (const float*)d_in[16];
    const float* w3 = (const float*)d_in[17];
    const float* b3 = (const float*)d_in[18];
    const float* w4 = (const float*)d_in[19];
    const float* b4 = (const float*)d_in[20];
    float* out = (float*)d_out;

    const int convSmem = (SXB_ELEMS + SW_ALL) * (int)sizeof(uint32_t);
    const int spSmem   = (128*SPN + 32*SPD + 8*16*SPP) * (int)sizeof(uint32_t)
                       + 128 * (int)sizeof(float);
    static bool attrSet = false;
    if (!attrSet) {
        cudaFuncSetAttribute(convmma_k, cudaFuncAttributeMaxDynamicSharedMemorySize, convSmem);
        cudaFuncSetAttribute(spflash_k, cudaFuncAttributeMaxDynamicSharedMemorySize, spSmem);
        attrSet = true;
    }

    wprep_k   <<<9*128*Cc/256, 256>>>(w_conv);
    convmma_k <<<dim3(32, 2, 4), 256, convSmem>>>(x, b_conv);
    dwfused_k <<<Bn*Cc, 256>>>(w01, b01, w02, b02, w11, b11, w12, b12, w21, b21, w22, b22);
    projnorm_k<<<512, 256>>>(w_proj, b_proj);
    chsoft_k  <<<4, 1024>>>();
    spflash_k <<<dim3(32, 2, 4), 256, spSmem>>>();
    final_k   <<<256, 256>>>(w3, b3, w4, b4, out);
}

// round 14
// speedup vs baseline: 1.9902x; 1.0168x over previous
#include <cuda_runtime.h>
#include <cuda_fp16.h>
#include <math.h>
#include <stdint.h>

#define Bn 4
#define Cc 256
#define C8 32
#define Hh 64
#define Ww 64
#define HW 4096

typedef unsigned long long u64;

__device__ __forceinline__ u64 ffma2(u64 a, u64 b, u64 c){
    u64 d; asm("fma.rn.f32x2 %0, %1, %2, %3;" : "=l"(d) : "l"(a), "l"(b), "l"(c)); return d;
}
__device__ __forceinline__ u64 pack2(float lo, float hi){
    u64 d; asm("mov.b64 %0, {%1, %2};" : "=l"(d) : "f"(lo), "f"(hi)); return d;
}
__device__ __forceinline__ float2 unpack2(u64 v){
    float lo, hi; asm("mov.b64 {%0, %1}, %2;" : "=f"(lo), "=f"(hi) : "l"(v));
    return make_float2(lo, hi);
}
__device__ __forceinline__ void mma_f16(float4& d, const uint32_t a0, const uint32_t a1,
                                        const uint32_t a2, const uint32_t a3,
                                        const uint32_t b0, const uint32_t b1){
    asm volatile(
      "mma.sync.aligned.m16n8k16.row.col.f32.f16.f16.f32 "
      "{%0,%1,%2,%3}, {%4,%5,%6,%7}, {%8,%9}, {%0,%1,%2,%3};"
      : "+f"(d.x), "+f"(d.y), "+f"(d.z), "+f"(d.w)
      : "r"(a0), "r"(a1), "r"(a2), "r"(a3), "r"(b0), "r"(b1));
}
__device__ __forceinline__ uint32_t pkhf(float a, float b){
    __half2 t = __floats2half2_rn(a, b);
    return *reinterpret_cast<uint32_t*>(&t);
}

// ---------------- scratch ----------------
__device__ __half g_x  [Bn*Cc*HW];    // conv output (fp16)
__device__ __half g_sum[Bn*Cc*HW];    // dw output (fp16)
__device__ float g_t  [Bn*C8*HW];
__device__ float g_attn1[Bn*C8*C8];
__device__ float g_p3 [Bn*2*HW*C8];
__device__ float g_pl [Bn*2*HW];
__device__ uint32_t g_qh[Bn*HW*16];
__device__ float g_norm[Bn*HW];
__device__ float g_pgram[Bn*128*C8*C8];
__device__ uint32_t g_wf[9*128*Cc];

// ================= weight prep =================
__global__ void __launch_bounds__(256) wprep_k(const float* __restrict__ w)
{
    int idx = blockIdx.x * 256 + threadIdx.x;
    int co  = idx & 255;
    int ci2 = (idx >> 8) & 127;
    int tap = idx >> 15;
    float v0 = w[((size_t)co*Cc + 2*ci2    )*9 + tap];
    float v1 = w[((size_t)co*Cc + 2*ci2 + 1)*9 + tap];
    g_wf[idx] = pkhf(v0, v1);
}

// ================= 3x3 conv via fp16 m16n8k16 MMA =================
#define SXB 264
#define SWB 136
#define SWT (8*SWB)
#define SXB_ELEMS (8*SXB)
#define SW_ALL (9*SWT)

__global__ void __launch_bounds__(256, 2) convmma_k(
    const float* __restrict__ x, const float* __restrict__ bias)
{
    extern __shared__ uint32_t smu[];
    uint32_t* sX = smu;
    uint32_t* sW = sX + SXB_ELEMS;

    const int pb = blockIdx.x, cog = blockIdx.y, b = blockIdx.z;
    const int tid  = threadIdx.x;
    const int wid  = tid >> 5, lane = tid & 31;
    const int wm   = wid >> 1, wn = wid & 1;
    const int gid  = lane >> 2, tig = lane & 3;
    const int h0   = pb * 2;

    float4 acc[2][8];
#pragma unroll
    for (int mt = 0; mt < 2; mt++)
#pragma unroll
        for (int nt = 0; nt < 8; nt++) acc[mt][nt] = make_float4(0.f,0.f,0.f,0.f);

    for (int cib = 0; cib < Cc/16; cib++) {
        __syncthreads();
        for (int e = tid; e < 8*264; e += 256) {
            int ci2 = e / 264;
            int rem = e - ci2*264;
            int r = rem / 66;
            int c = rem - r*66;
            int gh = h0 - 1 + r, gw = c - 1;
            float v0 = 0.f, v1 = 0.f;
            if (gh >= 0 && gh < Hh && gw >= 0 && gw < Ww) {
                const float* p = x + ((size_t)(b*Cc + cib*16 + 2*ci2))*HW + gh*Ww + gw;
                v0 = __ldg(p);
                v1 = __ldg(p + HW);
            }
            sX[ci2*SXB + rem] = pkhf(v0, v1);
        }
        {
            const size_t base = (size_t)(cib*8)*256 + cog*128;
#pragma unroll
            for (int i = 0; i < 9; i++) {
                int e = tid + i*256;
                int tap = e >> 8;
                int rem = e & 255;
                int ci2 = rem >> 5, c4 = rem & 31;
                uint4 v = __ldg((const uint4*)(g_wf + (size_t)tap*32768 + base + (size_t)ci2*256) + c4);
                *(uint4*)(sW + tap*SWT + ci2*SWB + c4*4) = v;
            }
        }
        __syncthreads();

#pragma unroll
        for (int tap = 0; tap < 9; tap++) {
            const int dh = tap/3 - 1, dw = tap%3 - 1;
            const uint32_t* wt = sW + tap*SWT;

            uint32_t a[2][4];
#pragma unroll
            for (int mt = 0; mt < 2; mt++) {
                int cb = wm*32 + mt*16 + gid;
                a[mt][0] = wt[tig*SWB + cb];       a[mt][1] = wt[tig*SWB + cb + 8];
                a[mt][2] = wt[(tig+4)*SWB + cb];   a[mt][3] = wt[(tig+4)*SWB + cb + 8];
            }
            const int boff = tig*SXB + (wn + 1 + dh)*66 + 1 + dw + gid;
#pragma unroll
            for (int nt = 0; nt < 8; nt++) {
                uint32_t b0 = sX[boff + nt*8];
                uint32_t b1 = sX[boff + nt*8 + 4*SXB];
#pragma unroll
                for (int mt = 0; mt < 2; mt++)
                    mma_f16(acc[mt][nt], a[mt][0],a[mt][1],a[mt][2],a[mt][3], b0, b1);
            }
        }
    }

#pragma unroll
    for (int mt = 0; mt < 2; mt++) {
        int co0 = cog*128 + wm*32 + mt*16 + gid;
        float b0 = __ldg(bias + co0);
        float b1 = __ldg(bias + co0 + 8);
#pragma unroll
        for (int nt = 0; nt < 8; nt++) {
            int px = pb*128 + wn*64 + nt*8 + 2*tig;
            __half* d0 = g_x + ((size_t)(b*Cc + co0))*HW + px;
            __half* d1 = g_x + ((size_t)(b*Cc + co0 + 8))*HW + px;
            float4 a4 = acc[mt][nt];
            *(half2*)d0 = __floats2half2_rn(a4.x + b0, a4.y + b0);
            *(half2*)d1 = __floats2half2_rn(a4.z + b1, a4.w + b1);
        }
    }
}

// ================= fused depthwise, zero-padded halos, fp16 I/O =================
#define XSP 88
template<int K>
__device__ __forceinline__ void dw_scale(
    const float* xs, float* hb, float out[16],
    const float* __restrict__ wh_c, const float* __restrict__ wv_c,
    float bh, float bv, int w, int h0)
{
    constexpr int P = K/2;
    float whr[K];
#pragma unroll
    for (int k = 0; k < K; k++) whr[k] = __ldg(wh_c + k);
#pragma unroll
    for (int i = 0; i < 16; i++) {
        int h = h0 + i; float s = bh;
        const float* row = xs + h*XSP + 12 + w - P;
#pragma unroll
        for (int k = 0; k < K; k++) s += whr[k] * row[k];
        hb[(12 + h)*64 + w] = s;
    }
    __syncthreads();
    float wvr[K];
#pragma unroll
    for (int k = 0; k < K; k++) wvr[k] = __ldg(wv_c + k);
#pragma unroll
    for (int i = 0; i < 16; i++) {
        int h = h0 + i; float s = bv;
        const float* col = hb + (12 + h - P)*64 + w;
#pragma unroll
        for (int k = 0; k < K; k++) s += wvr[k] * col[k*64];
        out[i] += s;
    }
    __syncthreads();
}

__global__ void __launch_bounds__(256) dwfused_k(
    const float* __restrict__ w01, const float* __restrict__ b01,
    const float* __restrict__ w02, const float* __restrict__ b02,
    const float* __restrict__ w11, const float* __restrict__ b11,
    const float* __restrict__ w12, const float* __restrict__ b12,
    const float* __restrict__ w21, const float* __restrict__ b21,
    const float* __restrict__ w22, const float* __restrict__ b22)
{
    __shared__ float sbuf[64*XSP + XSP*64];
    float* xs = sbuf;
    float* hb = sbuf + 64*XSP;

    const int plane = blockIdx.x;
    const int c = plane & (Cc-1);
    const int tid = threadIdx.x;
    const __half* src = g_x + (size_t)plane*HW;

#pragma unroll
    for (int s = 0; s < 11; s++)
        ((float4*)sbuf)[tid + s*256] = make_float4(0.f,0.f,0.f,0.f);
    __syncthreads();

    // stage interior: 512 uint4 groups of 8 halfs
#pragma unroll
    for (int s = 0; s < 2; s++) {
        int idx = tid + s*256;
        uint4 raw = ((const uint4*)src)[idx];
        int h = idx >> 3, w8 = (idx & 7)*8;
        float* dstp = xs + h*XSP + 12 + w8;
        float2 f0 = __half22float2(*(half2*)&raw.x);
        float2 f1 = __half22float2(*(half2*)&raw.y);
        float2 f2 = __half22float2(*(half2*)&raw.z);
        float2 f3 = __half22float2(*(half2*)&raw.w);
        dstp[0]=f0.x; dstp[1]=f0.y; dstp[2]=f1.x; dstp[3]=f1.y;
        dstp[4]=f2.x; dstp[5]=f2.y; dstp[6]=f3.x; dstp[7]=f3.y;
    }
    __syncthreads();

    const int w  = tid & 63;
    const int h0 = (tid >> 6) * 16;

    float out[16];
#pragma unroll
    for (int i = 0; i < 16; i++) out[i] = xs[(h0+i)*XSP + 12 + w];

    dw_scale<7> (xs, hb, out, w01 + c*7,  w02 + c*7,  __ldg(b01+c), __ldg(b02+c), w, h0);
    dw_scale<11>(xs, hb, out, w11 + c*11, w12 + c*11, __ldg(b11+c), __ldg(b12+c), w, h0);
    dw_scale<21>(xs, hb, out, w21 + c*21, w22 + c*21, __ldg(b21+c), __ldg(b22+c), w, h0);

    __half* dst = g_sum + (size_t)plane*HW;
#pragma unroll
    for (int i = 0; i < 16; i++) dst[(h0+i)*Ww + w] = __float2half_rn(out[i]);
}

// ================= fused 1x1 proj + l2norm + gram partials =================
// grid 512, block 256 = 32 px x 8 channel-slices of 32
__global__ void __launch_bounds__(256, 2) projnorm_k(
    const float* __restrict__ w_proj, const float* __restrict__ b_proj)
{
    __shared__ float ws[Cc*C8];
    __shared__ float sred[8*32*33];
    __shared__ float st[32*33];

    const int tid = threadIdx.x;
    for (int idx = tid; idx < Cc*C8; idx += 256) {
        int o = idx >> 8, c = idx & 255;
        ws[c*C8 + o] = w_proj[o*Cc + c];
    }
    __syncthreads();

    const int px = tid & 31, slice = tid >> 5;
    const int g0 = blockIdx.x * 32;
    const int gp = g0 + px;
    const int b = gp >> 12, k = gp & (HW-1);

    u64 acc[16];
    const u64 zero = pack2(0.f, 0.f);
#pragma unroll
    for (int d = 0; d < 16; d++) acc[d] = zero;

    const __half* src = g_sum + (size_t)b*Cc*HW + (size_t)slice*32*HW + k;
    const float* wsl = ws + slice*32*C8;
#pragma unroll 8
    for (int c = 0; c < 32; c++) {
        float v = __half2float(__ldg(src + (size_t)c*HW));
        u64 vp = pack2(v, v);
        const u64* wrow = (const u64*)(wsl + c*C8);
#pragma unroll
        for (int d = 0; d < 16; d++) acc[d] = ffma2(vp, wrow[d], acc[d]);
    }
    float* srow = sred + (slice*32 + px)*33;
#pragma unroll
    for (int d = 0; d < 16; d++) {
        float2 v = unpack2(acc[d]);
        srow[2*d] = v.x; srow[2*d+1] = v.y;
    }
    __syncthreads();

    for (int e = tid; e < 32*C8; e += 256) {
        int p = e >> 5, o = e & 31;
        float v = __ldg(b_proj + o);
#pragma unroll
        for (int s = 0; s < 8; s++) v += sred[(s*32 + p)*33 + o];
        st[p*33 + o] = v;
    }
    __syncthreads();

    if (tid < 32) {
        int p = tid;
        int gpp = g0 + p;
        int bb = gpp >> 12, kk = gpp & (HW-1);
        float v[C8]; float ss = 0.f;
#pragma unroll
        for (int c = 0; c < C8; c++) { v[c] = st[p*33 + c]; ss += v[c]*v[c]; }
        float n = sqrtf(ss);
        float inv = 1.f / fmaxf(n, 1e-12f);
        g_norm[gpp] = n;
        uint32_t* qh = g_qh + (size_t)gpp*16;
#pragma unroll
        for (int d = 0; d < 8; d++) {
            qh[2*d]   = pkhf(v[4*d+0]*inv, v[4*d+1]*inv);
            qh[2*d+1] = pkhf(v[4*d+2]*inv, v[4*d+3]*inv);
        }
        float* tb = g_t + (size_t)bb*C8*HW + kk;
#pragma unroll
        for (int c = 0; c < C8; c++) tb[(size_t)c*HW] = v[c];
    }

    {
        const int i  = tid >> 3;
        const int j0 = (tid & 7) * 4;
        float s0=0.f, s1=0.f, s2=0.f, s3=0.f;
#pragma unroll 8
        for (int xx = 0; xx < 32; xx++) {
            const float* r = st + xx*33;
            float a = r[i];
            s0 += a*r[j0]; s1 += a*r[j0+1]; s2 += a*r[j0+2]; s3 += a*r[j0+3];
        }
        float* dst = g_pgram + ((size_t)blockIdx.x << 10) + i*32 + j0;
        dst[0]=s0; dst[1]=s1; dst[2]=s2; dst[3]=s3;
    }
}

// ================= reduce gram + softmax =================
__global__ void __launch_bounds__(1024) chsoft_k()
{
    const int b = blockIdx.x;
    const int tid = threadIdx.x;
    __shared__ float G[1024];
    __shared__ float ninv[32];

    float g = 0.f;
#pragma unroll 8
    for (int s = 0; s < 128; s++)
        g += g_pgram[(((size_t)b*128 + s) << 10) + tid];
    G[tid] = g;
    if ((tid >> 5) == (tid & 31)) ninv[tid & 31] = 1.f / fmaxf(sqrtf(g), 1e-12f);
    __syncthreads();

    if (tid < 32) {
        int r = tid;
        float ir = ninv[r];
        float row[32]; float s = 0.f;
#pragma unroll
        for (int jj = 0; jj < 32; jj++) {
            float a = G[r*32 + jj] * ir * ninv[jj];
            float p = expf(a - 1.f);
            row[jj] = p; s += p;
        }
        float is = 1.f / s;
        float* dst = g_attn1 + b*C8*C8 + r*32;
#pragma unroll
        for (int jj = 0; jj < 32; jj++) dst[jj] = row[jj] * is;
    }
}

// ================= flash spatial attention, fp16 TC, split-K x2 =================
#define SPN 20
#define SPD 68
#define SPP 68

__global__ void __launch_bounds__(256, 2) spflash_k()
{
    extern __shared__ uint32_t su[];
    uint32_t* sKn = su;
    uint32_t* sKd = sKn + 128*SPN;
    uint32_t* sP  = sKd + 32*SPD;
    float*    sN  = (float*)(sP + 8*16*SPP);

    const int tid = threadIdx.x;
    const int w = tid >> 5, lane = tid & 31;
    const int gid = lane >> 2, tig = lane & 3;
    const int ks = blockIdx.y, b = blockIdx.z;
    const int qb = blockIdx.x*128 + w*16;

    uint32_t qf[2][4];
    {
        const uint32_t* Q = g_qh + ((size_t)b*HW + qb)*16;
#pragma unroll
        for (int kc = 0; kc < 2; kc++)
#pragma unroll
        for (int i = 0; i < 4; i++) {
            int row = gid + (i & 1)*8;
            int du = kc*8 + tig + ((i & 2) ? 4 : 0);
            qf[kc][i] = __ldg(Q + row*16 + du);
        }
    }

    float4 acc_o[4];
#pragma unroll
    for (int n = 0; n < 4; n++) acc_o[n] = make_float4(0.f,0.f,0.f,0.f);
    float l0 = 0.f, l1 = 0.f;
    uint32_t* sPw = sP + w*16*SPP;

    for (int kt = ks*16; kt < ks*16 + 16; kt++) {
        __syncthreads();
        {
            const uint4* src = (const uint4*)(g_qh + ((size_t)b*HW + kt*128)*16);
            int key = tid & 127, hf = tid >> 7;
            uint4 v0 = __ldg(src + key*4 + hf*2);
            uint4 v1 = __ldg(src + key*4 + hf*2 + 1);
            *(uint4*)(sKn + key*SPN + hf*8)     = v0;
            *(uint4*)(sKn + key*SPN + hf*8 + 4) = v1;
            int k2 = tid & 63, dg = tid >> 6;
            uint4 ua = __ldg(src + (2*k2)*4 + dg);
            uint4 ub = __ldg(src + (2*k2+1)*4 + dg);
            uint32_t uaa[4] = {ua.x, ua.y, ua.z, ua.w};
            uint32_t ubb[4] = {ub.x, ub.y, ub.z, ub.w};
#pragma unroll
            for (int j = 0; j < 4; j++) {
                sKd[(dg*8 + 2*j  )*SPD + k2] = __byte_perm(uaa[j], ubb[j], 0x5410);
                sKd[(dg*8 + 2*j+1)*SPD + k2] = __byte_perm(uaa[j], ubb[j], 0x7632);
            }
            if (tid < 128) sN[tid] = g_norm[(size_t)b*HW + kt*128 + tid];
        }
        __syncthreads();

#pragma unroll 4
        for (int nt = 0; nt < 16; nt++) {
            float4 s = make_float4(0.f,0.f,0.f,0.f);
            const int key = nt*8 + gid;
#pragma unroll
            for (int kc = 0; kc < 2; kc++) {
                uint32_t b0 = sKn[key*SPN + kc*8 + tig];
                uint32_t b1 = sKn[key*SPN + kc*8 + tig + 4];
                mma_f16(s, qf[kc][0],qf[kc][1],qf[kc][2],qf[kc][3], b0, b1);
            }
            float n0 = sN[nt*8 + 2*tig], n1 = sN[nt*8 + 2*tig + 1];
            float e0 = __expf(s.x - 1.f), e1 = __expf(s.y - 1.f);
            float e2 = __expf(s.z - 1.f), e3 = __expf(s.w - 1.f);
            l0 += e0 + e1;
            l1 += e2 + e3;
            sPw[(size_t)gid*SPP     + nt*4 + tig] = pkhf(e0*n0, e1*n1);
            sPw[(size_t)(gid+8)*SPP + nt*4 + tig] = pkhf(e2*n0, e3*n1);
        }
        __syncwarp();

#pragma unroll
        for (int ks2 = 0; ks2 < 8; ks2++) {
            uint32_t a0 = sPw[(size_t)gid*SPP     + ks2*8 + tig];
            uint32_t a1 = sPw[(size_t)(gid+8)*SPP + ks2*8 + tig];
            uint32_t a2 = sPw[(size_t)gid*SPP     + ks2*8 + tig + 4];
            uint32_t a3 = sPw[(size_t)(gid+8)*SPP + ks2*8 + tig + 4];
#pragma unroll
            for (int nt2 = 0; nt2 < 4; nt2++) {
                int dimc = nt2*8 + gid;
                uint32_t v0 = sKd[dimc*SPD + ks2*8 + tig];
                uint32_t v1 = sKd[dimc*SPD + ks2*8 + tig + 4];
                mma_f16(acc_o[nt2], a0,a1,a2,a3, v0, v1);
            }
        }
    }

    l0 += __shfl_xor_sync(0xffffffffu, l0, 1);
    l0 += __shfl_xor_sync(0xffffffffu, l0, 2);
    l1 += __shfl_xor_sync(0xffffffffu, l1, 1);
    l1 += __shfl_xor_sync(0xffffffffu, l1, 2);

    int q0 = qb + gid, q1 = qb + gid + 8;
    float* p0 = g_p3 + ((size_t)(b*2 + ks)*HW + q0)*C8;
    float* p1 = g_p3 + ((size_t)(b*2 + ks)*HW + q1)*C8;
#pragma unroll
    for (int nt2 = 0; nt2 < 4; nt2++) {
        int d0 = nt2*8 + 2*tig, d1 = d0 + 1;
        p0[d0] = acc_o[nt2].x;  p0[d1] = acc_o[nt2].y;
        p1[d0] = acc_o[nt2].z;  p1[d1] = acc_o[nt2].w;
    }
    if (tig == 0) {
        g_pl[(size_t)(b*2 + ks)*HW + q0] = l0;
        g_pl[(size_t)(b*2 + ks)*HW + q1] = l1;
    }
}

// ================= final: combine split-K + chout + 1x1s =================
__global__ void __launch_bounds__(256, 2) final_k(
    const float* __restrict__ w3, const float* __restrict__ b3,
    const float* __restrict__ w4, const float* __restrict__ b4,
    float* __restrict__ out)
{
    __shared__ float sw3[64*32];
    __shared__ float sw4[Cc*C8];
    __shared__ float sb4[Cc];
    __shared__ float sA[C8*C8];
    __shared__ float so3[64*33];

    const int tid = threadIdx.x;
    const int px = tid & 63, coh = tid >> 6;
    const int g0 = blockIdx.x * 64;
    const int gp = g0 + px;
    const int b = gp >> 12, k = gp & (HW-1);

    for (int idx = tid; idx < 64*32; idx += 256) {
        int j = idx >> 5, o = idx & 31;
        sw3[j*32 + o] = w3[o*64 + j];
    }
    for (int idx = tid; idx < Cc*C8; idx += 256) sw4[idx] = w4[idx];
    if (tid < Cc) sb4[tid] = b4[tid];
    for (int idx = tid; idx < C8*C8; idx += 256) sA[idx] = g_attn1[b*C8*C8 + idx];

    if (coh == 0) {
        float l = g_pl[(size_t)(b*2)*HW + k] + g_pl[(size_t)(b*2+1)*HW + k];
        float inv = 1.f / l;
        const float4* pa = (const float4*)(g_p3 + ((size_t)(b*2)*HW + k)*C8);
        const float4* pb = (const float4*)(g_p3 + ((size_t)(b*2+1)*HW + k)*C8);
#pragma unroll
        for (int d = 0; d < 8; d++) {
            float4 va = pa[d], vb = pb[d];
            so3[px*33 + 4*d+0] = (va.x + vb.x) * inv;
            so3[px*33 + 4*d+1] = (va.y + vb.y) * inv;
            so3[px*33 + 4*d+2] = (va.z + vb.z) * inv;
            so3[px*33 + 4*d+3] = (va.w + vb.w) * inv;
        }
    }
    __syncthreads();

    float tv[C8];
    {
        const float* tb = g_t + (size_t)b*C8*HW + k;
#pragma unroll
        for (int c = 0; c < C8; c++) tv[c] = tb[(size_t)c*HW];
    }
    u64 tvp[16];
#pragma unroll
    for (int d = 0; d < 16; d++) tvp[d] = pack2(tv[2*d], tv[2*d+1]);

    float out2[C8];
#pragma unroll
    for (int i = 0; i < C8; i++) {
        const u64* ar = (const u64*)(sA + i*32);
        u64 s2 = pack2(0.f, 0.f);
#pragma unroll
        for (int d = 0; d < 16; d++) s2 = ffma2(ar[d], tvp[d], s2);
        float2 f = unpack2(s2);
        out2[i] = f.x + f.y;
    }

    u64 o5[16];
#pragma unroll
    for (int d = 0; d < 16; d++)
        o5[d] = pack2(__ldg(b3 + 2*d) + tv[2*d], __ldg(b3 + 2*d+1) + tv[2*d+1]);

#pragma unroll 4
    for (int j = 0; j < 32; j++) {
        u64 vp = pack2(out2[j], out2[j]);
        const u64* wr = (const u64*)(sw3 + j*32);
#pragma unroll
        for (int d = 0; d < 16; d++) o5[d] = ffma2(vp, wr[d], o5[d]);
    }
#pragma unroll 4
    for (int j = 0; j < 32; j++) {
        float v = so3[px*33 + j];
        u64 vp = pack2(v, v);
        const u64* wr = (const u64*)(sw3 + (32+j)*32);
#pragma unroll
        for (int d = 0; d < 16; d++) o5[d] = ffma2(vp, wr[d], o5[d]);
    }

    const int co0 = coh * 64;
    float* dst = out + (size_t)b*Cc*HW + (size_t)co0*HW + k;
#pragma unroll 2
    for (int cc = 0; cc < 64; cc += 2) {
        const u64* w0 = (const u64*)(sw4 + (co0+cc)*C8);
        const u64* w1 = (const u64*)(sw4 + (co0+cc+1)*C8);
        u64 s0 = pack2(0.f, 0.f), s1 = pack2(0.f, 0.f);
#pragma unroll
        for (int d = 0; d < 16; d++) {
            s0 = ffma2(w0[d], o5[d], s0);
            s1 = ffma2(w1[d], o5[d], s1);
        }
        float2 f0 = unpack2(s0), f1 = unpack2(s1);
        dst[(size_t)cc*HW]     = f0.x + f0.y + sb4[co0+cc];
        dst[(size_t)(cc+1)*HW] = f1.x + f1.y + sb4[co0+cc+1];
    }
}

// ================= launch =================
extern "C" void kernel_launch(void* const* d_in, const int* in_sizes, int n_in,
                              void* d_out, int out_size)
{
    const float* x      = (const float*)d_in[0];
    const float* w_conv = (const float*)d_in[1];
    const float* b_conv = (const float*)d_in[2];
    const float* w01 = (const float*)d_in[3];
    const float* b01 = (const float*)d_in[4];
    const float* w02 = (const float*)d_in[5];
    const float* b02 = (const float*)d_in[6];
    const float* w11 = (const float*)d_in[7];
    const float* b11 = (const float*)d_in[8];
    const float* w12 = (const float*)d_in[9];
    const float* b12 = (const float*)d_in[10];
    const float* w21 = (const float*)d_in[11];
    const float* b21 = (const float*)d_in[12];
    const float* w22 = (const float*)d_in[13];
    const float* b22 = (const float*)d_in[14];
    const float* w_proj = (const float*)d_in[15];
    const float* b_proj = (const float*)d_in[16];
    const float* w3 = (const float*)d_in[17];
    const float* b3 = (const float*)d_in[18];
    const float* w4 = (const float*)d_in[19];
    const float* b4 = (const float*)d_in[20];
    float* out = (float*)d_out;

    const int convSmem = (SXB_ELEMS + SW_ALL) * (int)sizeof(uint32_t);
    const int spSmem   = (128*SPN + 32*SPD + 8*16*SPP) * (int)sizeof(uint32_t)
                       + 128 * (int)sizeof(float);
    static bool attrSet = false;
    if (!attrSet) {
        cudaFuncSetAttribute(convmma_k, cudaFuncAttributeMaxDynamicSharedMemorySize, convSmem);
        cudaFuncSetAttribute(spflash_k, cudaFuncAttributeMaxDynamicSharedMemorySize, spSmem);
        attrSet = true;
    }

    wprep_k   <<<9*128*Cc/256, 256>>>(w_conv);
    convmma_k <<<dim3(32, 2, 4), 256, convSmem>>>(x, b_conv);
    dwfused_k <<<Bn*Cc, 256>>>(w01, b01, w02, b02, w11, b11, w12, b12, w21, b21, w22, b22);
    projnorm_k<<<512, 256>>>(w_proj, b_proj);
    chsoft_k  <<<4, 1024>>>();
    spflash_k <<<dim3(32, 2, 4), 256, spSmem>>>();
    final_k   <<<256, 256>>>(w3, b3, w4, b4, out);
}

// round 16
// speedup vs baseline: 2.0806x; 1.0455x over previous
#include <cuda_runtime.h>
#include <cuda_fp16.h>
#include <math.h>
#include <stdint.h>

#define Bn 4
#define Cc 256
#define C8 32
#define Hh 64
#define Ww 64
#define HW 4096

typedef unsigned long long u64;

__device__ __forceinline__ u64 ffma2(u64 a, u64 b, u64 c){
    u64 d; asm("fma.rn.f32x2 %0, %1, %2, %3;" : "=l"(d) : "l"(a), "l"(b), "l"(c)); return d;
}
__device__ __forceinline__ u64 pack2(float lo, float hi){
    u64 d; asm("mov.b64 %0, {%1, %2};" : "=l"(d) : "f"(lo), "f"(hi)); return d;
}
__device__ __forceinline__ float2 unpack2(u64 v){
    float lo, hi; asm("mov.b64 {%0, %1}, %2;" : "=f"(lo), "=f"(hi) : "l"(v));
    return make_float2(lo, hi);
}
__device__ __forceinline__ void mma_f16(float4& d, const uint32_t a0, const uint32_t a1,
                                        const uint32_t a2, const uint32_t a3,
                                        const uint32_t b0, const uint32_t b1){
    asm volatile(
      "mma.sync.aligned.m16n8k16.row.col.f32.f16.f16.f32 "
      "{%0,%1,%2,%3}, {%4,%5,%6,%7}, {%8,%9}, {%0,%1,%2,%3};"
      : "+f"(d.x), "+f"(d.y), "+f"(d.z), "+f"(d.w)
      : "r"(a0), "r"(a1), "r"(a2), "r"(a3), "r"(b0), "r"(b1));
}
__device__ __forceinline__ uint32_t pkhf(float a, float b){
    __half2 t = __floats2half2_rn(a, b);
    return *reinterpret_cast<uint32_t*>(&t);
}

// ---------------- scratch ----------------
__device__ uint32_t g_xI [Bn*128*HW];   // input, channel-pair interleaved fp16
__device__ __half   g_x  [Bn*Cc*HW];    // conv output (fp16, planar)
__device__ uint32_t g_sumI[Bn*128*HW];  // dw output, channel-pair interleaved fp16
__device__ float g_t  [Bn*C8*HW];
__device__ float g_attn1[Bn*C8*C8];
__device__ float g_p3 [Bn*2*HW*C8];
__device__ float g_pl [Bn*2*HW];
__device__ uint32_t g_qh[Bn*HW*16];
__device__ float g_norm[Bn*HW];
__device__ float g_pgram[Bn*32*C8*C8];
__device__ uint32_t g_wf[9*128*Cc];
__device__ uint32_t g_wp[128*C8];       // w_proj fp16 pairs [k2][o]

// ================= input prep: fp32 planar -> fp16 channel-pair interleaved =================
__global__ void __launch_bounds__(256) xprep_k(const float* __restrict__ x)
{
    int idx = blockIdx.x * 256 + threadIdx.x;   // Bn*128*HW = 2097152
    int pos = idx & (HW-1);
    int p   = idx >> 12;           // b*128 + ci2
    int b   = p >> 7, ci2 = p & 127;
    const float* xp = x + ((size_t)(b*Cc + 2*ci2))*HW + pos;
    g_xI[idx] = pkhf(__ldg(xp), __ldg(xp + HW));
}

// ================= weight prep =================
__global__ void __launch_bounds__(256) wprep_k(const float* __restrict__ w,
                                               const float* __restrict__ w_proj)
{
    int idx = blockIdx.x * 256 + threadIdx.x;
    int co  = idx & 255;
    int ci2 = (idx >> 8) & 127;
    int tap = idx >> 15;
    float v0 = w[((size_t)co*Cc + 2*ci2    )*9 + tap];
    float v1 = w[((size_t)co*Cc + 2*ci2 + 1)*9 + tap];
    g_wf[idx] = pkhf(v0, v1);
    if (idx < 128*C8) {
        int k2 = idx >> 5, o = idx & 31;
        g_wp[idx] = pkhf(w_proj[o*Cc + 2*k2], w_proj[o*Cc + 2*k2 + 1]);
    }
}

// ================= 3x3 conv via fp16 m16n8k16 MMA =================
#define SXB 264
#define SWB 136
#define SWT (8*SWB)
#define SXB_ELEMS (8*SXB)
#define SW_ALL (9*SWT)

__global__ void __launch_bounds__(256, 2) convmma_k(const float* __restrict__ bias)
{
    extern __shared__ uint32_t smu[];
    uint32_t* sX = smu;
    uint32_t* sW = sX + SXB_ELEMS;

    const int pb = blockIdx.x, cog = blockIdx.y, b = blockIdx.z;
    const int tid  = threadIdx.x;
    const int wid  = tid >> 5, lane = tid & 31;
    const int wm   = wid >> 1, wn = wid & 1;
    const int gid  = lane >> 2, tig = lane & 3;
    const int h0   = pb * 2;

    float4 acc[2][8];
#pragma unroll
    for (int mt = 0; mt < 2; mt++)
#pragma unroll
        for (int nt = 0; nt < 8; nt++) acc[mt][nt] = make_float4(0.f,0.f,0.f,0.f);

    for (int cib = 0; cib < Cc/16; cib++) {
        __syncthreads();
        // ---- stage X strip from interleaved fp16: 1 LDG + 1 STS per elem
        for (int e = tid; e < 8*264; e += 256) {
            int ci2 = e / 264;
            int rem = e - ci2*264;
            int r = rem / 66;
            int c = rem - r*66;
            int gh = h0 - 1 + r, gw = c - 1;
            uint32_t v = 0;
            if (gh >= 0 && gh < Hh && gw >= 0 && gw < Ww)
                v = __ldg(g_xI + (size_t)(b*128 + cib*8 + ci2)*HW + gh*Ww + gw);
            sX[ci2*SXB + rem] = v;
        }
        {
            const size_t base = (size_t)(cib*8)*256 + cog*128;
#pragma unroll
            for (int i = 0; i < 9; i++) {
                int e = tid + i*256;
                int tap = e >> 8;
                int rem = e & 255;
                int ci2 = rem >> 5, c4 = rem & 31;
                uint4 v = __ldg((const uint4*)(g_wf + (size_t)tap*32768 + base + (size_t)ci2*256) + c4);
                *(uint4*)(sW + tap*SWT + ci2*SWB + c4*4) = v;
            }
        }
        __syncthreads();

#pragma unroll
        for (int tap = 0; tap < 9; tap++) {
            const int dh = tap/3 - 1, dw = tap%3 - 1;
            const uint32_t* wt = sW + tap*SWT;

            uint32_t a[2][4];
#pragma unroll
            for (int mt = 0; mt < 2; mt++) {
                int cb = wm*32 + mt*16 + gid;
                a[mt][0] = wt[tig*SWB + cb];       a[mt][1] = wt[tig*SWB + cb + 8];
                a[mt][2] = wt[(tig+4)*SWB + cb];   a[mt][3] = wt[(tig+4)*SWB + cb + 8];
            }
            const int boff = tig*SXB + (wn + 1 + dh)*66 + 1 + dw + gid;
#pragma unroll
            for (int nt = 0; nt < 8; nt++) {
                uint32_t b0 = sX[boff + nt*8];
                uint32_t b1 = sX[boff + nt*8 + 4*SXB];
#pragma unroll
                for (int mt = 0; mt < 2; mt++)
                    mma_f16(acc[mt][nt], a[mt][0],a[mt][1],a[mt][2],a[mt][3], b0, b1);
            }
        }
    }

#pragma unroll
    for (int mt = 0; mt < 2; mt++) {
        int co0 = cog*128 + wm*32 + mt*16 + gid;
        float b0 = __ldg(bias + co0);
        float b1 = __ldg(bias + co0 + 8);
#pragma unroll
        for (int nt = 0; nt < 8; nt++) {
            int px = pb*128 + wn*64 + nt*8 + 2*tig;
            __half* d0 = g_x + ((size_t)(b*Cc + co0))*HW + px;
            __half* d1 = g_x + ((size_t)(b*Cc + co0 + 8))*HW + px;
            float4 a4 = acc[mt][nt];
            *(half2*)d0 = __floats2half2_rn(a4.x + b0, a4.y + b0);
            *(half2*)d1 = __floats2half2_rn(a4.z + b1, a4.w + b1);
        }
    }
}

// ================= fused depthwise, zero-padded halos, fp16 I/O =================
#define XSP 88
template<int K>
__device__ __forceinline__ void dw_scale(
    const float* xs, float* hb, float out[16],
    const float* __restrict__ wh_c, const float* __restrict__ wv_c,
    float bh, float bv, int w, int h0)
{
    constexpr int P = K/2;
    float whr[K];
#pragma unroll
    for (int k = 0; k < K; k++) whr[k] = __ldg(wh_c + k);
#pragma unroll
    for (int i = 0; i < 16; i++) {
        int h = h0 + i; float s = bh;
        const float* row = xs + h*XSP + 12 + w - P;
#pragma unroll
        for (int k = 0; k < K; k++) s += whr[k] * row[k];
        hb[(12 + h)*64 + w] = s;
    }
    __syncthreads();
    float wvr[K];
#pragma unroll
    for (int k = 0; k < K; k++) wvr[k] = __ldg(wv_c + k);
#pragma unroll
    for (int i = 0; i < 16; i++) {
        int h = h0 + i; float s = bv;
        const float* col = hb + (12 + h - P)*64 + w;
#pragma unroll
        for (int k = 0; k < K; k++) s += wvr[k] * col[k*64];
        out[i] += s;
    }
    __syncthreads();
}

__global__ void __launch_bounds__(256) dwfused_k(
    const float* __restrict__ w01, const float* __restrict__ b01,
    const float* __restrict__ w02, const float* __restrict__ b02,
    const float* __restrict__ w11, const float* __restrict__ b11,
    const float* __restrict__ w12, const float* __restrict__ b12,
    const float* __restrict__ w21, const float* __restrict__ b21,
    const float* __restrict__ w22, const float* __restrict__ b22)
{
    __shared__ float sbuf[64*XSP + XSP*64];
    float* xs = sbuf;
    float* hb = sbuf + 64*XSP;

    const int plane = blockIdx.x;
    const int c = plane & (Cc-1);
    const int b = plane >> 8;
    const int tid = threadIdx.x;
    const __half* src = g_x + (size_t)plane*HW;

#pragma unroll
    for (int s = 0; s < 11; s++)
        ((float4*)sbuf)[tid + s*256] = make_float4(0.f,0.f,0.f,0.f);
    __syncthreads();

#pragma unroll
    for (int s = 0; s < 2; s++) {
        int idx = tid + s*256;
        uint4 raw = ((const uint4*)src)[idx];
        int h = idx >> 3, w8 = (idx & 7)*8;
        float* dstp = xs + h*XSP + 12 + w8;
        float2 f0 = __half22float2(*(half2*)&raw.x);
        float2 f1 = __half22float2(*(half2*)&raw.y);
        float2 f2 = __half22float2(*(half2*)&raw.z);
        float2 f3 = __half22float2(*(half2*)&raw.w);
        dstp[0]=f0.x; dstp[1]=f0.y; dstp[2]=f1.x; dstp[3]=f1.y;
        dstp[4]=f2.x; dstp[5]=f2.y; dstp[6]=f3.x; dstp[7]=f3.y;
    }
    __syncthreads();

    const int w  = tid & 63;
    const int h0 = (tid >> 6) * 16;

    float out[16];
#pragma unroll
    for (int i = 0; i < 16; i++) out[i] = xs[(h0+i)*XSP + 12 + w];

    dw_scale<7> (xs, hb, out, w01 + c*7,  w02 + c*7,  __ldg(b01+c), __ldg(b02+c), w, h0);
    dw_scale<11>(xs, hb, out, w11 + c*11, w12 + c*11, __ldg(b11+c), __ldg(b12+c), w, h0);
    dw_scale<21>(xs, hb, out, w21 + c*21, w22 + c*21, __ldg(b21+c), __ldg(b22+c), w, h0);

    // write into interleaved g_sumI (half scalar at slot c&1)
    __half* dst = (__half*)g_sumI + ((size_t)(b*128 + (c>>1))*HW)*2 + (c&1);
#pragma unroll
    for (int i = 0; i < 16; i++)
        dst[(size_t)((h0+i)*Ww + w)*2] = __float2half_rn(out[i]);
}

// ================= proj via tensor cores + l2norm + gram =================
// grid (32 px-tiles of 128, 4 b), block 256 (8 warps x 16 px)
#define SWPP 40     // u32 stride [k2][o]
#define SSP  136    // u32 stride [k2][px]

__global__ void __launch_bounds__(256, 2) projTC_k(const float* __restrict__ b_proj)
{
    extern __shared__ float smf[];
    uint32_t* sWp = (uint32_t*)smf;            // 128*40
    uint32_t* sS  = sWp + 128*SWPP;            // 64*136
    float*    st  = (float*)(sS + 64*SSP);     // 128*33

    const int tid = threadIdx.x;
    const int w = tid >> 5, lane = tid & 31;
    const int gid = lane >> 2, tig = lane & 3;
    const int pb = blockIdx.x, b = blockIdx.y;
    const int px0 = pb * 128;

    // stage W once: [k2][o] padded
#pragma unroll
    for (int i = 0; i < 16; i++) {
        int idx = tid + i*256;        // 4096
        int k2 = idx >> 5, o = idx & 31;
        sWp[k2*SWPP + o] = __ldg(g_wp + idx);
    }

    float4 acc[2][2];
#pragma unroll
    for (int mt = 0; mt < 2; mt++)
#pragma unroll
        for (int nt = 0; nt < 2; nt++) acc[mt][nt] = make_float4(0.f,0.f,0.f,0.f);

#pragma unroll
    for (int kc = 0; kc < 2; kc++) {
        __syncthreads();
        // stage S chunk: 64 k2 x 128 px, uint4 loads
#pragma unroll
        for (int i = 0; i < 8; i++) {
            int idx = tid + i*256;    // 2048 uint4
            int k2 = idx >> 5, c4 = idx & 31;
            uint4 v = __ldg((const uint4*)(g_sumI + (size_t)(b*128 + kc*64 + k2)*HW + px0) + c4);
            *(uint4*)(sS + k2*SSP + c4*4) = v;
        }
        __syncthreads();

#pragma unroll
        for (int ks2 = 0; ks2 < 8; ks2++) {
            uint32_t a[2][4];
#pragma unroll
            for (int mt = 0; mt < 2; mt++) {
                int o = mt*16 + gid;
                a[mt][0] = sWp[(kc*64 + ks2*8 + tig)*SWPP + o];
                a[mt][1] = sWp[(kc*64 + ks2*8 + tig)*SWPP + o + 8];
                a[mt][2] = sWp[(kc*64 + ks2*8 + tig + 4)*SWPP + o];
                a[mt][3] = sWp[(kc*64 + ks2*8 + tig + 4)*SWPP + o + 8];
            }
#pragma unroll
            for (int nt = 0; nt < 2; nt++) {
                int col = w*16 + nt*8 + gid;
                uint32_t b0 = sS[(ks2*8 + tig)*SSP + col];
                uint32_t b1 = sS[(ks2*8 + tig + 4)*SSP + col];
#pragma unroll
                for (int mt = 0; mt < 2; mt++)
                    mma_f16(acc[mt][nt], a[mt][0],a[mt][1],a[mt][2],a[mt][3], b0, b1);
            }
        }
    }

    // epilogue: add bias, park t tile in smem [px][o]
    __syncthreads();
#pragma unroll
    for (int mt = 0; mt < 2; mt++) {
        float bo0 = __ldg(b_proj + mt*16 + gid);
        float bo1 = __ldg(b_proj + mt*16 + gid + 8);
#pragma unroll
        for (int nt = 0; nt < 2; nt++) {
            int pxl = w*16 + nt*8 + 2*tig;
            float4 a4 = acc[mt][nt];
            st[(pxl  )*33 + mt*16 + gid    ] = a4.x + bo0;
            st[(pxl+1)*33 + mt*16 + gid    ] = a4.y + bo0;
            st[(pxl  )*33 + mt*16 + gid + 8] = a4.z + bo1;
            st[(pxl+1)*33 + mt*16 + gid + 8] = a4.w + bo1;
        }
    }
    __syncthreads();

    // t, norms, fp16 q2n (128 threads, one per px)
    if (tid < 128) {
        int p = tid;
        int gpp = b*HW + px0 + p;
        float v[C8]; float ss = 0.f;
#pragma unroll
        for (int c = 0; c < C8; c++) { v[c] = st[p*33 + c]; ss += v[c]*v[c]; }
        float n = sqrtf(ss);
        float inv = 1.f / fmaxf(n, 1e-12f);
        g_norm[gpp] = n;
        uint32_t* qh = g_qh + (size_t)gpp*16;
#pragma unroll
        for (int d = 0; d < 8; d++) {
            qh[2*d]   = pkhf(v[4*d+0]*inv, v[4*d+1]*inv);
            qh[2*d+1] = pkhf(v[4*d+2]*inv, v[4*d+3]*inv);
        }
        float* tb = g_t + (size_t)b*C8*HW + px0 + p;
#pragma unroll
        for (int c = 0; c < C8; c++) tb[(size_t)c*HW] = v[c];
    }

    // gram partial over 128 px
    {
        const int i  = tid >> 3;
        const int j0 = (tid & 7) * 4;
        float s0=0.f, s1=0.f, s2=0.f, s3=0.f;
#pragma unroll 8
        for (int xx = 0; xx < 128; xx++) {
            const float* r = st + xx*33;
            float a = r[i];
            s0 += a*r[j0]; s1 += a*r[j0+1]; s2 += a*r[j0+2]; s3 += a*r[j0+3];
        }
        float* dst = g_pgram + ((size_t)(b*32 + pb) << 10) + i*32 + j0;
        dst[0]=s0; dst[1]=s1; dst[2]=s2; dst[3]=s3;
    }
}

// ================= reduce gram (32 slabs) + softmax =================
__global__ void __launch_bounds__(1024) chsoft_k()
{
    const int b = blockIdx.x;
    const int tid = threadIdx.x;
    __shared__ float G[1024];
    __shared__ float ninv[32];

    float g = 0.f;
#pragma unroll 8
    for (int s = 0; s < 32; s++)
        g += g_pgram[(((size_t)b*32 + s) << 10) + tid];
    G[tid] = g;
    if ((tid >> 5) == (tid & 31)) ninv[tid & 31] = 1.f / fmaxf(sqrtf(g), 1e-12f);
    __syncthreads();

    if (tid < 32) {
        int r = tid;
        float ir = ninv[r];
        float row[32]; float s = 0.f;
#pragma unroll
        for (int jj = 0; jj < 32; jj++) {
            float a = G[r*32 + jj] * ir * ninv[jj];
            float p = expf(a - 1.f);
            row[jj] = p; s += p;
        }
        float is = 1.f / s;
        float* dst = g_attn1 + b*C8*C8 + r*32;
#pragma unroll
        for (int jj = 0; jj < 32; jj++) dst[jj] = row[jj] * is;
    }
}

// ================= flash spatial attention, fp16 TC, split-K x2 =================
#define SPN 20
#define SPD 68
#define SPP 68

__global__ void __launch_bounds__(256, 2) spflash_k()
{
    extern __shared__ uint32_t su[];
    uint32_t* sKn = su;
    uint32_t* sKd = sKn + 128*SPN;
    uint32_t* sP  = sKd + 32*SPD;
    float*    sN  = (float*)(sP + 8*16*SPP);

    const int tid = threadIdx.x;
    const int w = tid >> 5, lane = tid & 31;
    const int gid = lane >> 2, tig = lane & 3;
    const int ks = blockIdx.y, b = blockIdx.z;
    const int qb = blockIdx.x*128 + w*16;

    uint32_t qf[2][4];
    {
        const uint32_t* Q = g_qh + ((size_t)b*HW + qb)*16;
#pragma unroll
        for (int kc = 0; kc < 2; kc++)
#pragma unroll
        for (int i = 0; i < 4; i++) {
            int row = gid + (i & 1)*8;
            int du = kc*8 + tig + ((i & 2) ? 4 : 0);
            qf[kc][i] = __ldg(Q + row*16 + du);
        }
    }

    float4 acc_o[4];
#pragma unroll
    for (int n = 0; n < 4; n++) acc_o[n] = make_float4(0.f,0.f,0.f,0.f);
    float l0 = 0.f, l1 = 0.f;
    uint32_t* sPw = sP + w*16*SPP;

    for (int kt = ks*16; kt < ks*16 + 16; kt++) {
        __syncthreads();
        {
            const uint4* src = (const uint4*)(g_qh + ((size_t)b*HW + kt*128)*16);
            int key = tid & 127, hf = tid >> 7;
            uint4 v0 = __ldg(src + key*4 + hf*2);
            uint4 v1 = __ldg(src + key*4 + hf*2 + 1);
            *(uint4*)(sKn + key*SPN + hf*8)     = v0;
            *(uint4*)(sKn + key*SPN + hf*8 + 4) = v1;
            int k2 = tid & 63, dg = tid >> 6;
            uint4 ua = __ldg(src + (2*k2)*4 + dg);
            uint4 ub = __ldg(src + (2*k2+1)*4 + dg);
            uint32_t uaa[4] = {ua.x, ua.y, ua.z, ua.w};
            uint32_t ubb[4] = {ub.x, ub.y, ub.z, ub.w};
#pragma unroll
            for (int j = 0; j < 4; j++) {
                sKd[(dg*8 + 2*j  )*SPD + k2] = __byte_perm(uaa[j], ubb[j], 0x5410);
                sKd[(dg*8 + 2*j+1)*SPD + k2] = __byte_perm(uaa[j], ubb[j], 0x7632);
            }
            if (tid < 128) sN[tid] = g_norm[(size_t)b*HW + kt*128 + tid];
        }
        __syncthreads();

#pragma unroll 4
        for (int nt = 0; nt < 16; nt++) {
            float4 s = make_float4(0.f,0.f,0.f,0.f);
            const int key = nt*8 + gid;
#pragma unroll
            for (int kc = 0; kc < 2; kc++) {
                uint32_t b0 = sKn[key*SPN + kc*8 + tig];
                uint32_t b1 = sKn[key*SPN + kc*8 + tig + 4];
                mma_f16(s, qf[kc][0],qf[kc][1],qf[kc][2],qf[kc][3], b0, b1);
            }
            float n0 = sN[nt*8 + 2*tig], n1 = sN[nt*8 + 2*tig + 1];
            float e0 = __expf(s.x - 1.f), e1 = __expf(s.y - 1.f);
            float e2 = __expf(s.z - 1.f), e3 = __expf(s.w - 1.f);
            l0 += e0 + e1;
            l1 += e2 + e3;
            sPw[(size_t)gid*SPP     + nt*4 + tig] = pkhf(e0*n0, e1*n1);
            sPw[(size_t)(gid+8)*SPP + nt*4 + tig] = pkhf(e2*n0, e3*n1);
        }
        __syncwarp();

#pragma unroll
        for (int ks2 = 0; ks2 < 8; ks2++) {
            uint32_t a0 = sPw[(size_t)gid*SPP     + ks2*8 + tig];
            uint32_t a1 = sPw[(size_t)(gid+8)*SPP + ks2*8 + tig];
            uint32_t a2 = sPw[(size_t)gid*SPP     + ks2*8 + tig + 4];
            uint32_t a3 = sPw[(size_t)(gid+8)*SPP + ks2*8 + tig + 4];
#pragma unroll
            for (int nt2 = 0; nt2 < 4; nt2++) {
                int dimc = nt2*8 + gid;
                uint32_t v0 = sKd[dimc*SPD + ks2*8 + tig];
                uint32_t v1 = sKd[dimc*SPD + ks2*8 + tig + 4];
                mma_f16(acc_o[nt2], a0,a1,a2,a3, v0, v1);
            }
        }
    }

    l0 += __shfl_xor_sync(0xffffffffu, l0, 1);
    l0 += __shfl_xor_sync(0xffffffffu, l0, 2);
    l1 += __shfl_xor_sync(0xffffffffu, l1, 1);
    l1 += __shfl_xor_sync(0xffffffffu, l1, 2);

    int q0 = qb + gid, q1 = qb + gid + 8;
    float* p0 = g_p3 + ((size_t)(b*2 + ks)*HW + q0)*C8;
    float* p1 = g_p3 + ((size_t)(b*2 + ks)*HW + q1)*C8;
#pragma unroll
    for (int nt2 = 0; nt2 < 4; nt2++) {
        int d0 = nt2*8 + 2*tig, d1 = d0 + 1;
        p0[d0] = acc_o[nt2].x;  p0[d1] = acc_o[nt2].y;
        p1[d0] = acc_o[nt2].z;  p1[d1] = acc_o[nt2].w;
    }
    if (tig == 0) {
        g_pl[(size_t)(b*2 + ks)*HW + q0] = l0;
        g_pl[(size_t)(b*2 + ks)*HW + q1] = l1;
    }
}

// ================= final: combine split-K + chout + 1x1s =================
__global__ void __launch_bounds__(256, 2) final_k(
    const float* __restrict__ w3, const float* __restrict__ b3,
    const float* __restrict__ w4, const float* __restrict__ b4,
    float* __restrict__ out)
{
    __shared__ float sw3[64*32];
    __shared__ float sw4[Cc*C8];
    __shared__ float sb4[Cc];
    __shared__ float sA[C8*C8];
    __shared__ float so3[64*33];

    const int tid = threadIdx.x;
    const int px = tid & 63, coh = tid >> 6;
    const int g0 = blockIdx.x * 64;
    const int gp = g0 + px;
    const int b = gp >> 12, k = gp & (HW-1);

    for (int idx = tid; idx < 64*32; idx += 256) {
        int j = idx >> 5, o = idx & 31;
        sw3[j*32 + o] = w3[o*64 + j];
    }
    for (int idx = tid; idx < Cc*C8; idx += 256) sw4[idx] = w4[idx];
    if (tid < Cc) sb4[tid] = b4[tid];
    for (int idx = tid; idx < C8*C8; idx += 256) sA[idx] = g_attn1[b*C8*C8 + idx];

    if (coh == 0) {
        float l = g_pl[(size_t)(b*2)*HW + k] + g_pl[(size_t)(b*2+1)*HW + k];
        float inv = 1.f / l;
        const float4* pa = (const float4*)(g_p3 + ((size_t)(b*2)*HW + k)*C8);
        const float4* pb = (const float4*)(g_p3 + ((size_t)(b*2+1)*HW + k)*C8);
#pragma unroll
        for (int d = 0; d < 8; d++) {
            float4 va = pa[d], vb = pb[d];
            so3[px*33 + 4*d+0] = (va.x + vb.x) * inv;
            so3[px*33 + 4*d+1] = (va.y + vb.y) * inv;
            so3[px*33 + 4*d+2] = (va.z + vb.z) * inv;
            so3[px*33 + 4*d+3] = (va.w + vb.w) * inv;
        }
    }
    __syncthreads();

    float tv[C8];
    {
        const float* tb = g_t + (size_t)b*C8*HW + k;
#pragma unroll
        for (int c = 0; c < C8; c++) tv[c] = tb[(size_t)c*HW];
    }
    u64 tvp[16];
#pragma unroll
    for (int d = 0; d < 16; d++) tvp[d] = pack2(tv[2*d], tv[2*d+1]);

    float out2[C8];
#pragma unroll
    for (int i = 0; i < C8; i++) {
        const u64* ar = (const u64*)(sA + i*32);
        u64 s2 = pack2(0.f, 0.f);
#pragma unroll
        for (int d = 0; d < 16; d++) s2 = ffma2(ar[d], tvp[d], s2);
        float2 f = unpack2(s2);
        out2[i] = f.x + f.y;
    }

    u64 o5[16];
#pragma unroll
    for (int d = 0; d < 16; d++)
        o5[d] = pack2(__ldg(b3 + 2*d) + tv[2*d], __ldg(b3 + 2*d+1) + tv[2*d+1]);

#pragma unroll 4
    for (int j = 0; j < 32; j++) {
        u64 vp = pack2(out2[j], out2[j]);
        const u64* wr = (const u64*)(sw3 + j*32);
#pragma unroll
        for (int d = 0; d < 16; d++) o5[d] = ffma2(vp, wr[d], o5[d]);
    }
#pragma unroll 4
    for (int j = 0; j < 32; j++) {
        float v = so3[px*33 + j];
        u64 vp = pack2(v, v);
        const u64* wr = (const u64*)(sw3 + (32+j)*32);
#pragma unroll
        for (int d = 0; d < 16; d++) o5[d] = ffma2(vp, wr[d], o5[d]);
    }

    const int co0 = coh * 64;
    float* dst = out + (size_t)b*Cc*HW + (size_t)co0*HW + k;
#pragma unroll 2
    for (int cc = 0; cc < 64; cc += 2) {
        const u64* w0 = (const u64*)(sw4 + (co0+cc)*C8);
        const u64* w1 = (const u64*)(sw4 + (co0+cc+1)*C8);
        u64 s0 = pack2(0.f, 0.f), s1 = pack2(0.f, 0.f);
#pragma unroll
        for (int d = 0; d < 16; d++) {
            s0 = ffma2(w0[d], o5[d], s0);
            s1 = ffma2(w1[d], o5[d], s1);
        }
        float2 f0 = unpack2(s0), f1 = unpack2(s1);
        dst[(size_t)cc*HW]     = f0.x + f0.y + sb4[co0+cc];
        dst[(size_t)(cc+1)*HW] = f1.x + f1.y + sb4[co0+cc+1];
    }
}

// ================= launch =================
extern "C" void kernel_launch(void* const* d_in, const int* in_sizes, int n_in,
                              void* d_out, int out_size)
{
    const float* x      = (const float*)d_in[0];
    const float* w_conv = (const float*)d_in[1];
    const float* b_conv = (const float*)d_in[2];
    const float* w01 = (const float*)d_in[3];
    const float* b01 = (const float*)d_in[4];
    const float* w02 = (const float*)d_in[5];
    const float* b02 = (const float*)d_in[6];
    const float* w11 = (const float*)d_in[7];
    const float* b11 = (const float*)d_in[8];
    const float* w12 = (const float*)d_in[9];
    const float* b12 = (const float*)d_in[10];
    const float* w21 = (const float*)d_in[11];
    const float* b21 = (const float*)d_in[12];
    const float* w22 = (const float*)d_in[13];
    const float* b22 = (const float*)d_in[14];
    const float* w_proj = (const float*)d_in[15];
    const float* b_proj = (const float*)d_in[16];
    const float* w3 = (const float*)d_in[17];
    const float* b3 = (const float*)d_in[18];
    const float* w4 = (const float*)d_in[19];
    const float* b4 = (const float*)d_in[20];
    float* out = (float*)d_out;

    const int convSmem = (SXB_ELEMS + SW_ALL) * (int)sizeof(uint32_t);
    const int projSmem = (128*SWPP + 64*SSP) * (int)sizeof(uint32_t) + 128*33*(int)sizeof(float);
    const int spSmem   = (128*SPN + 32*SPD + 8*16*SPP) * (int)sizeof(uint32_t)
                       + 128 * (int)sizeof(float);
    static bool attrSet = false;
    if (!attrSet) {
        cudaFuncSetAttribute(convmma_k, cudaFuncAttributeMaxDynamicSharedMemorySize, convSmem);
        cudaFuncSetAttribute(projTC_k,  cudaFuncAttributeMaxDynamicSharedMemorySize, projSmem);
        cudaFuncSetAttribute(spflash_k, cudaFuncAttributeMaxDynamicSharedMemorySize, spSmem);
        attrSet = true;
    }

    xprep_k   <<<Bn*128*HW/256, 256>>>(x);
    wprep_k   <<<9*128*Cc/256, 256>>>(w_conv, w_proj);
    convmma_k <<<dim3(32, 2, 4), 256, convSmem>>>(b_conv);
    dwfused_k <<<Bn*Cc, 256>>>(w01, b01, w02, b02, w11, b11, w12, b12, w21, b21, w22, b22);
    projTC_k  <<<dim3(32, 4), 256, projSmem>>>(b_proj);
    chsoft_k  <<<4, 1024>>>();
    spflash_k <<<dim3(32, 2, 4), 256, spSmem>>>();
    final_k   <<<256, 256>>>(w3, b3, w4, b4, out);
}

// round 17
// speedup vs baseline: 2.2163x; 1.0652x over previous
#include <cuda_runtime.h>
#include <cuda_fp16.h>
#include <math.h>
#include <stdint.h>

#define Bn 4
#define Cc 256
#define C8 32
#define Hh 64
#define Ww 64
#define HW 4096

typedef unsigned long long u64;

__device__ __forceinline__ u64 ffma2(u64 a, u64 b, u64 c){
    u64 d; asm("fma.rn.f32x2 %0, %1, %2, %3;" : "=l"(d) : "l"(a), "l"(b), "l"(c)); return d;
}
__device__ __forceinline__ u64 pack2(float lo, float hi){
    u64 d; asm("mov.b64 %0, {%1, %2};" : "=l"(d) : "f"(lo), "f"(hi)); return d;
}
__device__ __forceinline__ float2 unpack2(u64 v){
    float lo, hi; asm("mov.b64 {%0, %1}, %2;" : "=f"(lo), "=f"(hi) : "l"(v));
    return make_float2(lo, hi);
}
__device__ __forceinline__ void mma_f16(float4& d, const uint32_t a0, const uint32_t a1,
                                        const uint32_t a2, const uint32_t a3,
                                        const uint32_t b0, const uint32_t b1){
    asm volatile(
      "mma.sync.aligned.m16n8k16.row.col.f32.f16.f16.f32 "
      "{%0,%1,%2,%3}, {%4,%5,%6,%7}, {%8,%9}, {%0,%1,%2,%3};"
      : "+f"(d.x), "+f"(d.y), "+f"(d.z), "+f"(d.w)
      : "r"(a0), "r"(a1), "r"(a2), "r"(a3), "r"(b0), "r"(b1));
}
__device__ __forceinline__ uint32_t pkhf(float a, float b){
    __half2 t = __floats2half2_rn(a, b);
    return *reinterpret_cast<uint32_t*>(&t);
}

// ---------------- scratch ----------------
__device__ uint32_t g_xI [Bn*128*HW];
__device__ __half   g_x  [Bn*Cc*HW];
__device__ uint32_t g_sumI[Bn*128*HW];
__device__ float g_t  [Bn*C8*HW];
__device__ float g_attn1[Bn*C8*C8];
__device__ float g_p3 [Bn*2*HW*C8];
__device__ float g_pl [Bn*2*HW];
__device__ uint32_t g_qh[Bn*HW*16];
__device__ float g_norm[Bn*HW];
__device__ float g_pgram[Bn*32*C8*C8];
__device__ uint32_t g_wf[9*128*Cc];
__device__ uint32_t g_wp[128*C8];

// ================= input prep =================
__global__ void __launch_bounds__(256) xprep_k(const float* __restrict__ x)
{
    int idx = blockIdx.x * 256 + threadIdx.x;
    int pos = idx & (HW-1);
    int p   = idx >> 12;
    int b   = p >> 7, ci2 = p & 127;
    const float* xp = x + ((size_t)(b*Cc + 2*ci2))*HW + pos;
    g_xI[idx] = pkhf(__ldg(xp), __ldg(xp + HW));
}

// ================= weight prep =================
__global__ void __launch_bounds__(256) wprep_k(const float* __restrict__ w,
                                               const float* __restrict__ w_proj)
{
    int idx = blockIdx.x * 256 + threadIdx.x;
    int co  = idx & 255;
    int ci2 = (idx >> 8) & 127;
    int tap = idx >> 15;
    float v0 = w[((size_t)co*Cc + 2*ci2    )*9 + tap];
    float v1 = w[((size_t)co*Cc + 2*ci2 + 1)*9 + tap];
    g_wf[idx] = pkhf(v0, v1);
    if (idx < 128*C8) {
        int k2 = idx >> 5, o = idx & 31;
        g_wp[idx] = pkhf(w_proj[o*Cc + 2*k2], w_proj[o*Cc + 2*k2 + 1]);
    }
}

// ================= 3x3 conv via fp16 m16n8k16 MMA =================
#define SXB 264
#define SWB 136
#define SWT (8*SWB)
#define SXB_ELEMS (8*SXB)
#define SW_ALL (9*SWT)

__global__ void __launch_bounds__(256, 2) convmma_k(const float* __restrict__ bias)
{
    extern __shared__ uint32_t smu[];
    uint32_t* sX = smu;
    uint32_t* sW = sX + SXB_ELEMS;

    const int pb = blockIdx.x, cog = blockIdx.y, b = blockIdx.z;
    const int tid  = threadIdx.x;
    const int wid  = tid >> 5, lane = tid & 31;
    const int wm   = wid >> 1, wn = wid & 1;
    const int gid  = lane >> 2, tig = lane & 3;
    const int h0   = pb * 2;

    float4 acc[2][8];
#pragma unroll
    for (int mt = 0; mt < 2; mt++)
#pragma unroll
        for (int nt = 0; nt < 8; nt++) acc[mt][nt] = make_float4(0.f,0.f,0.f,0.f);

    for (int cib = 0; cib < Cc/16; cib++) {
        __syncthreads();
        for (int e = tid; e < 8*264; e += 256) {
            int ci2 = e / 264;
            int rem = e - ci2*264;
            int r = rem / 66;
            int c = rem - r*66;
            int gh = h0 - 1 + r, gw = c - 1;
            uint32_t v = 0;
            if (gh >= 0 && gh < Hh && gw >= 0 && gw < Ww)
                v = __ldg(g_xI + (size_t)(b*128 + cib*8 + ci2)*HW + gh*Ww + gw);
            sX[ci2*SXB + rem] = v;
        }
        {
            const size_t base = (size_t)(cib*8)*256 + cog*128;
#pragma unroll
            for (int i = 0; i < 9; i++) {
                int e = tid + i*256;
                int tap = e >> 8;
                int rem = e & 255;
                int ci2 = rem >> 5, c4 = rem & 31;
                uint4 v = __ldg((const uint4*)(g_wf + (size_t)tap*32768 + base + (size_t)ci2*256) + c4);
                *(uint4*)(sW + tap*SWT + ci2*SWB + c4*4) = v;
            }
        }
        __syncthreads();

#pragma unroll
        for (int tap = 0; tap < 9; tap++) {
            const int dh = tap/3 - 1, dw = tap%3 - 1;
            const uint32_t* wt = sW + tap*SWT;

            uint32_t a[2][4];
#pragma unroll
            for (int mt = 0; mt < 2; mt++) {
                int cb = wm*32 + mt*16 + gid;
                a[mt][0] = wt[tig*SWB + cb];       a[mt][1] = wt[tig*SWB + cb + 8];
                a[mt][2] = wt[(tig+4)*SWB + cb];   a[mt][3] = wt[(tig+4)*SWB + cb + 8];
            }
            const int boff = tig*SXB + (wn + 1 + dh)*66 + 1 + dw + gid;
#pragma unroll
            for (int nt = 0; nt < 8; nt++) {
                uint32_t b0 = sX[boff + nt*8];
                uint32_t b1 = sX[boff + nt*8 + 4*SXB];
#pragma unroll
                for (int mt = 0; mt < 2; mt++)
                    mma_f16(acc[mt][nt], a[mt][0],a[mt][1],a[mt][2],a[mt][3], b0, b1);
            }
        }
    }

#pragma unroll
    for (int mt = 0; mt < 2; mt++) {
        int co0 = cog*128 + wm*32 + mt*16 + gid;
        float b0 = __ldg(bias + co0);
        float b1 = __ldg(bias + co0 + 8);
#pragma unroll
        for (int nt = 0; nt < 8; nt++) {
            int px = pb*128 + wn*64 + nt*8 + 2*tig;
            __half* d0 = g_x + ((size_t)(b*Cc + co0))*HW + px;
            __half* d1 = g_x + ((size_t)(b*Cc + co0 + 8))*HW + px;
            float4 a4 = acc[mt][nt];
            *(half2*)d0 = __floats2half2_rn(a4.x + b0, a4.y + b0);
            *(half2*)d1 = __floats2half2_rn(a4.z + b1, a4.w + b1);
        }
    }
}

// ================= fused depthwise: sliding-window register reuse =================
#define XSP 89            // xs row stride (odd -> row-varying warps conflict-free)
#define HSP 65            // hb row stride ((h+w)%32 distinct)
#define DWBUF (64*XSP + 88*HSP)   // 5696 + 5720 = 11416 floats

template<int K>
__device__ __forceinline__ void dw_scale(
    const float* xs, float* hb, float out[16],
    const float* __restrict__ wh_c, const float* __restrict__ wv_c,
    float bh, float bv, int hr, int w0, int w, int h0)
{
    constexpr int P = K/2;
    constexpr int NV = 16 + K - 1;
    // ---- horizontal: thread = (row hr, cols w0..w0+15)
    {
        float whr[K];
#pragma unroll
        for (int k = 0; k < K; k++) whr[k] = __ldg(wh_c + k);
        float v[NV];
        const float* row = xs + hr*XSP + 12 + w0 - P;
#pragma unroll
        for (int j = 0; j < NV; j++) v[j] = row[j];
        float* hrow = hb + (12 + hr)*HSP + w0;
#pragma unroll
        for (int i = 0; i < 16; i++) {
            float s = bh;
#pragma unroll
            for (int k = 0; k < K; k++) s += whr[k] * v[i + k];
            hrow[i] = s;
        }
    }
    __syncthreads();
    // ---- vertical: thread = (col w, rows h0..h0+15)
    {
        float wvr[K];
#pragma unroll
        for (int k = 0; k < K; k++) wvr[k] = __ldg(wv_c + k);
        float u[NV];
        const float* col = hb + (12 + h0 - P)*HSP + w;
#pragma unroll
        for (int j = 0; j < NV; j++) u[j] = col[j*HSP];
#pragma unroll
        for (int i = 0; i < 16; i++) {
            float s = bv;
#pragma unroll
            for (int k = 0; k < K; k++) s += wvr[k] * u[i + k];
            out[i] += s;
        }
    }
    __syncthreads();
}

__global__ void __launch_bounds__(256) dwfused_k(
    const float* __restrict__ w01, const float* __restrict__ b01,
    const float* __restrict__ w02, const float* __restrict__ b02,
    const float* __restrict__ w11, const float* __restrict__ b11,
    const float* __restrict__ w12, const float* __restrict__ b12,
    const float* __restrict__ w21, const float* __restrict__ b21,
    const float* __restrict__ w22, const float* __restrict__ b22)
{
    __shared__ float sbuf[DWBUF];
    float* xs = sbuf;
    float* hb = sbuf + 64*XSP;

    const int plane = blockIdx.x;
    const int c = plane & (Cc-1);
    const int b = plane >> 8;
    const int tid = threadIdx.x;
    const __half* src = g_x + (size_t)plane*HW;

    // zero everything (halos stay zero thereafter)
    for (int i = tid; i < DWBUF/4; i += 256)
        ((float4*)sbuf)[i] = make_float4(0.f,0.f,0.f,0.f);
    __syncthreads();

    // stage interior (fp16 -> fp32, scalar stores)
#pragma unroll
    for (int s = 0; s < 2; s++) {
        int idx = tid + s*256;
        uint4 raw = ((const uint4*)src)[idx];
        int h = idx >> 3, w8 = (idx & 7)*8;
        float* dstp = xs + h*XSP + 12 + w8;
        float2 f0 = __half22float2(*(half2*)&raw.x);
        float2 f1 = __half22float2(*(half2*)&raw.y);
        float2 f2 = __half22float2(*(half2*)&raw.z);
        float2 f3 = __half22float2(*(half2*)&raw.w);
        dstp[0]=f0.x; dstp[1]=f0.y; dstp[2]=f1.x; dstp[3]=f1.y;
        dstp[4]=f2.x; dstp[5]=f2.y; dstp[6]=f3.x; dstp[7]=f3.y;
    }
    __syncthreads();

    const int hr = tid & 63, w0 = (tid >> 6) * 16;   // horizontal mapping
    const int w  = tid & 63, h0 = (tid >> 6) * 16;   // vertical mapping

    float out[16];
#pragma unroll
    for (int i = 0; i < 16; i++) out[i] = xs[(h0+i)*XSP + 12 + w];

    dw_scale<7> (xs, hb, out, w01 + c*7,  w02 + c*7,  __ldg(b01+c), __ldg(b02+c), hr, w0, w, h0);
    dw_scale<11>(xs, hb, out, w11 + c*11, w12 + c*11, __ldg(b11+c), __ldg(b12+c), hr, w0, w, h0);
    dw_scale<21>(xs, hb, out, w21 + c*21, w22 + c*21, __ldg(b21+c), __ldg(b22+c), hr, w0, w, h0);

    __half* dst = (__half*)g_sumI + ((size_t)(b*128 + (c>>1))*HW)*2 + (c&1);
#pragma unroll
    for (int i = 0; i < 16; i++)
        dst[(size_t)((h0+i)*Ww + w)*2] = __float2half_rn(out[i]);
}

// ================= proj via tensor cores + l2norm + gram =================
#define SWPP 40
#define SSP  136

__global__ void __launch_bounds__(256, 2) projTC_k(const float* __restrict__ b_proj)
{
    extern __shared__ float smf[];
    uint32_t* sWp = (uint32_t*)smf;
    uint32_t* sS  = sWp + 128*SWPP;
    float*    st  = (float*)(sS + 64*SSP);

    const int tid = threadIdx.x;
    const int w = tid >> 5, lane = tid & 31;
    const int gid = lane >> 2, tig = lane & 3;
    const int pb = blockIdx.x, b = blockIdx.y;
    const int px0 = pb * 128;

#pragma unroll
    for (int i = 0; i < 16; i++) {
        int idx = tid + i*256;
        int k2 = idx >> 5, o = idx & 31;
        sWp[k2*SWPP + o] = __ldg(g_wp + idx);
    }

    float4 acc[2][2];
#pragma unroll
    for (int mt = 0; mt < 2; mt++)
#pragma unroll
        for (int nt = 0; nt < 2; nt++) acc[mt][nt] = make_float4(0.f,0.f,0.f,0.f);

#pragma unroll
    for (int kc = 0; kc < 2; kc++) {
        __syncthreads();
#pragma unroll
        for (int i = 0; i < 8; i++) {
            int idx = tid + i*256;
            int k2 = idx >> 5, c4 = idx & 31;
            uint4 v = __ldg((const uint4*)(g_sumI + (size_t)(b*128 + kc*64 + k2)*HW + px0) + c4);
            *(uint4*)(sS + k2*SSP + c4*4) = v;
        }
        __syncthreads();

#pragma unroll
        for (int ks2 = 0; ks2 < 8; ks2++) {
            uint32_t a[2][4];
#pragma unroll
            for (int mt = 0; mt < 2; mt++) {
                int o = mt*16 + gid;
                a[mt][0] = sWp[(kc*64 + ks2*8 + tig)*SWPP + o];
                a[mt][1] = sWp[(kc*64 + ks2*8 + tig)*SWPP + o + 8];
                a[mt][2] = sWp[(kc*64 + ks2*8 + tig + 4)*SWPP + o];
                a[mt][3] = sWp[(kc*64 + ks2*8 + tig + 4)*SWPP + o + 8];
            }
#pragma unroll
            for (int nt = 0; nt < 2; nt++) {
                int col = w*16 + nt*8 + gid;
                uint32_t b0 = sS[(ks2*8 + tig)*SSP + col];
                uint32_t b1 = sS[(ks2*8 + tig + 4)*SSP + col];
#pragma unroll
                for (int mt = 0; mt < 2; mt++)
                    mma_f16(acc[mt][nt], a[mt][0],a[mt][1],a[mt][2],a[mt][3], b0, b1);
            }
        }
    }

    __syncthreads();
#pragma unroll
    for (int mt = 0; mt < 2; mt++) {
        float bo0 = __ldg(b_proj + mt*16 + gid);
        float bo1 = __ldg(b_proj + mt*16 + gid + 8);
#pragma unroll
        for (int nt = 0; nt < 2; nt++) {
            int pxl = w*16 + nt*8 + 2*tig;
            float4 a4 = acc[mt][nt];
            st[(pxl  )*33 + mt*16 + gid    ] = a4.x + bo0;
            st[(pxl+1)*33 + mt*16 + gid    ] = a4.y + bo0;
            st[(pxl  )*33 + mt*16 + gid + 8] = a4.z + bo1;
            st[(pxl+1)*33 + mt*16 + gid + 8] = a4.w + bo1;
        }
    }
    __syncthreads();

    if (tid < 128) {
        int p = tid;
        int gpp = b*HW + px0 + p;
        float v[C8]; float ss = 0.f;
#pragma unroll
        for (int c = 0; c < C8; c++) { v[c] = st[p*33 + c]; ss += v[c]*v[c]; }
        float n = sqrtf(ss);
        float inv = 1.f / fmaxf(n, 1e-12f);
        g_norm[gpp] = n;
        uint32_t* qh = g_qh + (size_t)gpp*16;
#pragma unroll
        for (int d = 0; d < 8; d++) {
            qh[2*d]   = pkhf(v[4*d+0]*inv, v[4*d+1]*inv);
            qh[2*d+1] = pkhf(v[4*d+2]*inv, v[4*d+3]*inv);
        }
        float* tb = g_t + (size_t)b*C8*HW + px0 + p;
#pragma unroll
        for (int c = 0; c < C8; c++) tb[(size_t)c*HW] = v[c];
    }

    {
        const int i  = tid >> 3;
        const int j0 = (tid & 7) * 4;
        float s0=0.f, s1=0.f, s2=0.f, s3=0.f;
#pragma unroll 8
        for (int xx = 0; xx < 128; xx++) {
            const float* r = st + xx*33;
            float a = r[i];
            s0 += a*r[j0]; s1 += a*r[j0+1]; s2 += a*r[j0+2]; s3 += a*r[j0+3];
        }
        float* dst = g_pgram + ((size_t)(b*32 + pb) << 10) + i*32 + j0;
        dst[0]=s0; dst[1]=s1; dst[2]=s2; dst[3]=s3;
    }
}

// ================= reduce gram + softmax =================
__global__ void __launch_bounds__(1024) chsoft_k()
{
    const int b = blockIdx.x;
    const int tid = threadIdx.x;
    __shared__ float G[1024];
    __shared__ float ninv[32];

    float g = 0.f;
#pragma unroll 8
    for (int s = 0; s < 32; s++)
        g += g_pgram[(((size_t)b*32 + s) << 10) + tid];
    G[tid] = g;
    if ((tid >> 5) == (tid & 31)) ninv[tid & 31] = 1.f / fmaxf(sqrtf(g), 1e-12f);
    __syncthreads();

    if (tid < 32) {
        int r = tid;
        float ir = ninv[r];
        float row[32]; float s = 0.f;
#pragma unroll
        for (int jj = 0; jj < 32; jj++) {
            float a = G[r*32 + jj] * ir * ninv[jj];
            float p = expf(a - 1.f);
            row[jj] = p; s += p;
        }
        float is = 1.f / s;
        float* dst = g_attn1 + b*C8*C8 + r*32;
#pragma unroll
        for (int jj = 0; jj < 32; jj++) dst[jj] = row[jj] * is;
    }
}

// ================= flash spatial attention, fp16 TC, split-K x2 =================
#define SPN 20
#define SPD 68
#define SPP 68

__global__ void __launch_bounds__(256, 2) spflash_k()
{
    extern __shared__ uint32_t su[];
    uint32_t* sKn = su;
    uint32_t* sKd = sKn + 128*SPN;
    uint32_t* sP  = sKd + 32*SPD;
    float*    sN  = (float*)(sP + 8*16*SPP);

    const int tid = threadIdx.x;
    const int w = tid >> 5, lane = tid & 31;
    const int gid = lane >> 2, tig = lane & 3;
    const int ks = blockIdx.y, b = blockIdx.z;
    const int qb = blockIdx.x*128 + w*16;

    uint32_t qf[2][4];
    {
        const uint32_t* Q = g_qh + ((size_t)b*HW + qb)*16;
#pragma unroll
        for (int kc = 0; kc < 2; kc++)
#pragma unroll
        for (int i = 0; i < 4; i++) {
            int row = gid + (i & 1)*8;
            int du = kc*8 + tig + ((i & 2) ? 4 : 0);
            qf[kc][i] = __ldg(Q + row*16 + du);
        }
    }

    float4 acc_o[4];
#pragma unroll
    for (int n = 0; n < 4; n++) acc_o[n] = make_float4(0.f,0.f,0.f,0.f);
    float l0 = 0.f, l1 = 0.f;
    uint32_t* sPw = sP + w*16*SPP;

    for (int kt = ks*16; kt < ks*16 + 16; kt++) {
        __syncthreads();
        {
            const uint4* src = (const uint4*)(g_qh + ((size_t)b*HW + kt*128)*16);
            int key = tid & 127, hf = tid >> 7;
            uint4 v0 = __ldg(src + key*4 + hf*2);
            uint4 v1 = __ldg(src + key*4 + hf*2 + 1);
            *(uint4*)(sKn + key*SPN + hf*8)     = v0;
            *(uint4*)(sKn + key*SPN + hf*8 + 4) = v1;
            int k2 = tid & 63, dg = tid >> 6;
            uint4 ua = __ldg(src + (2*k2)*4 + dg);
            uint4 ub = __ldg(src + (2*k2+1)*4 + dg);
            uint32_t uaa[4] = {ua.x, ua.y, ua.z, ua.w};
            uint32_t ubb[4] = {ub.x, ub.y, ub.z, ub.w};
#pragma unroll
            for (int j = 0; j < 4; j++) {
                sKd[(dg*8 + 2*j  )*SPD + k2] = __byte_perm(uaa[j], ubb[j], 0x5410);
                sKd[(dg*8 + 2*j+1)*SPD + k2] = __byte_perm(uaa[j], ubb[j], 0x7632);
            }
            if (tid < 128) sN[tid] = g_norm[(size_t)b*HW + kt*128 + tid];
        }
        __syncthreads();

#pragma unroll 4
        for (int nt = 0; nt < 16; nt++) {
            float4 s = make_float4(0.f,0.f,0.f,0.f);
            const int key = nt*8 + gid;
#pragma unroll
            for (int kc = 0; kc < 2; kc++) {
                uint32_t b0 = sKn[key*SPN + kc*8 + tig];
                uint32_t b1 = sKn[key*SPN + kc*8 + tig + 4];
                mma_f16(s, qf[kc][0],qf[kc][1],qf[kc][2],qf[kc][3], b0, b1);
            }
            float n0 = sN[nt*8 + 2*tig], n1 = sN[nt*8 + 2*tig + 1];
            float e0 = __expf(s.x - 1.f), e1 = __expf(s.y - 1.f);
            float e2 = __expf(s.z - 1.f), e3 = __expf(s.w - 1.f);
            l0 += e0 + e1;
            l1 += e2 + e3;
            sPw[(size_t)gid*SPP     + nt*4 + tig] = pkhf(e0*n0, e1*n1);
            sPw[(size_t)(gid+8)*SPP + nt*4 + tig] = pkhf(e2*n0, e3*n1);
        }
        __syncwarp();

#pragma unroll
        for (int ks2 = 0; ks2 < 8; ks2++) {
            uint32_t a0 = sPw[(size_t)gid*SPP     + ks2*8 + tig];
            uint32_t a1 = sPw[(size_t)(gid+8)*SPP + ks2*8 + tig];
            uint32_t a2 = sPw[(size_t)gid*SPP     + ks2*8 + tig + 4];
            uint32_t a3 = sPw[(size_t)(gid+8)*SPP + ks2*8 + tig + 4];
#pragma unroll
            for (int nt2 = 0; nt2 < 4; nt2++) {
                int dimc = nt2*8 + gid;
                uint32_t v0 = sKd[dimc*SPD + ks2*8 + tig];
                uint32_t v1 = sKd[dimc*SPD + ks2*8 + tig + 4];
                mma_f16(acc_o[nt2], a0,a1,a2,a3, v0, v1);
            }
        }
    }

    l0 += __shfl_xor_sync(0xffffffffu, l0, 1);
    l0 += __shfl_xor_sync(0xffffffffu, l0, 2);
    l1 += __shfl_xor_sync(0xffffffffu, l1, 1);
    l1 += __shfl_xor_sync(0xffffffffu, l1, 2);

    int q0 = qb + gid, q1 = qb + gid + 8;
    float* p0 = g_p3 + ((size_t)(b*2 + ks)*HW + q0)*C8;
    float* p1 = g_p3 + ((size_t)(b*2 + ks)*HW + q1)*C8;
#pragma unroll
    for (int nt2 = 0; nt2 < 4; nt2++) {
        int d0 = nt2*8 + 2*tig, d1 = d0 + 1;
        p0[d0] = acc_o[nt2].x;  p0[d1] = acc_o[nt2].y;
        p1[d0] = acc_o[nt2].z;  p1[d1] = acc_o[nt2].w;
    }
    if (tig == 0) {
        g_pl[(size_t)(b*2 + ks)*HW + q0] = l0;
        g_pl[(size_t)(b*2 + ks)*HW + q1] = l1;
    }
}

// ================= final: combine split-K + chout + 1x1s =================
__global__ void __launch_bounds__(256, 2) final_k(
    const float* __restrict__ w3, const float* __restrict__ b3,
    const float* __restrict__ w4, const float* __restrict__ b4,
    float* __restrict__ out)
{
    __shared__ float sw3[64*32];
    __shared__ float sw4[Cc*C8];
    __shared__ float sb4[Cc];
    __shared__ float sA[C8*C8];
    __shared__ float so3[64*33];

    const int tid = threadIdx.x;
    const int px = tid & 63, coh = tid >> 6;
    const int g0 = blockIdx.x * 64;
    const int gp = g0 + px;
    const int b = gp >> 12, k = gp & (HW-1);

    for (int idx = tid; idx < 64*32; idx += 256) {
        int j = idx >> 5, o = idx & 31;
        sw3[j*32 + o] = w3[o*64 + j];
    }
    for (int idx = tid; idx < Cc*C8; idx += 256) sw4[idx] = w4[idx];
    if (tid < Cc) sb4[tid] = b4[tid];
    for (int idx = tid; idx < C8*C8; idx += 256) sA[idx] = g_attn1[b*C8*C8 + idx];

    if (coh == 0) {
        float l = g_pl[(size_t)(b*2)*HW + k] + g_pl[(size_t)(b*2+1)*HW + k];
        float inv = 1.f / l;
        const float4* pa = (const float4*)(g_p3 + ((size_t)(b*2)*HW + k)*C8);
        const float4* pb = (const float4*)(g_p3 + ((size_t)(b*2+1)*HW + k)*C8);
#pragma unroll
        for (int d = 0; d < 8; d++) {
            float4 va = pa[d], vb = pb[d];
            so3[px*33 + 4*d+0] = (va.x + vb.x) * inv;
            so3[px*33 + 4*d+1] = (va.y + vb.y) * inv;
            so3[px*33 + 4*d+2] = (va.z + vb.z) * inv;
            so3[px*33 + 4*d+3] = (va.w + vb.w) * inv;
        }
    }
    __syncthreads();

    float tv[C8];
    {
        const float* tb = g_t + (size_t)b*C8*HW + k;
#pragma unroll
        for (int c = 0; c < C8; c++) tv[c] = tb[(size_t)c*HW];
    }
    u64 tvp[16];
#pragma unroll
    for (int d = 0; d < 16; d++) tvp[d] = pack2(tv[2*d], tv[2*d+1]);

    float out2[C8];
#pragma unroll
    for (int i = 0; i < C8; i++) {
        const u64* ar = (const u64*)(sA + i*32);
        u64 s2 = pack2(0.f, 0.f);
#pragma unroll
        for (int d = 0; d < 16; d++) s2 = ffma2(ar[d], tvp[d], s2);
        float2 f = unpack2(s2);
        out2[i] = f.x + f.y;
    }

    u64 o5[16];
#pragma unroll
    for (int d = 0; d < 16; d++)
        o5[d] = pack2(__ldg(b3 + 2*d) + tv[2*d], __ldg(b3 + 2*d+1) + tv[2*d+1]);

#pragma unroll 4
    for (int j = 0; j < 32; j++) {
        u64 vp = pack2(out2[j], out2[j]);
        const u64* wr = (const u64*)(sw3 + j*32);
#pragma unroll
        for (int d = 0; d < 16; d++) o5[d] = ffma2(vp, wr[d], o5[d]);
    }
#pragma unroll 4
    for (int j = 0; j < 32; j++) {
        float v = so3[px*33 + j];
        u64 vp = pack2(v, v);
        const u64* wr = (const u64*)(sw3 + (32+j)*32);
#pragma unroll
        for (int d = 0; d < 16; d++) o5[d] = ffma2(vp, wr[d], o5[d]);
    }

    const int co0 = coh * 64;
    float* dst = out + (size_t)b*Cc*HW + (size_t)co0*HW + k;
#pragma unroll 2
    for (int cc = 0; cc < 64; cc += 2) {
        const u64* w0 = (const u64*)(sw4 + (co0+cc)*C8);
        const u64* w1 = (const u64*)(sw4 + (co0+cc+1)*C8);
        u64 s0 = pack2(0.f, 0.f), s1 = pack2(0.f, 0.f);
#pragma unroll
        for (int d = 0; d < 16; d++) {
            s0 = ffma2(w0[d], o5[d], s0);
            s1 = ffma2(w1[d], o5[d], s1);
        }
        float2 f0 = unpack2(s0), f1 = unpack2(s1);
        dst[(size_t)cc*HW]     = f0.x + f0.y + sb4[co0+cc];
        dst[(size_t)(cc+1)*HW] = f1.x + f1.y + sb4[co0+cc+1];
    }
}

// ================= launch =================
extern "C" void kernel_launch(void* const* d_in, const int* in_sizes, int n_in,
                              void* d_out, int out_size)
{
    const float* x      = (const float*)d_in[0];
    const float* w_conv = (const float*)d_in[1];
    const float* b_conv = (const float*)d_in[2];
    const float* w01 = (const float*)d_in[3];
    const float* b01 = (const float*)d_in[4];
    const float* w02 = (const float*)d_in[5];
    const float* b02 = (const float*)d_in[6];
    const float* w11 = (const float*)d_in[7];
    const float* b11 = (const float*)d_in[8];
    const float* w12 = (const float*)d_in[9];
    const float* b12 = (const float*)d_in[10];
    const float* w21 = (const float*)d_in[11];
    const float* b21 = (const float*)d_in[12];
    const float* w22 = (const float*)d_in[13];
    const float* b22 = (const float*)d_in[14];
    const float* w_proj = (const float*)d_in[15];
    const float* b_proj = (const float*)d_in[16];
    const float* w3 = (const float*)d_in[17];
    const float* b3 = (const float*)d_in[18];
    const float* w4 = (const float*)d_in[19];
    const float* b4 = (const float*)d_in[20];
    float* out = (float*)d_out;

    const int convSmem = (SXB_ELEMS + SW_ALL) * (int)sizeof(uint32_t);
    const int projSmem = (128*SWPP + 64*SSP) * (int)sizeof(uint32_t) + 128*33*(int)sizeof(float);
    const int spSmem   = (128*SPN + 32*SPD + 8*16*SPP) * (int)sizeof(uint32_t)
                       + 128 * (int)sizeof(float);
    static bool attrSet = false;
    if (!attrSet) {
        cudaFuncSetAttribute(convmma_k, cudaFuncAttributeMaxDynamicSharedMemorySize, convSmem);
        cudaFuncSetAttribute(projTC_k,  cudaFuncAttributeMaxDynamicSharedMemorySize, projSmem);
        cudaFuncSetAttribute(spflash_k, cudaFuncAttributeMaxDynamicSharedMemorySize, spSmem);
        attrSet = true;
    }

    xprep_k   <<<Bn*128*HW/256, 256>>>(x);
    wprep_k   <<<9*128*Cc/256, 256>>>(w_conv, w_proj);
    convmma_k <<<dim3(32, 2, 4), 256, convSmem>>>(b_conv);
    dwfused_k <<<Bn*Cc, 256>>>(w01, b01, w02, b02, w11, b11, w12, b12, w21, b21, w22, b22);
    projTC_k  <<<dim3(32, 4), 256, projSmem>>>(b_proj);
    chsoft_k  <<<4, 1024>>>();
    spflash_k <<<dim3(32, 2, 4), 256, spSmem>>>();
    final_k   <<<256, 256>>>(w3, b3, w4, b4, out);
}